// round 2
// baseline (speedup 1.0000x reference)
#include <cuda_runtime.h>
#include <math.h>

// ---------------- problem constants ----------------
#define Dm     1024
#define Lnum   2
#define Hh     16
#define DHh    64
#define INNERd 1024
#define MLPd   4096
#define Ee     8
#define Bb     4
#define Nn     1024
#define Tt     (Bb*Nn)          // 4096 tokens
#define NEXP   (Ee-1)           // 7 FiLM experts

// ---------------- scratch (device globals; no cudaMalloc allowed) ----------------
__device__ float g_x[Tt*Dm];
__device__ float g_h[Tt*Dm];
__device__ float g_qkv[Tt*3*INNERd];
__device__ float g_scores[(size_t)Bb*Hh*Nn*Nn];
__device__ float g_o[Tt*INNERd];
__device__ float g_t0[Tt*Dm];     // also holds ytf after FiLM elementwise
__device__ float g_t1[Tt*Dm];     // also holds y (mix output)
__device__ float g_pe[(size_t)NEXP*Tt*Dm];
__device__ float g_ae[(size_t)NEXP*Tt*Dm];
__device__ float g_mid[(size_t)Tt*MLPd];
__device__ float g_w[Lnum*Tt*Ee];

__device__ __forceinline__ float gelu_f(float v) {
    return 0.5f * v * (1.0f + erff(v * 0.7071067811865475f));
}

// ---------------- generic tiled SGEMM ----------------
// C[M,N] = A[M,K] @ B[K,N] (+bias[N]) (act) (+resid, same layout as C)
// batched via blockIdx.z: bb=z/Hd, hh=z%Hd, pointer offsets by strides.
// BM=128, BN=64, BK=16; 16x16 threads, 8x4 micro-tile. M%128==0, N%64==0, K%16==0.
__global__ __launch_bounds__(256) void sgemm_kernel(
    const float* __restrict__ A, const float* __restrict__ B,
    const float* __restrict__ bias, const float* __restrict__ resid,
    float* __restrict__ C,
    int M, int N, int K, int lda, int ldb, int ldc,
    int Hd, long sAb, long sAh, long sBb, long sBh, long sCb, long sCh,
    int act, int hasBias, int hasRes)
{
    int z = blockIdx.z;
    int zb = z / Hd, zh = z % Hd;
    A += zb * sAb + zh * sAh;
    B += zb * sBb + zh * sBh;
    C += zb * sCb + zh * sCh;
    if (hasRes) resid += zb * sCb + zh * sCh;

    int row0 = blockIdx.y * 128;
    int col0 = blockIdx.x * 64;

    __shared__ float As[16][128];
    __shared__ float Bs[16][64];

    float acc[8][4];
#pragma unroll
    for (int i = 0; i < 8; i++)
#pragma unroll
        for (int j = 0; j < 4; j++) acc[i][j] = 0.f;

    int t = threadIdx.y * 16 + threadIdx.x;

    for (int kt = 0; kt < K; kt += 16) {
        // load A tile 128x16 (transposed into As[k][m])
#pragma unroll
        for (int li = 0; li < 2; li++) {
            int idx = li * 1024 + t * 4;
            int r = idx >> 4, c = idx & 15;
            float4 v = *(const float4*)(A + (long)(row0 + r) * lda + kt + c);
            As[c + 0][r] = v.x; As[c + 1][r] = v.y;
            As[c + 2][r] = v.z; As[c + 3][r] = v.w;
        }
        // load B tile 16x64
        {
            int idx = t * 4;
            int r = idx >> 6, c = idx & 63;
            float4 v = *(const float4*)(B + (long)(kt + r) * ldb + col0 + c);
            *(float4*)&Bs[r][c] = v;
        }
        __syncthreads();
#pragma unroll
        for (int kk = 0; kk < 16; kk++) {
            float4 a0 = *(const float4*)&As[kk][threadIdx.y * 8];
            float4 a1 = *(const float4*)&As[kk][threadIdx.y * 8 + 4];
            float4 b0 = *(const float4*)&Bs[kk][threadIdx.x * 4];
            float av[8] = {a0.x, a0.y, a0.z, a0.w, a1.x, a1.y, a1.z, a1.w};
            float bv[4] = {b0.x, b0.y, b0.z, b0.w};
#pragma unroll
            for (int i = 0; i < 8; i++)
#pragma unroll
                for (int j = 0; j < 4; j++) acc[i][j] += av[i] * bv[j];
        }
        __syncthreads();
    }

#pragma unroll
    for (int i = 0; i < 8; i++) {
        int row = row0 + threadIdx.y * 8 + i;
#pragma unroll
        for (int j = 0; j < 4; j++) {
            int col = col0 + threadIdx.x * 4 + j;
            float v = acc[i][j];
            if (hasBias) v += bias[col];
            if (act == 1) v = gelu_f(v);
            if (hasRes) v += resid[(long)row * ldc + col];
            C[(long)row * ldc + col] = v;
        }
    }
}

// ---------------- QK^T attention scores ----------------
// scores[z, q, k] = (1/8) * sum_d Q[q,d] * K[k,d],  z = b*H + h
__global__ __launch_bounds__(256) void qk_kernel(const float* __restrict__ qkv,
                                                 float* __restrict__ scores)
{
    int z = blockIdx.z;
    int b = z / Hh, h = z % Hh;
    const float* Q = qkv + (long)b * Nn * 3 * INNERd + h * DHh;
    const float* Kp = Q + INNERd;
    int q0 = blockIdx.y * 64, k0 = blockIdx.x * 64;

    __shared__ float Qs[64][68];   // [d][row]
    __shared__ float Ks[64][68];   // [d][col]

    int t = threadIdx.y * 16 + threadIdx.x;
#pragma unroll
    for (int li = 0; li < 16; li++) {
        int idx = li * 256 + t;
        int r = idx >> 6, d = idx & 63;
        Qs[d][r] = Q[(long)(q0 + r) * (3 * INNERd) + d];
        Ks[d][r] = Kp[(long)(k0 + r) * (3 * INNERd) + d];
    }
    __syncthreads();

    float acc[4][4];
#pragma unroll
    for (int i = 0; i < 4; i++)
#pragma unroll
        for (int j = 0; j < 4; j++) acc[i][j] = 0.f;

#pragma unroll 8
    for (int d = 0; d < 64; d++) {
        float4 qv = *(const float4*)&Qs[d][threadIdx.y * 4];
        float4 kv = *(const float4*)&Ks[d][threadIdx.x * 4];
        float av[4] = {qv.x, qv.y, qv.z, qv.w};
        float bv[4] = {kv.x, kv.y, kv.z, kv.w};
#pragma unroll
        for (int i = 0; i < 4; i++)
#pragma unroll
            for (int j = 0; j < 4; j++) acc[i][j] += av[i] * bv[j];
    }

    float* out = scores + (long)z * Nn * Nn;
#pragma unroll
    for (int i = 0; i < 4; i++)
#pragma unroll
        for (int j = 0; j < 4; j++)
            out[(long)(q0 + threadIdx.y * 4 + i) * Nn + k0 + threadIdx.x * 4 + j] =
                acc[i][j] * 0.125f;
}

// ---------------- softmax over last dim (row length Nn) ----------------
__global__ __launch_bounds__(256) void softmax_kernel(float* __restrict__ s)
{
    float* p = s + (size_t)blockIdx.x * Nn;
    int tid = threadIdx.x;
    __shared__ float red[256];

    float v[4];
    float m = -3.4e38f;
#pragma unroll
    for (int i = 0; i < 4; i++) { v[i] = p[tid + i * 256]; m = fmaxf(m, v[i]); }
    red[tid] = m; __syncthreads();
    for (int st = 128; st > 0; st >>= 1) {
        if (tid < st) red[tid] = fmaxf(red[tid], red[tid + st]);
        __syncthreads();
    }
    m = red[0]; __syncthreads();

    float sum = 0.f;
#pragma unroll
    for (int i = 0; i < 4; i++) { v[i] = expf(v[i] - m); sum += v[i]; }
    red[tid] = sum; __syncthreads();
    for (int st = 128; st > 0; st >>= 1) {
        if (tid < st) red[tid] += red[tid + st];
        __syncthreads();
    }
    float inv = 1.f / red[0];
#pragma unroll
    for (int i = 0; i < 4; i++) p[tid + i * 256] = v[i] * inv;
}

// ---------------- LayerNorm ----------------
__global__ __launch_bounds__(256) void ln_kernel(const float* __restrict__ x,
                                                 const float* __restrict__ g,
                                                 const float* __restrict__ bta,
                                                 float* __restrict__ out)
{
    int t = blockIdx.x, tid = threadIdx.x;
    const float* xp = x + (long)t * Dm;
    __shared__ float r1[256], r2[256];

    float v[4], s = 0.f, s2 = 0.f;
#pragma unroll
    for (int i = 0; i < 4; i++) { v[i] = xp[tid + i * 256]; s += v[i]; s2 += v[i] * v[i]; }
    r1[tid] = s; r2[tid] = s2; __syncthreads();
    for (int st = 128; st > 0; st >>= 1) {
        if (tid < st) { r1[tid] += r1[tid + st]; r2[tid] += r2[tid + st]; }
        __syncthreads();
    }
    float mean = r1[0] * (1.f / Dm);
    float var = r2[0] * (1.f / Dm) - mean * mean;
    float rstd = rsqrtf(var + 1e-5f);
    float* op = out + (long)t * Dm;
#pragma unroll
    for (int i = 0; i < 4; i++) {
        int d = tid + i * 256;
        op[d] = (v[i] - mean) * rstd * g[d] + bta[d];
    }
}

// ---------------- router: logits -> keep top-2 -> softmax ----------------
__global__ __launch_bounds__(128) void router_kernel(const float* __restrict__ x,
                                                     const float* __restrict__ Wr,
                                                     const float* __restrict__ br,
                                                     float* __restrict__ wout)
{
    int t = blockIdx.x, tid = threadIdx.x;
    __shared__ float part[128][Ee];
    float acc[Ee];
#pragma unroll
    for (int e = 0; e < Ee; e++) acc[e] = 0.f;
    const float* xp = x + (long)t * Dm;
    for (int d = tid; d < Dm; d += 128) {
        float xv = xp[d];
        const float* wrow = Wr + (long)d * Ee;
#pragma unroll
        for (int e = 0; e < Ee; e++) acc[e] += xv * wrow[e];
    }
#pragma unroll
    for (int e = 0; e < Ee; e++) part[tid][e] = acc[e];
    __syncthreads();
    for (int st = 64; st > 0; st >>= 1) {
        if (tid < st)
#pragma unroll
            for (int e = 0; e < Ee; e++) part[tid][e] += part[tid + st][e];
        __syncthreads();
    }
    if (tid == 0) {
        float lg[Ee];
#pragma unroll
        for (int e = 0; e < Ee; e++) lg[e] = part[0][e] + br[e];
        float m1 = -3.4e38f, m2 = -3.4e38f;
#pragma unroll
        for (int e = 0; e < Ee; e++) {
            float v = lg[e];
            if (v > m1) { m2 = m1; m1 = v; }
            else if (v > m2) m2 = v;
        }
        float sum = 0.f, we[Ee];
#pragma unroll
        for (int e = 0; e < Ee; e++) {
            we[e] = (lg[e] < m2) ? 0.f : expf(lg[e] - m1);
            sum += we[e];
        }
        float inv = 1.f / sum;
#pragma unroll
        for (int e = 0; e < Ee; e++) wout[(long)t * Ee + e] = we[e] * inv;
    }
}

// ---------------- FiLM elementwise: t0 = gelu(t0) * t1 ----------------
__global__ __launch_bounds__(256) void film_kernel(float* __restrict__ t0,
                                                   const float* __restrict__ t1)
{
    long i = (long)blockIdx.x * 256 + threadIdx.x;
    t0[i] = gelu_f(t0[i]) * t1[i];
}

// ---------------- expert mixing ----------------
// y = w0*gelu(ytf) + sum_{e=1..7} w_e * ((pe_e + Pb_e)*ytf + ae_e + Ab_e)
__global__ __launch_bounds__(256) void mix_kernel(const float* __restrict__ ytf,
                                                  const float* __restrict__ pe,
                                                  const float* __restrict__ ae,
                                                  const float* __restrict__ Pb,
                                                  const float* __restrict__ Ab,
                                                  const float* __restrict__ w,
                                                  float* __restrict__ y)
{
    int t = blockIdx.x;
    __shared__ float ws[Ee];
    if (threadIdx.x < Ee) ws[threadIdx.x] = w[(long)t * Ee + threadIdx.x];
    __syncthreads();
#pragma unroll
    for (int it = 0; it < 4; it++) {
        int d = threadIdx.x + it * 256;
        long td = (long)t * Dm + d;
        float yv = ytf[td];
        float out = ws[0] * gelu_f(yv);
#pragma unroll
        for (int e = 0; e < NEXP; e++) {
            float we = ws[e + 1];
            if (we != 0.f) {
                float p = pe[(long)e * Tt * Dm + td] + Pb[e * Dm + d];
                float a = ae[(long)e * Tt * Dm + td] + Ab[e * Dm + d];
                out += we * (p * yv + a);
            }
        }
        y[td] = out;
    }
}

// ---------------- host-side helpers ----------------
static float* sym(const void* s) {
    void* p = nullptr;
    cudaGetSymbolAddress(&p, s);
    return (float*)p;
}

static void gemm(const float* A, const float* B, const float* bias, const float* resid,
                 float* C, int M, int N, int K, int lda, int ldb, int ldc,
                 int Z, int Hd, long sAb, long sAh, long sBb, long sBh, long sCb, long sCh,
                 int act)
{
    dim3 grid(N / 64, M / 128, Z), block(16, 16);
    sgemm_kernel<<<grid, block>>>(A, B, bias, resid, C, M, N, K, lda, ldb, ldc,
                                  Hd, sAb, sAh, sBb, sBh, sCb, sCh,
                                  act, bias != nullptr, resid != nullptr);
}

extern "C" void kernel_launch(void* const* d_in, const int* in_sizes, int n_in,
                              void* d_out, int out_size)
{
    const float* x_in  = (const float*)d_in[0];
    const float* ln1_g = (const float*)d_in[1];
    const float* ln1_b = (const float*)d_in[2];
    const float* Wqkv  = (const float*)d_in[3];
    const float* bqkv  = (const float*)d_in[4];
    const float* Wo    = (const float*)d_in[5];
    const float* bo    = (const float*)d_in[6];
    const float* Wr    = (const float*)d_in[7];
    const float* br    = (const float*)d_in[8];
    const float* Wa1   = (const float*)d_in[9];
    const float* ba1   = (const float*)d_in[10];
    const float* Wa2   = (const float*)d_in[11];
    const float* ba2   = (const float*)d_in[12];
    const float* ln2_g = (const float*)d_in[13];
    const float* ln2_b = (const float*)d_in[14];
    const float* Wb0   = (const float*)d_in[15];
    const float* bb0   = (const float*)d_in[16];
    const float* Wb1   = (const float*)d_in[17];
    const float* bb1   = (const float*)d_in[18];
    const float* We_p  = (const float*)d_in[19];
    const float* be_p  = (const float*)d_in[20];
    const float* We_a  = (const float*)d_in[21];
    const float* be_a  = (const float*)d_in[22];

    float* X   = sym(g_x);
    float* Hb  = sym(g_h);
    float* QKV = sym(g_qkv);
    float* S   = sym(g_scores);
    float* O   = sym(g_o);
    float* T0  = sym(g_t0);
    float* T1  = sym(g_t1);
    float* PE  = sym(g_pe);
    float* AE  = sym(g_ae);
    float* MID = sym(g_mid);
    float* Wt  = sym(g_w);

    cudaMemcpyAsync(X, x_in, (size_t)Tt * Dm * sizeof(float),
                    cudaMemcpyDeviceToDevice, 0);

    for (int l = 0; l < Lnum; l++) {
        // --- attention block ---
        ln_kernel<<<Tt, 256>>>(X, ln1_g + l * Dm, ln1_b + l * Dm, Hb);

        gemm(Hb, Wqkv + (long)l * Dm * 3 * INNERd, bqkv + (long)l * 3 * INNERd, nullptr,
             QKV, Tt, 3 * INNERd, Dm, Dm, 3 * INNERd, 3 * INNERd,
             1, 1, 0, 0, 0, 0, 0, 0, 0);

        {
            dim3 grid(Nn / 64, Nn / 64, Bb * Hh), block(16, 16);
            qk_kernel<<<grid, block>>>(QKV, S);
        }
        softmax_kernel<<<Bb * Hh * Nn, 256>>>(S);

        // O[b,n,h*DH+d] = sum_k S[b,h,n,k] * V[b,k,h*DH+d]
        gemm(S, QKV + 2 * INNERd, nullptr, nullptr, O,
             Nn, DHh, Nn, Nn, 3 * INNERd, INNERd,
             Bb * Hh, Hh,
             (long)Hh * Nn * Nn, (long)Nn * Nn,
             (long)Nn * 3 * INNERd, DHh,
             (long)Nn * INNERd, DHh, 0);

        // x = O @ Wo + bo + x
        gemm(O, Wo + (long)l * INNERd * Dm, bo + (long)l * Dm, X, X,
             Tt, Dm, INNERd, INNERd, Dm, Dm,
             1, 1, 0, 0, 0, 0, 0, 0, 0);

        // --- router ---
        router_kernel<<<Tt, 128>>>(X, Wr + (long)l * Dm * Ee, br + (long)l * Ee,
                                   Wt + (long)l * Tt * Ee);

        // --- FiLM trunk ---
        ln_kernel<<<Tt, 256>>>(X, ln2_g + l * Dm, ln2_b + l * Dm, Hb);
        gemm(Hb, Wb0 + (long)l * Dm * Dm, bb0 + (long)l * Dm, nullptr, T0,
             Tt, Dm, Dm, Dm, Dm, Dm, 1, 1, 0, 0, 0, 0, 0, 0, 0);
        gemm(Hb, Wb1 + (long)l * Dm * Dm, bb1 + (long)l * Dm, nullptr, T1,
             Tt, Dm, Dm, Dm, Dm, Dm, 1, 1, 0, 0, 0, 0, 0, 0, 0);
        film_kernel<<<(Tt * Dm) / 256, 256>>>(T0, T1);   // T0 := ytf

        // --- dense expert GEMMs (batched over 7 experts) ---
        gemm(T0, We_p + (long)l * NEXP * Dm * Dm, nullptr, nullptr, PE,
             Tt, Dm, Dm, Dm, Dm, Dm,
             NEXP, 1, 0, 0, (long)Dm * Dm, 0, (long)Tt * Dm, 0, 0);
        gemm(T0, We_a + (long)l * NEXP * Dm * Dm, nullptr, nullptr, AE,
             Tt, Dm, Dm, Dm, Dm, Dm,
             NEXP, 1, 0, 0, (long)Dm * Dm, 0, (long)Tt * Dm, 0, 0);

        // --- mix (T1 := y) ---
        mix_kernel<<<Tt, 256>>>(T0, PE, AE,
                                be_p + (long)l * NEXP * Dm,
                                be_a + (long)l * NEXP * Dm,
                                Wt + (long)l * Tt * Ee, T1);

        // --- adaptor MLP + residual ---
        gemm(T1, Wa1 + (long)l * Dm * MLPd, ba1 + (long)l * MLPd, nullptr, MID,
             Tt, MLPd, Dm, Dm, MLPd, MLPd, 1, 1, 0, 0, 0, 0, 0, 0, 1 /*gelu*/);
        gemm(MID, Wa2 + (long)l * MLPd * Dm, ba2 + (long)l * Dm, X, X,
             Tt, Dm, MLPd, MLPd, Dm, Dm, 1, 1, 0, 0, 0, 0, 0, 0, 0);
    }

    // outputs: x [B,N,D] then stacked router weights [L,B,N,E]
    cudaMemcpyAsync(d_out, X, (size_t)Tt * Dm * sizeof(float),
                    cudaMemcpyDeviceToDevice, 0);
    if (out_size >= Tt * Dm + Lnum * Tt * Ee) {
        cudaMemcpyAsync((float*)d_out + (size_t)Tt * Dm, Wt,
                        (size_t)Lnum * Tt * Ee * sizeof(float),
                        cudaMemcpyDeviceToDevice, 0);
    }
}

// round 5
// speedup vs baseline: 1.9629x; 1.9629x over previous
#include <cuda_runtime.h>
#include <cuda_fp16.h>
#include <cstdint>
#include <math.h>

// ---------------- problem constants ----------------
#define Dm     1024
#define Lnum   2
#define Hh     16
#define DHh    64
#define INNERd 1024
#define MLPd   4096
#define Ee     8
#define Bb     4
#define Nn     1024
#define Tt     (Bb*Nn)          // 4096 tokens
#define NEXP   (Ee-1)           // 7 FiLM experts

// weight pack offsets (elements, per layer)
#define SZ1M   (1024L*1024L)
#define OFF_QKV 0L
#define OFF_WO  (OFF_QKV + 3072L*1024L)
#define OFF_WB0 (OFF_WO  + SZ1M)
#define OFF_WB1 (OFF_WB0 + SZ1M)
#define OFF_WEP (OFF_WB1 + SZ1M)
#define OFF_WEA (OFF_WEP + 7L*SZ1M)
#define OFF_WA1 (OFF_WEA + 7L*SZ1M)
#define OFF_WA2 (OFF_WA1 + 4096L*1024L)
#define PER_L   (OFF_WA2 + 4096L*1024L)

// ---------------- scratch (device globals) ----------------
__device__ float g_x[Tt*Dm];
__device__ float g_h[Tt*Dm];
__device__ float g_qkv[Tt*3*INNERd];
__device__ float g_scores[(size_t)Bb*Hh*Nn*Nn];
__device__ float g_o[Tt*INNERd];
__device__ float g_t01[2L*Tt*Dm];                 // T0 = ytf trunk, T1
__device__ float g_pa[(size_t)2*NEXP*Tt*Dm];      // PE then AE
__device__ float g_mid[(size_t)Tt*MLPd];
__device__ float g_w[Lnum*Tt*Ee];
__device__ __half g_whi[2L*PER_L];
__device__ __half g_wlo[2L*PER_L];
__device__ __half g_ahi[(size_t)Tt*MLPd];
__device__ __half g_alo[(size_t)Tt*MLPd];

__device__ __forceinline__ float gelu_f(float v) {
    return 0.5f * v * (1.0f + erff(v * 0.7071067811865475f));
}

__device__ __forceinline__ uint32_t smem_u32(const void* p) {
    uint32_t a;
    asm("{ .reg .u64 t; cvta.to.shared.u64 t, %1; cvt.u32.u64 %0, t; }"
        : "=r"(a) : "l"(p));
    return a;
}

__device__ __forceinline__ void ldmx4(uint32_t* r, uint32_t addr) {
    asm volatile("ldmatrix.sync.aligned.m8n8.x4.shared.b16 {%0,%1,%2,%3}, [%4];"
        : "=r"(r[0]), "=r"(r[1]), "=r"(r[2]), "=r"(r[3]) : "r"(addr));
}
__device__ __forceinline__ void ldmx2(uint32_t* r, uint32_t addr) {
    asm volatile("ldmatrix.sync.aligned.m8n8.x2.shared.b16 {%0,%1}, [%2];"
        : "=r"(r[0]), "=r"(r[1]) : "r"(addr));
}
__device__ __forceinline__ void mma16816(float* d, const uint32_t* a, const uint32_t* b) {
    asm volatile("mma.sync.aligned.m16n8k16.row.col.f32.f16.f16.f32 "
        "{%0,%1,%2,%3}, {%4,%5,%6,%7}, {%8,%9}, {%0,%1,%2,%3};"
        : "+f"(d[0]), "+f"(d[1]), "+f"(d[2]), "+f"(d[3])
        : "r"(a[0]), "r"(a[1]), "r"(a[2]), "r"(a[3]), "r"(b[0]), "r"(b[1]));
}

// ---------------- HMMA GEMM: C[M,N] = (Ahi+Alo)[M,K] @ (Bhi+Blo)^T ----------------
// A: [M,K] fp16 K-major. B: [N,K] fp16 K-major (pre-transposed weights).
// BM=128, BN=128, BK=32; 8 warps (2x4), warp tile 64x32; 2-stage cp.async.
#define BM 128
#define BN 128
#define BK 32
#define LDT 40                      // halves per smem row (pad for ldmatrix)
#define TILE_B (128*LDT*2)          // 10240 bytes per matrix tile
#define ST_AHI 0
#define ST_ALO (1*TILE_B)
#define ST_BHI (2*TILE_B)
#define ST_BLO (3*TILE_B)
#define STAGE_B (4*TILE_B)          // 40960
#define SMEM_MM (2*STAGE_B)         // 81920

__global__ __launch_bounds__(256, 1) void mma_gemm_kernel(
    const __half* __restrict__ Ahi, const __half* __restrict__ Alo,
    const __half* __restrict__ Bhi, const __half* __restrict__ Blo,
    const float* __restrict__ bias, const float* __restrict__ resid,
    float* __restrict__ C,
    int M, int N, int K, long sB, long sC, int act, int hasBias, int hasRes)
{
    extern __shared__ char smem[];
    uint32_t sb = smem_u32(smem);
    const int tid = threadIdx.x;
    const int wid = tid >> 5;
    const int lane = tid & 31;
    const long z = blockIdx.z;
    Bhi += z * sB;
    Blo += z * sB;
    C += z * sC;
    const float* res = hasRes ? (resid + z * sC) : nullptr;
    const int row0 = blockIdx.y * BM;
    const int col0 = blockIdx.x * BN;
    const int wm = wid & 1;    // 64-row block
    const int wn = wid >> 1;   // 32-col block

    float acc[4][4][4];
#pragma unroll
    for (int a = 0; a < 4; a++)
#pragma unroll
        for (int b = 0; b < 4; b++)
#pragma unroll
            for (int c = 0; c < 4; c++) acc[a][b][c] = 0.f;

    const int nc = K / BK;

    // ---- async stage loader: 2048 16B chunks, 8 per thread ----
    auto load_stage = [&](int s, int kt) {
        uint32_t base = sb + s * STAGE_B;
#pragma unroll
        for (int i = 0; i < 8; i++) {
            int idx = i * 256 + tid;
            int mat = idx >> 9;        // 0:Ahi 1:Alo 2:Bhi 3:Blo
            int rem = idx & 511;
            int r = rem >> 2, c = rem & 3;
            uint32_t sa = base + mat * TILE_B + (uint32_t)(r * LDT + c * 8) * 2;
            const __half* gp;
            if (mat == 0)      gp = Ahi + (long)(row0 + r) * K + kt + c * 8;
            else if (mat == 1) gp = Alo + (long)(row0 + r) * K + kt + c * 8;
            else if (mat == 2) gp = Bhi + (long)(col0 + r) * K + kt + c * 8;
            else               gp = Blo + (long)(col0 + r) * K + kt + c * 8;
            asm volatile("cp.async.cg.shared.global [%0], [%1], 16;"
                         :: "r"(sa), "l"(gp));
        }
        asm volatile("cp.async.commit_group;");
    };

    load_stage(0, 0);

    for (int c = 0; c < nc; c++) {
        int s = c & 1;
        if (c + 1 < nc) {
            load_stage(s ^ 1, (c + 1) * BK);
            asm volatile("cp.async.wait_group 1;");
        } else {
            asm volatile("cp.async.wait_group 0;");
        }
        __syncthreads();

        uint32_t base = sb + s * STAGE_B;
#pragma unroll
        for (int ph = 0; ph < 2; ph++) {
            uint32_t ahi[4][4], alo[4][4], bhi[4][2], blo[4][2];
#pragma unroll
            for (int mt = 0; mt < 4; mt++) {
                int rr = wm * 64 + mt * 16 + (lane & 15);
                uint32_t co = (uint32_t)(rr * LDT + ph * 16 + (lane >> 4) * 8) * 2;
                ldmx4(ahi[mt], base + ST_AHI + co);
                ldmx4(alo[mt], base + ST_ALO + co);
            }
#pragma unroll
            for (int nt = 0; nt < 4; nt++) {
                int rr = wn * 32 + nt * 8 + (lane & 7);
                uint32_t co = (uint32_t)(rr * LDT + ph * 16 + ((lane >> 3) & 1) * 8) * 2;
                ldmx2(bhi[nt], base + ST_BHI + co);
                ldmx2(blo[nt], base + ST_BLO + co);
            }
#pragma unroll
            for (int mt = 0; mt < 4; mt++)
#pragma unroll
                for (int nt = 0; nt < 4; nt++) {
                    mma16816(acc[mt][nt], ahi[mt], bhi[nt]);
                    mma16816(acc[mt][nt], ahi[mt], blo[nt]);
                    mma16816(acc[mt][nt], alo[mt], bhi[nt]);
                }
        }
        __syncthreads();
    }

    // ---- epilogue ----
#pragma unroll
    for (int mt = 0; mt < 4; mt++) {
#pragma unroll
        for (int nt = 0; nt < 4; nt++) {
            int rb = row0 + wm * 64 + mt * 16 + (lane >> 2);
            int cc = col0 + wn * 32 + nt * 8 + (lane & 3) * 2;
            float b0 = 0.f, b1 = 0.f;
            if (hasBias) { b0 = bias[cc]; b1 = bias[cc + 1]; }
#pragma unroll
            for (int hf = 0; hf < 2; hf++) {
                int rr = rb + hf * 8;
                float v0 = acc[mt][nt][hf * 2] + b0;
                float v1 = acc[mt][nt][hf * 2 + 1] + b1;
                if (act == 1) { v0 = gelu_f(v0); v1 = gelu_f(v1); }
                if (hasRes) {
                    v0 += res[(long)rr * N + cc];
                    v1 += res[(long)rr * N + cc + 1];
                }
                *(float2*)&C[(long)rr * N + cc] = make_float2(v0, v1);
            }
        }
    }
}

// ---------------- weight transpose + fp16 split: W[K,N] -> Wt[N,K] hi/lo ----------------
__global__ __launch_bounds__(256) void wsplit_kernel(
    const float* __restrict__ W, __half* __restrict__ hi, __half* __restrict__ lo,
    int K, int N, long inStride, long outStride)
{
    __shared__ float tile[32][33];
    const float* Wz = W + blockIdx.z * inStride;
    long ob = blockIdx.z * outStride;
    int k0 = blockIdx.y * 32, n0 = blockIdx.x * 32;
    int tx = threadIdx.x & 31, ty = threadIdx.x >> 5;
#pragma unroll
    for (int i = 0; i < 4; i++)
        tile[ty + i * 8][tx] = Wz[(long)(k0 + ty + i * 8) * N + n0 + tx];
    __syncthreads();
#pragma unroll
    for (int i = 0; i < 4; i++) {
        float v = tile[tx][ty + i * 8];
        __half h = __float2half_rn(v);
        __half l = __float2half_rn(v - __half2float(h));
        long o = ob + (long)(n0 + ty + i * 8) * K + k0 + tx;
        hi[o] = h; lo[o] = l;
    }
}

// ---------------- activation fp16 split ----------------
__global__ __launch_bounds__(256) void asplit_kernel(
    const float4* __restrict__ a, __half2* __restrict__ hi, __half2* __restrict__ lo)
{
    long i = (long)blockIdx.x * 256 + threadIdx.x;
    float4 v = a[i];
    __half hx = __float2half_rn(v.x), hy = __float2half_rn(v.y);
    __half hz = __float2half_rn(v.z), hw = __float2half_rn(v.w);
    __half lx = __float2half_rn(v.x - __half2float(hx));
    __half ly = __float2half_rn(v.y - __half2float(hy));
    __half lz = __float2half_rn(v.z - __half2float(hz));
    __half lw = __float2half_rn(v.w - __half2float(hw));
    hi[i * 2] = __halves2half2(hx, hy); hi[i * 2 + 1] = __halves2half2(hz, hw);
    lo[i * 2] = __halves2half2(lx, ly); lo[i * 2 + 1] = __halves2half2(lz, lw);
}

// ---------------- fp32 tiled SGEMM (attention PV only) ----------------
__global__ __launch_bounds__(256) void sgemm_kernel(
    const float* __restrict__ A, const float* __restrict__ B,
    float* __restrict__ C,
    int M, int N, int K, int lda, int ldb, int ldc,
    int Hd, long sAb, long sAh, long sBb, long sBh, long sCb, long sCh)
{
    int z = blockIdx.z;
    int zb = z / Hd, zh = z % Hd;
    A += zb * sAb + zh * sAh;
    B += zb * sBb + zh * sBh;
    C += zb * sCb + zh * sCh;

    int row0 = blockIdx.y * 128;
    int col0 = blockIdx.x * 64;

    __shared__ float As[16][128];
    __shared__ float Bs[16][64];

    float acc[8][4];
#pragma unroll
    for (int i = 0; i < 8; i++)
#pragma unroll
        for (int j = 0; j < 4; j++) acc[i][j] = 0.f;

    int t = threadIdx.y * 16 + threadIdx.x;

    for (int kt = 0; kt < K; kt += 16) {
#pragma unroll
        for (int li = 0; li < 2; li++) {
            int idx = li * 1024 + t * 4;
            int r = idx >> 4, c = idx & 15;
            float4 v = *(const float4*)(A + (long)(row0 + r) * lda + kt + c);
            As[c + 0][r] = v.x; As[c + 1][r] = v.y;
            As[c + 2][r] = v.z; As[c + 3][r] = v.w;
        }
        {
            int idx = t * 4;
            int r = idx >> 6, c = idx & 63;
            float4 v = *(const float4*)(B + (long)(kt + r) * ldb + col0 + c);
            *(float4*)&Bs[r][c] = v;
        }
        __syncthreads();
#pragma unroll
        for (int kk = 0; kk < 16; kk++) {
            float4 a0 = *(const float4*)&As[kk][threadIdx.y * 8];
            float4 a1 = *(const float4*)&As[kk][threadIdx.y * 8 + 4];
            float4 b0 = *(const float4*)&Bs[kk][threadIdx.x * 4];
            float av[8] = {a0.x, a0.y, a0.z, a0.w, a1.x, a1.y, a1.z, a1.w};
            float bv[4] = {b0.x, b0.y, b0.z, b0.w};
#pragma unroll
            for (int i = 0; i < 8; i++)
#pragma unroll
                for (int j = 0; j < 4; j++) acc[i][j] += av[i] * bv[j];
        }
        __syncthreads();
    }

#pragma unroll
    for (int i = 0; i < 8; i++) {
        int row = row0 + threadIdx.y * 8 + i;
#pragma unroll
        for (int j = 0; j < 4; j++) {
            int col = col0 + threadIdx.x * 4 + j;
            C[(long)row * ldc + col] = acc[i][j];
        }
    }
}

// ---------------- QK^T attention scores ----------------
__global__ __launch_bounds__(256) void qk_kernel(const float* __restrict__ qkv,
                                                 float* __restrict__ scores)
{
    int z = blockIdx.z;
    int b = z / Hh, h = z % Hh;
    const float* Q = qkv + (long)b * Nn * 3 * INNERd + h * DHh;
    const float* Kp = Q + INNERd;
    int q0 = blockIdx.y * 64, k0 = blockIdx.x * 64;

    __shared__ float Qs[64][68];
    __shared__ float Ks[64][68];

    int t = threadIdx.y * 16 + threadIdx.x;
#pragma unroll
    for (int li = 0; li < 16; li++) {
        int idx = li * 256 + t;
        int r = idx >> 6, d = idx & 63;
        Qs[d][r] = Q[(long)(q0 + r) * (3 * INNERd) + d];
        Ks[d][r] = Kp[(long)(k0 + r) * (3 * INNERd) + d];
    }
    __syncthreads();

    float acc[4][4];
#pragma unroll
    for (int i = 0; i < 4; i++)
#pragma unroll
        for (int j = 0; j < 4; j++) acc[i][j] = 0.f;

#pragma unroll 8
    for (int d = 0; d < 64; d++) {
        float4 qv = *(const float4*)&Qs[d][threadIdx.y * 4];
        float4 kv = *(const float4*)&Ks[d][threadIdx.x * 4];
        float av[4] = {qv.x, qv.y, qv.z, qv.w};
        float bv[4] = {kv.x, kv.y, kv.z, kv.w};
#pragma unroll
        for (int i = 0; i < 4; i++)
#pragma unroll
            for (int j = 0; j < 4; j++) acc[i][j] += av[i] * bv[j];
    }

    float* out = scores + (long)z * Nn * Nn;
#pragma unroll
    for (int i = 0; i < 4; i++)
#pragma unroll
        for (int j = 0; j < 4; j++)
            out[(long)(q0 + threadIdx.y * 4 + i) * Nn + k0 + threadIdx.x * 4 + j] =
                acc[i][j] * 0.125f;
}

// ---------------- softmax over last dim ----------------
__global__ __launch_bounds__(256) void softmax_kernel(float* __restrict__ s)
{
    float* p = s + (size_t)blockIdx.x * Nn;
    int tid = threadIdx.x;
    __shared__ float red[256];

    float v[4];
    float m = -3.4e38f;
#pragma unroll
    for (int i = 0; i < 4; i++) { v[i] = p[tid + i * 256]; m = fmaxf(m, v[i]); }
    red[tid] = m; __syncthreads();
    for (int st = 128; st > 0; st >>= 1) {
        if (tid < st) red[tid] = fmaxf(red[tid], red[tid + st]);
        __syncthreads();
    }
    m = red[0]; __syncthreads();

    float sum = 0.f;
#pragma unroll
    for (int i = 0; i < 4; i++) { v[i] = expf(v[i] - m); sum += v[i]; }
    red[tid] = sum; __syncthreads();
    for (int st = 128; st > 0; st >>= 1) {
        if (tid < st) red[tid] += red[tid + st];
        __syncthreads();
    }
    float inv = 1.f / red[0];
#pragma unroll
    for (int i = 0; i < 4; i++) p[tid + i * 256] = v[i] * inv;
}

// ---------------- LayerNorm ----------------
__global__ __launch_bounds__(256) void ln_kernel(const float* __restrict__ x,
                                                 const float* __restrict__ g,
                                                 const float* __restrict__ bta,
                                                 float* __restrict__ out)
{
    int t = blockIdx.x, tid = threadIdx.x;
    const float* xp = x + (long)t * Dm;
    __shared__ float r1[256], r2[256];

    float v[4], s = 0.f, s2 = 0.f;
#pragma unroll
    for (int i = 0; i < 4; i++) { v[i] = xp[tid + i * 256]; s += v[i]; s2 += v[i] * v[i]; }
    r1[tid] = s; r2[tid] = s2; __syncthreads();
    for (int st = 128; st > 0; st >>= 1) {
        if (tid < st) { r1[tid] += r1[tid + st]; r2[tid] += r2[tid + st]; }
        __syncthreads();
    }
    float mean = r1[0] * (1.f / Dm);
    float var = r2[0] * (1.f / Dm) - mean * mean;
    float rstd = rsqrtf(var + 1e-5f);
    float* op = out + (long)t * Dm;
#pragma unroll
    for (int i = 0; i < 4; i++) {
        int d = tid + i * 256;
        op[d] = (v[i] - mean) * rstd * g[d] + bta[d];
    }
}

// ---------------- router ----------------
__global__ __launch_bounds__(128) void router_kernel(const float* __restrict__ x,
                                                     const float* __restrict__ Wr,
                                                     const float* __restrict__ br,
                                                     float* __restrict__ wout)
{
    int t = blockIdx.x, tid = threadIdx.x;
    __shared__ float part[128][Ee];
    float acc[Ee];
#pragma unroll
    for (int e = 0; e < Ee; e++) acc[e] = 0.f;
    const float* xp = x + (long)t * Dm;
    for (int d = tid; d < Dm; d += 128) {
        float xv = xp[d];
        const float* wrow = Wr + (long)d * Ee;
#pragma unroll
        for (int e = 0; e < Ee; e++) acc[e] += xv * wrow[e];
    }
#pragma unroll
    for (int e = 0; e < Ee; e++) part[tid][e] = acc[e];
    __syncthreads();
    for (int st = 64; st > 0; st >>= 1) {
        if (tid < st)
#pragma unroll
            for (int e = 0; e < Ee; e++) part[tid][e] += part[tid + st][e];
        __syncthreads();
    }
    if (tid == 0) {
        float lg[Ee];
#pragma unroll
        for (int e = 0; e < Ee; e++) lg[e] = part[0][e] + br[e];
        float m1 = -3.4e38f, m2 = -3.4e38f;
#pragma unroll
        for (int e = 0; e < Ee; e++) {
            float v = lg[e];
            if (v > m1) { m2 = m1; m1 = v; }
            else if (v > m2) m2 = v;
        }
        float sum = 0.f, we[Ee];
#pragma unroll
        for (int e = 0; e < Ee; e++) {
            we[e] = (lg[e] < m2) ? 0.f : expf(lg[e] - m1);
            sum += we[e];
        }
        float inv = 1.f / sum;
#pragma unroll
        for (int e = 0; e < Ee; e++) wout[(long)t * Ee + e] = we[e] * inv;
    }
}

// ---------------- FiLM elementwise: t0 = gelu(t0+b0)*(t1+b1) ----------------
__global__ __launch_bounds__(256) void film_kernel(float* __restrict__ t0,
                                                   const float* __restrict__ t1,
                                                   const float* __restrict__ b0,
                                                   const float* __restrict__ b1)
{
    long i = (long)blockIdx.x * 256 + threadIdx.x;
    int d = (int)(i & (Dm - 1));
    t0[i] = gelu_f(t0[i] + b0[d]) * (t1[i] + b1[d]);
}

// ---------------- expert mixing ----------------
__global__ __launch_bounds__(256) void mix_kernel(const float* __restrict__ ytf,
                                                  const float* __restrict__ pe,
                                                  const float* __restrict__ ae,
                                                  const float* __restrict__ Pb,
                                                  const float* __restrict__ Ab,
                                                  const float* __restrict__ w,
                                                  float* __restrict__ y)
{
    int t = blockIdx.x;
    __shared__ float ws[Ee];
    if (threadIdx.x < Ee) ws[threadIdx.x] = w[(long)t * Ee + threadIdx.x];
    __syncthreads();
#pragma unroll
    for (int it = 0; it < 4; it++) {
        int d = threadIdx.x + it * 256;
        long td = (long)t * Dm + d;
        float yv = ytf[td];
        float out = ws[0] * gelu_f(yv);
#pragma unroll
        for (int e = 0; e < NEXP; e++) {
            float we = ws[e + 1];
            if (we != 0.f) {
                float p = pe[(long)e * Tt * Dm + td] + Pb[e * Dm + d];
                float a = ae[(long)e * Tt * Dm + td] + Ab[e * Dm + d];
                out += we * (p * yv + a);
            }
        }
        y[td] = out;
    }
}

// ---------------- host helpers ----------------
static float* symf(const void* s) { void* p = nullptr; cudaGetSymbolAddress(&p, s); return (float*)p; }
static __half* symh(const void* s) { void* p = nullptr; cudaGetSymbolAddress(&p, s); return (__half*)p; }

static void wsplit(const float* W, __half* hi, __half* lo, int K, int N,
                   long inStride, long outStride, int z)
{
    dim3 grid(N / 32, K / 32, z);
    wsplit_kernel<<<grid, 256>>>(W, hi, lo, K, N, inStride, outStride);
}

static void asplit(const float* a, __half* hi, __half* lo, long n)
{
    asplit_kernel<<<(int)(n / 4 / 256), 256>>>((const float4*)a, (__half2*)hi, (__half2*)lo);
}

static void tgemm(const __half* ahi, const __half* alo,
                  const __half* bhi, const __half* blo,
                  const float* bias, const float* resid, float* C,
                  int N, int K, int Z, long sB, long sC, int act)
{
    dim3 grid(N / BN, Tt / BM, Z);
    mma_gemm_kernel<<<grid, 256, SMEM_MM>>>(ahi, alo, bhi, blo, bias, resid, C,
                                            Tt, N, K, sB, sC, act,
                                            bias != nullptr, resid != nullptr);
}

extern "C" void kernel_launch(void* const* d_in, const int* in_sizes, int n_in,
                              void* d_out, int out_size)
{
    const float* x_in  = (const float*)d_in[0];
    const float* ln1_g = (const float*)d_in[1];
    const float* ln1_b = (const float*)d_in[2];
    const float* Wqkv  = (const float*)d_in[3];
    const float* bqkv  = (const float*)d_in[4];
    const float* Wo    = (const float*)d_in[5];
    const float* bo    = (const float*)d_in[6];
    const float* Wr    = (const float*)d_in[7];
    const float* br    = (const float*)d_in[8];
    const float* Wa1   = (const float*)d_in[9];
    const float* ba1   = (const float*)d_in[10];
    const float* Wa2   = (const float*)d_in[11];
    const float* ba2   = (const float*)d_in[12];
    const float* ln2_g = (const float*)d_in[13];
    const float* ln2_b = (const float*)d_in[14];
    const float* Wb0   = (const float*)d_in[15];
    const float* bb0   = (const float*)d_in[16];
    const float* Wb1   = (const float*)d_in[17];
    const float* bb1   = (const float*)d_in[18];
    const float* We_p  = (const float*)d_in[19];
    const float* be_p  = (const float*)d_in[20];
    const float* We_a  = (const float*)d_in[21];
    const float* be_a  = (const float*)d_in[22];

    float* X   = symf(g_x);
    float* Hb  = symf(g_h);
    float* QKV = symf(g_qkv);
    float* S   = symf(g_scores);
    float* O   = symf(g_o);
    float* T01 = symf(g_t01);
    float* T0  = T01;
    float* T1  = T01 + (long)Tt * Dm;
    float* PA  = symf(g_pa);
    float* MID = symf(g_mid);
    float* Wt  = symf(g_w);
    __half* WHI = symh(g_whi);
    __half* WLO = symh(g_wlo);
    __half* AHI = symh(g_ahi);
    __half* ALO = symh(g_alo);

    cudaFuncSetAttribute(mma_gemm_kernel,
                         cudaFuncAttributeMaxDynamicSharedMemorySize, SMEM_MM);

    // ---- weight transpose + split ----
    wsplit(Wqkv, WHI + OFF_QKV, WLO + OFF_QKV, 1024, 3072, 3072L * 1024, PER_L, Lnum);
    wsplit(Wo,   WHI + OFF_WO,  WLO + OFF_WO,  1024, 1024, SZ1M, PER_L, Lnum);
    wsplit(Wb0,  WHI + OFF_WB0, WLO + OFF_WB0, 1024, 1024, SZ1M, PER_L, Lnum);
    wsplit(Wb1,  WHI + OFF_WB1, WLO + OFF_WB1, 1024, 1024, SZ1M, PER_L, Lnum);
    for (int l = 0; l < Lnum; l++) {
        wsplit(We_p + (long)l * NEXP * SZ1M, WHI + l * PER_L + OFF_WEP,
               WLO + l * PER_L + OFF_WEP, 1024, 1024, SZ1M, SZ1M, NEXP);
        wsplit(We_a + (long)l * NEXP * SZ1M, WHI + l * PER_L + OFF_WEA,
               WLO + l * PER_L + OFF_WEA, 1024, 1024, SZ1M, SZ1M, NEXP);
    }
    wsplit(Wa1, WHI + OFF_WA1, WLO + OFF_WA1, 1024, 4096, 4096L * 1024, PER_L, Lnum);
    wsplit(Wa2, WHI + OFF_WA2, WLO + OFF_WA2, 4096, 1024, 4096L * 1024, PER_L, Lnum);

    cudaMemcpyAsync(X, x_in, (size_t)Tt * Dm * sizeof(float),
                    cudaMemcpyDeviceToDevice, 0);

    for (int l = 0; l < Lnum; l++) {
        const __half* whl = WHI + (long)l * PER_L;
        const __half* wll = WLO + (long)l * PER_L;

        // --- attention ---
        ln_kernel<<<Tt, 256>>>(X, ln1_g + l * Dm, ln1_b + l * Dm, Hb);
        asplit(Hb, AHI, ALO, (long)Tt * Dm);
        tgemm(AHI, ALO, whl + OFF_QKV, wll + OFF_QKV,
              bqkv + (long)l * 3 * INNERd, nullptr, QKV, 3 * INNERd, Dm, 1, 0, 0, 0);

        {
            dim3 grid(Nn / 64, Nn / 64, Bb * Hh), block(16, 16);
            qk_kernel<<<grid, block>>>(QKV, S);
        }
        softmax_kernel<<<Bb * Hh * Nn, 256>>>(S);

        {   // PV: O[b,n,h*DH+d] = sum_k S[b,h,n,k] * V[b,k,h*DH+d]
            dim3 grid(1, Nn / 128, Bb * Hh), block(16, 16);
            sgemm_kernel<<<grid, block>>>(S, QKV + 2 * INNERd, O,
                Nn, DHh, Nn, Nn, 3 * INNERd, INNERd,
                Hh, (long)Hh * Nn * Nn, (long)Nn * Nn,
                (long)Nn * 3 * INNERd, DHh,
                (long)Nn * INNERd, DHh);
        }

        asplit(O, AHI, ALO, (long)Tt * INNERd);
        tgemm(AHI, ALO, whl + OFF_WO, wll + OFF_WO,
              bo + (long)l * Dm, X, X, Dm, INNERd, 1, 0, 0, 0);

        // --- router ---
        router_kernel<<<Tt, 128>>>(X, Wr + (long)l * Dm * Ee, br + (long)l * Ee,
                                   Wt + (long)l * Tt * Ee);

        // --- FiLM trunk: Wb0 & Wb1 batched (z=2), biases added in film ---
        ln_kernel<<<Tt, 256>>>(X, ln2_g + l * Dm, ln2_b + l * Dm, Hb);
        asplit(Hb, AHI, ALO, (long)Tt * Dm);
        tgemm(AHI, ALO, whl + OFF_WB0, wll + OFF_WB0,
              nullptr, nullptr, T01, Dm, Dm, 2, SZ1M, (long)Tt * Dm, 0);
        film_kernel<<<(Tt * Dm) / 256, 256>>>(T0, T1, bb0 + (long)l * Dm,
                                              bb1 + (long)l * Dm);   // T0 := ytf

        // --- 14 expert GEMMs in one batched launch ---
        asplit(T0, AHI, ALO, (long)Tt * Dm);
        tgemm(AHI, ALO, whl + OFF_WEP, wll + OFF_WEP,
              nullptr, nullptr, PA, Dm, Dm, 2 * NEXP, SZ1M, (long)Tt * Dm, 0);

        // --- mix (T1 := y) ---
        mix_kernel<<<Tt, 256>>>(T0, PA, PA + (long)NEXP * Tt * Dm,
                                be_p + (long)l * NEXP * Dm,
                                be_a + (long)l * NEXP * Dm,
                                Wt + (long)l * Tt * Ee, T1);

        // --- adaptor MLP + residual ---
        asplit(T1, AHI, ALO, (long)Tt * Dm);
        tgemm(AHI, ALO, whl + OFF_WA1, wll + OFF_WA1,
              ba1 + (long)l * MLPd, nullptr, MID, MLPd, Dm, 1, 0, 0, 1 /*gelu*/);
        asplit(MID, AHI, ALO, (long)Tt * MLPd);
        tgemm(AHI, ALO, whl + OFF_WA2, wll + OFF_WA2,
              ba2 + (long)l * Dm, X, X, Dm, MLPd, 1, 0, 0, 0);
    }

    // outputs: x [B,N,D] then stacked router weights [L,B,N,E]
    cudaMemcpyAsync(d_out, X, (size_t)Tt * Dm * sizeof(float),
                    cudaMemcpyDeviceToDevice, 0);
    if (out_size >= Tt * Dm + Lnum * Tt * Ee) {
        cudaMemcpyAsync((float*)d_out + (size_t)Tt * Dm, Wt,
                        (size_t)Lnum * Tt * Ee * sizeof(float),
                        cudaMemcpyDeviceToDevice, 0);
    }
}

// round 6
// speedup vs baseline: 2.3296x; 1.1869x over previous
#include <cuda_runtime.h>
#include <cuda_fp16.h>
#include <cstdint>
#include <math.h>

// ---------------- problem constants ----------------
#define Dm     1024
#define Lnum   2
#define Hh     16
#define DHh    64
#define INNERd 1024
#define MLPd   4096
#define Ee     8
#define Bb     4
#define Nn     1024
#define Tt     (Bb*Nn)
#define NEXP   (Ee-1)

// weight pack offsets (elements, per layer)
#define SZ1M   (1024L*1024L)
#define OFF_QKV 0L
#define OFF_WO  (OFF_QKV + 3072L*1024L)
#define OFF_WB0 (OFF_WO  + SZ1M)
#define OFF_WB1 (OFF_WB0 + SZ1M)
#define OFF_WEP (OFF_WB1 + SZ1M)
#define OFF_WEA (OFF_WEP + 7L*SZ1M)
#define OFF_WA1 (OFF_WEA + 7L*SZ1M)
#define OFF_WA2 (OFF_WA1 + 4096L*1024L)
#define PER_L   (OFF_WA2 + 4096L*1024L)

// ---------------- scratch (device globals) ----------------
__device__ float g_x[Tt*Dm];
__device__ float g_t01[2L*Tt*Dm];                 // T0/T1 (FiLM), T0 also ytf
__device__ float g_pa[(size_t)2*NEXP*Tt*Dm];      // PE then AE
__device__ float g_w[Lnum*Tt*Ee];
__device__ __half g_whi[2L*PER_L];
__device__ __half g_wlo[2L*PER_L];
__device__ __half g_ahi[(size_t)Tt*Dm];           // activation hi (split producers)
__device__ __half g_alo[(size_t)Tt*Dm];           // activation lo
__device__ __half g_mhi[(size_t)Tt*MLPd];         // MLP mid hi
__device__ __half g_mlo[(size_t)Tt*MLPd];         // MLP mid lo
__device__ __half g_qkvh[(size_t)Tt*3*INNERd];    // fp16 qkv
__device__ __half g_vt[(size_t)Bb*Hh*DHh*Nn];     // V transposed [z][d][k]
__device__ __half g_sh[(size_t)Bb*Hh*Nn*Nn];      // fp16 scores/probs

__device__ __forceinline__ float gelu_f(float v) {
    return 0.5f * v * (1.0f + erff(v * 0.7071067811865475f));
}

__device__ __forceinline__ uint32_t smem_u32(const void* p) {
    uint32_t a;
    asm("{ .reg .u64 t; cvta.to.shared.u64 t, %1; cvt.u32.u64 %0, t; }"
        : "=r"(a) : "l"(p));
    return a;
}
__device__ __forceinline__ void ldmx4(uint32_t* r, uint32_t addr) {
    asm volatile("ldmatrix.sync.aligned.m8n8.x4.shared.b16 {%0,%1,%2,%3}, [%4];"
        : "=r"(r[0]), "=r"(r[1]), "=r"(r[2]), "=r"(r[3]) : "r"(addr));
}
__device__ __forceinline__ void ldmx2(uint32_t* r, uint32_t addr) {
    asm volatile("ldmatrix.sync.aligned.m8n8.x2.shared.b16 {%0,%1}, [%2];"
        : "=r"(r[0]), "=r"(r[1]) : "r"(addr));
}
__device__ __forceinline__ void mma16816(float* d, const uint32_t* a, const uint32_t* b) {
    asm volatile("mma.sync.aligned.m16n8k16.row.col.f32.f16.f16.f32 "
        "{%0,%1,%2,%3}, {%4,%5,%6,%7}, {%8,%9}, {%0,%1,%2,%3};"
        : "+f"(d[0]), "+f"(d[1]), "+f"(d[2]), "+f"(d[3])
        : "r"(a[0]), "r"(a[1]), "r"(a[2]), "r"(a[3]), "r"(b[0]), "r"(b[1]));
}

// ================= split HMMA GEMM: C = (Ahi+Alo)[M,K] @ (Bhi+Blo)[N,K]^T =================
#define BM 128
#define BN 128
#define BK 32
#define LDT 40
#define TILE_B (128*LDT*2)
#define ST_AHI 0
#define ST_ALO (1*TILE_B)
#define ST_BHI (2*TILE_B)
#define ST_BLO (3*TILE_B)
#define STAGE_B (4*TILE_B)
#define SMEM_MM (2*STAGE_B)

__global__ __launch_bounds__(256, 1) void mma_gemm_kernel(
    const __half* __restrict__ Ahi, const __half* __restrict__ Alo,
    const __half* __restrict__ Bhi, const __half* __restrict__ Blo,
    const float* __restrict__ bias, const float* __restrict__ resid,
    float* __restrict__ C, __half* __restrict__ Chi, __half* __restrict__ Clo,
    int M, int N, int K, long sB, long sC, int act,
    int hasBias, int hasRes, int wantF32, int wantHi, int wantLo)
{
    extern __shared__ char smem[];
    uint32_t sb = smem_u32(smem);
    const int tid = threadIdx.x;
    const int wid = tid >> 5;
    const int lane = tid & 31;
    const long z = blockIdx.z;
    Bhi += z * sB;
    Blo += z * sB;
    if (wantF32) C += z * sC;
    if (wantHi) Chi += z * sC;
    if (wantLo) Clo += z * sC;
    const float* res = hasRes ? (resid + z * sC) : nullptr;
    const int row0 = blockIdx.y * BM;
    const int col0 = blockIdx.x * BN;
    const int wm = wid & 1;
    const int wn = wid >> 1;

    float acc[4][4][4];
#pragma unroll
    for (int a = 0; a < 4; a++)
#pragma unroll
        for (int b = 0; b < 4; b++)
#pragma unroll
            for (int c = 0; c < 4; c++) acc[a][b][c] = 0.f;

    const int nc = K / BK;

    auto load_stage = [&](int s, int kt) {
        uint32_t base = sb + s * STAGE_B;
#pragma unroll
        for (int i = 0; i < 8; i++) {
            int idx = i * 256 + tid;
            int mat = idx >> 9;
            int rem = idx & 511;
            int r = rem >> 2, c = rem & 3;
            uint32_t sa = base + mat * TILE_B + (uint32_t)(r * LDT + c * 8) * 2;
            const __half* gp;
            if (mat == 0)      gp = Ahi + (long)(row0 + r) * K + kt + c * 8;
            else if (mat == 1) gp = Alo + (long)(row0 + r) * K + kt + c * 8;
            else if (mat == 2) gp = Bhi + (long)(col0 + r) * K + kt + c * 8;
            else               gp = Blo + (long)(col0 + r) * K + kt + c * 8;
            asm volatile("cp.async.cg.shared.global [%0], [%1], 16;"
                         :: "r"(sa), "l"(gp));
        }
        asm volatile("cp.async.commit_group;");
    };

    load_stage(0, 0);

    for (int c = 0; c < nc; c++) {
        int s = c & 1;
        if (c + 1 < nc) {
            load_stage(s ^ 1, (c + 1) * BK);
            asm volatile("cp.async.wait_group 1;");
        } else {
            asm volatile("cp.async.wait_group 0;");
        }
        __syncthreads();

        uint32_t base = sb + s * STAGE_B;
#pragma unroll
        for (int ph = 0; ph < 2; ph++) {
            uint32_t ahi[4][4], alo[4][4], bhi[4][2], blo[4][2];
#pragma unroll
            for (int mt = 0; mt < 4; mt++) {
                int rr = wm * 64 + mt * 16 + (lane & 15);
                uint32_t co = (uint32_t)(rr * LDT + ph * 16 + (lane >> 4) * 8) * 2;
                ldmx4(ahi[mt], base + ST_AHI + co);
                ldmx4(alo[mt], base + ST_ALO + co);
            }
#pragma unroll
            for (int nt = 0; nt < 4; nt++) {
                int rr = wn * 32 + nt * 8 + (lane & 7);
                uint32_t co = (uint32_t)(rr * LDT + ph * 16 + ((lane >> 3) & 1) * 8) * 2;
                ldmx2(bhi[nt], base + ST_BHI + co);
                ldmx2(blo[nt], base + ST_BLO + co);
            }
#pragma unroll
            for (int mt = 0; mt < 4; mt++)
#pragma unroll
                for (int nt = 0; nt < 4; nt++) {
                    mma16816(acc[mt][nt], ahi[mt], bhi[nt]);
                    mma16816(acc[mt][nt], ahi[mt], blo[nt]);
                    mma16816(acc[mt][nt], alo[mt], bhi[nt]);
                }
        }
        __syncthreads();
    }

#pragma unroll
    for (int mt = 0; mt < 4; mt++) {
#pragma unroll
        for (int nt = 0; nt < 4; nt++) {
            int rb = row0 + wm * 64 + mt * 16 + (lane >> 2);
            int cc = col0 + wn * 32 + nt * 8 + (lane & 3) * 2;
            float b0 = 0.f, b1 = 0.f;
            if (hasBias) { b0 = bias[cc]; b1 = bias[cc + 1]; }
#pragma unroll
            for (int hf = 0; hf < 2; hf++) {
                int rr = rb + hf * 8;
                float v0 = acc[mt][nt][hf * 2] + b0;
                float v1 = acc[mt][nt][hf * 2 + 1] + b1;
                if (act == 1) { v0 = gelu_f(v0); v1 = gelu_f(v1); }
                if (hasRes) {
                    v0 += res[(long)rr * N + cc];
                    v1 += res[(long)rr * N + cc + 1];
                }
                long o = (long)rr * N + cc;
                if (wantF32) *(float2*)&C[o] = make_float2(v0, v1);
                if (wantHi) {
                    __half h0 = __float2half_rn(v0), h1 = __float2half_rn(v1);
                    *(__half2*)&Chi[o] = __halves2half2(h0, h1);
                    if (wantLo) {
                        __half l0 = __float2half_rn(v0 - __half2float(h0));
                        __half l1 = __float2half_rn(v1 - __half2float(h1));
                        *(__half2*)&Clo[o] = __halves2half2(l0, l1);
                    }
                }
            }
        }
    }
}

// ================= single-term fp16 HMMA (attention QK^T and P*V) =================
// A [M,K] row-major(ld=lda), B [N,K] K-major(ld=ldb); out half (hi[,lo]) scaled.
#define HBM 128
#define HBN 64
#define HBK 64
#define LDTH 72
#define H_ATILE (128*LDTH*2)
#define H_BTILE (64*LDTH*2)
#define H_STAGE (H_ATILE + H_BTILE)
#define SMEM_H  (2*H_STAGE)

__global__ __launch_bounds__(256, 1) void mma_h_kernel(
    const __half* __restrict__ A, const __half* __restrict__ B,
    __half* __restrict__ Chi, __half* __restrict__ Clo,
    int K, int lda, int ldb, int ldc, int Hd,
    long sAb, long sAh, long sBb, long sBh, long sCb, long sCh,
    float scale, int wantLo)
{
    extern __shared__ char smem[];
    uint32_t sb = smem_u32(smem);
    const int tid = threadIdx.x;
    const int wid = tid >> 5;
    const int lane = tid & 31;
    const int z = blockIdx.z;
    const int zb = z / Hd, zh = z % Hd;
    A += (long)zb * sAb + (long)zh * sAh;
    B += (long)zb * sBb + (long)zh * sBh;
    Chi += (long)zb * sCb + (long)zh * sCh;
    if (wantLo) Clo += (long)zb * sCb + (long)zh * sCh;
    const int row0 = blockIdx.y * HBM;
    const int col0 = blockIdx.x * HBN;
    const int wm = wid & 1;
    const int wn = wid >> 1;   // 0..3, 16 cols each

    float acc[4][2][4];
#pragma unroll
    for (int a = 0; a < 4; a++)
#pragma unroll
        for (int b = 0; b < 2; b++)
#pragma unroll
            for (int c = 0; c < 4; c++) acc[a][b][c] = 0.f;

    const int nc = K / HBK;

    auto load_stage = [&](int s, int kt) {
        uint32_t base = sb + s * H_STAGE;
#pragma unroll
        for (int i = 0; i < 6; i++) {
            int idx = i * 256 + tid;
            if (idx < 1024) {          // A: 128 rows x 8 chunks
                int r = idx >> 3, c = idx & 7;
                uint32_t sa = base + (uint32_t)(r * LDTH + c * 8) * 2;
                const __half* gp = A + (long)(row0 + r) * lda + kt + c * 8;
                asm volatile("cp.async.cg.shared.global [%0], [%1], 16;"
                             :: "r"(sa), "l"(gp));
            } else {                   // B: 64 rows x 8 chunks
                int j = idx - 1024;
                int r = j >> 3, c = j & 7;
                uint32_t sa = base + H_ATILE + (uint32_t)(r * LDTH + c * 8) * 2;
                const __half* gp = B + (long)(col0 + r) * ldb + kt + c * 8;
                asm volatile("cp.async.cg.shared.global [%0], [%1], 16;"
                             :: "r"(sa), "l"(gp));
            }
        }
        asm volatile("cp.async.commit_group;");
    };

    load_stage(0, 0);

    for (int c = 0; c < nc; c++) {
        int s = c & 1;
        if (c + 1 < nc) {
            load_stage(s ^ 1, (c + 1) * HBK);
            asm volatile("cp.async.wait_group 1;");
        } else {
            asm volatile("cp.async.wait_group 0;");
        }
        __syncthreads();

        uint32_t base = sb + s * H_STAGE;
#pragma unroll
        for (int ph = 0; ph < 4; ph++) {
            uint32_t af[4][4], bf[2][2];
#pragma unroll
            for (int mt = 0; mt < 4; mt++) {
                int rr = wm * 64 + mt * 16 + (lane & 15);
                uint32_t co = (uint32_t)(rr * LDTH + ph * 16 + (lane >> 4) * 8) * 2;
                ldmx4(af[mt], base + co);
            }
#pragma unroll
            for (int nt = 0; nt < 2; nt++) {
                int rr = wn * 16 + nt * 8 + (lane & 7);
                uint32_t co = (uint32_t)(rr * LDTH + ph * 16 + ((lane >> 3) & 1) * 8) * 2;
                ldmx2(bf[nt], base + H_ATILE + co);
            }
#pragma unroll
            for (int mt = 0; mt < 4; mt++)
#pragma unroll
                for (int nt = 0; nt < 2; nt++)
                    mma16816(acc[mt][nt], af[mt], bf[nt]);
        }
        __syncthreads();
    }

#pragma unroll
    for (int mt = 0; mt < 4; mt++) {
#pragma unroll
        for (int nt = 0; nt < 2; nt++) {
            int rb = row0 + wm * 64 + mt * 16 + (lane >> 2);
            int cc = col0 + wn * 16 + nt * 8 + (lane & 3) * 2;
#pragma unroll
            for (int hf = 0; hf < 2; hf++) {
                int rr = rb + hf * 8;
                float v0 = acc[mt][nt][hf * 2] * scale;
                float v1 = acc[mt][nt][hf * 2 + 1] * scale;
                __half h0 = __float2half_rn(v0), h1 = __float2half_rn(v1);
                long o = (long)rr * ldc + cc;
                *(__half2*)&Chi[o] = __halves2half2(h0, h1);
                if (wantLo) {
                    __half l0 = __float2half_rn(v0 - __half2float(h0));
                    __half l1 = __float2half_rn(v1 - __half2float(h1));
                    *(__half2*)&Clo[o] = __halves2half2(l0, l1);
                }
            }
        }
    }
}

// ---------------- V transpose: qkvh[b,k,2048+h*64+d] -> vt[(z*64+d), k] ----------------
__global__ __launch_bounds__(256) void vtrans_kernel(const __half* __restrict__ qkvh,
                                                     __half* __restrict__ vt)
{
    __shared__ __half t[32][33];
    int z = blockIdx.z, b = z >> 4, h = z & 15;
    int k0 = blockIdx.x * 32, d0 = blockIdx.y * 32;
    int tx = threadIdx.x & 31, ty = threadIdx.x >> 5;
#pragma unroll
    for (int i = 0; i < 4; i++) {
        int k = k0 + ty + i * 8;
        t[ty + i * 8][tx] = qkvh[(long)(b * Nn + k) * 3072 + 2048 + h * 64 + d0 + tx];
    }
    __syncthreads();
#pragma unroll
    for (int i = 0; i < 4; i++) {
        int d = d0 + ty + i * 8;
        vt[((long)z * 64 + d) * Nn + k0 + tx] = t[tx][ty + i * 8];
    }
}

// ---------------- fp16 softmax over rows of 1024 ----------------
__global__ __launch_bounds__(256) void softmax_h_kernel(__half* __restrict__ s)
{
    __half2* p = (__half2*)(s + (size_t)blockIdx.x * Nn);
    int tid = threadIdx.x;
    __shared__ float red[256];

    __half2 a = p[tid * 2], b = p[tid * 2 + 1];
    float v[4] = {__low2float(a), __high2float(a), __low2float(b), __high2float(b)};
    float m = fmaxf(fmaxf(v[0], v[1]), fmaxf(v[2], v[3]));
    red[tid] = m; __syncthreads();
    for (int st = 128; st > 0; st >>= 1) {
        if (tid < st) red[tid] = fmaxf(red[tid], red[tid + st]);
        __syncthreads();
    }
    m = red[0]; __syncthreads();

    float sum = 0.f;
#pragma unroll
    for (int i = 0; i < 4; i++) { v[i] = expf(v[i] - m); sum += v[i]; }
    red[tid] = sum; __syncthreads();
    for (int st = 128; st > 0; st >>= 1) {
        if (tid < st) red[tid] += red[tid + st];
        __syncthreads();
    }
    float inv = 1.f / red[0];
    p[tid * 2]     = __halves2half2(__float2half_rn(v[0] * inv), __float2half_rn(v[1] * inv));
    p[tid * 2 + 1] = __halves2half2(__float2half_rn(v[2] * inv), __float2half_rn(v[3] * inv));
}

// ---------------- weight transpose + fp16 split ----------------
__global__ __launch_bounds__(256) void wsplit_kernel(
    const float* __restrict__ W, __half* __restrict__ hi, __half* __restrict__ lo,
    int K, int N, long inStride, long outStride)
{
    __shared__ float tile[32][33];
    const float* Wz = W + blockIdx.z * inStride;
    long ob = blockIdx.z * outStride;
    int k0 = blockIdx.y * 32, n0 = blockIdx.x * 32;
    int tx = threadIdx.x & 31, ty = threadIdx.x >> 5;
#pragma unroll
    for (int i = 0; i < 4; i++)
        tile[ty + i * 8][tx] = Wz[(long)(k0 + ty + i * 8) * N + n0 + tx];
    __syncthreads();
#pragma unroll
    for (int i = 0; i < 4; i++) {
        float v = tile[tx][ty + i * 8];
        __half h = __float2half_rn(v);
        __half l = __float2half_rn(v - __half2float(h));
        long o = ob + (long)(n0 + ty + i * 8) * K + k0 + tx;
        hi[o] = h; lo[o] = l;
    }
}

// ---------------- LayerNorm -> fp16 hi/lo ----------------
__global__ __launch_bounds__(256) void ln_split_kernel(
    const float* __restrict__ x, const float* __restrict__ g,
    const float* __restrict__ bta,
    __half* __restrict__ hi, __half* __restrict__ lo)
{
    int t = blockIdx.x, tid = threadIdx.x;
    const float* xp = x + (long)t * Dm;
    __shared__ float r1[256], r2[256];

    float v[4], s = 0.f, s2 = 0.f;
#pragma unroll
    for (int i = 0; i < 4; i++) { v[i] = xp[tid + i * 256]; s += v[i]; s2 += v[i] * v[i]; }
    r1[tid] = s; r2[tid] = s2; __syncthreads();
    for (int st = 128; st > 0; st >>= 1) {
        if (tid < st) { r1[tid] += r1[tid + st]; r2[tid] += r2[tid + st]; }
        __syncthreads();
    }
    float mean = r1[0] * (1.f / Dm);
    float var = r2[0] * (1.f / Dm) - mean * mean;
    float rstd = rsqrtf(var + 1e-5f);
#pragma unroll
    for (int i = 0; i < 4; i++) {
        int d = tid + i * 256;
        float y = (v[i] - mean) * rstd * g[d] + bta[d];
        __half h = __float2half_rn(y);
        hi[(long)t * Dm + d] = h;
        lo[(long)t * Dm + d] = __float2half_rn(y - __half2float(h));
    }
}

// ---------------- router ----------------
__global__ __launch_bounds__(128) void router_kernel(const float* __restrict__ x,
                                                     const float* __restrict__ Wr,
                                                     const float* __restrict__ br,
                                                     float* __restrict__ wout)
{
    int t = blockIdx.x, tid = threadIdx.x;
    __shared__ float part[128][Ee];
    float acc[Ee];
#pragma unroll
    for (int e = 0; e < Ee; e++) acc[e] = 0.f;
    const float* xp = x + (long)t * Dm;
    for (int d = tid; d < Dm; d += 128) {
        float xv = xp[d];
        const float* wrow = Wr + (long)d * Ee;
#pragma unroll
        for (int e = 0; e < Ee; e++) acc[e] += xv * wrow[e];
    }
#pragma unroll
    for (int e = 0; e < Ee; e++) part[tid][e] = acc[e];
    __syncthreads();
    for (int st = 64; st > 0; st >>= 1) {
        if (tid < st)
#pragma unroll
            for (int e = 0; e < Ee; e++) part[tid][e] += part[tid + st][e];
        __syncthreads();
    }
    if (tid == 0) {
        float lg[Ee];
#pragma unroll
        for (int e = 0; e < Ee; e++) lg[e] = part[0][e] + br[e];
        float m1 = -3.4e38f, m2 = -3.4e38f;
#pragma unroll
        for (int e = 0; e < Ee; e++) {
            float v = lg[e];
            if (v > m1) { m2 = m1; m1 = v; }
            else if (v > m2) m2 = v;
        }
        float sum = 0.f, we[Ee];
#pragma unroll
        for (int e = 0; e < Ee; e++) {
            we[e] = (lg[e] < m2) ? 0.f : expf(lg[e] - m1);
            sum += we[e];
        }
        float inv = 1.f / sum;
#pragma unroll
        for (int e = 0; e < Ee; e++) wout[(long)t * Ee + e] = we[e] * inv;
    }
}

// ---------------- FiLM: ytf = gelu(t0+b0)*(t1+b1); write fp32 + hi/lo ----------------
__global__ __launch_bounds__(256) void film_kernel(float* __restrict__ t0,
                                                   const float* __restrict__ t1,
                                                   const float* __restrict__ b0,
                                                   const float* __restrict__ b1,
                                                   __half* __restrict__ hi,
                                                   __half* __restrict__ lo)
{
    long i = (long)blockIdx.x * 256 + threadIdx.x;
    int d = (int)(i & (Dm - 1));
    float y = gelu_f(t0[i] + b0[d]) * (t1[i] + b1[d]);
    t0[i] = y;
    __half h = __float2half_rn(y);
    hi[i] = h;
    lo[i] = __float2half_rn(y - __half2float(h));
}

// ---------------- expert mixing -> hi/lo only ----------------
__global__ __launch_bounds__(256) void mix_kernel(const float* __restrict__ ytf,
                                                  const float* __restrict__ pe,
                                                  const float* __restrict__ ae,
                                                  const float* __restrict__ Pb,
                                                  const float* __restrict__ Ab,
                                                  const float* __restrict__ w,
                                                  __half* __restrict__ hi,
                                                  __half* __restrict__ lo)
{
    int t = blockIdx.x;
    __shared__ float ws[Ee];
    if (threadIdx.x < Ee) ws[threadIdx.x] = w[(long)t * Ee + threadIdx.x];
    __syncthreads();
#pragma unroll
    for (int it = 0; it < 4; it++) {
        int d = threadIdx.x + it * 256;
        long td = (long)t * Dm + d;
        float yv = ytf[td];
        float out = ws[0] * gelu_f(yv);
#pragma unroll
        for (int e = 0; e < NEXP; e++) {
            float we = ws[e + 1];
            if (we != 0.f) {
                float p = pe[(long)e * Tt * Dm + td] + Pb[e * Dm + d];
                float a = ae[(long)e * Tt * Dm + td] + Ab[e * Dm + d];
                out += we * (p * yv + a);
            }
        }
        __half h = __float2half_rn(out);
        hi[td] = h;
        lo[td] = __float2half_rn(out - __half2float(h));
    }
}

// ---------------- host helpers ----------------
static float* symf(const void* s) { void* p = nullptr; cudaGetSymbolAddress(&p, s); return (float*)p; }
static __half* symh(const void* s) { void* p = nullptr; cudaGetSymbolAddress(&p, s); return (__half*)p; }

static void wsplit(const float* W, __half* hi, __half* lo, int K, int N,
                   long inStride, long outStride, int z)
{
    dim3 grid(N / 32, K / 32, z);
    wsplit_kernel<<<grid, 256>>>(W, hi, lo, K, N, inStride, outStride);
}

static void tgemm(const __half* ahi, const __half* alo,
                  const __half* bhi, const __half* blo,
                  const float* bias, const float* resid,
                  float* C, __half* Chi, __half* Clo,
                  int N, int K, int Z, long sB, long sC, int act)
{
    dim3 grid(N / BN, Tt / BM, Z);
    mma_gemm_kernel<<<grid, 256, SMEM_MM>>>(ahi, alo, bhi, blo, bias, resid,
                                            C, Chi, Clo, Tt, N, K, sB, sC, act,
                                            bias != nullptr, resid != nullptr,
                                            C != nullptr, Chi != nullptr, Clo != nullptr);
}

extern "C" void kernel_launch(void* const* d_in, const int* in_sizes, int n_in,
                              void* d_out, int out_size)
{
    const float* x_in  = (const float*)d_in[0];
    const float* ln1_g = (const float*)d_in[1];
    const float* ln1_b = (const float*)d_in[2];
    const float* Wqkv  = (const float*)d_in[3];
    const float* bqkv  = (const float*)d_in[4];
    const float* Wo    = (const float*)d_in[5];
    const float* bo    = (const float*)d_in[6];
    const float* Wr    = (const float*)d_in[7];
    const float* br    = (const float*)d_in[8];
    const float* Wa1   = (const float*)d_in[9];
    const float* ba1   = (const float*)d_in[10];
    const float* Wa2   = (const float*)d_in[11];
    const float* ba2   = (const float*)d_in[12];
    const float* ln2_g = (const float*)d_in[13];
    const float* ln2_b = (const float*)d_in[14];
    const float* Wb0   = (const float*)d_in[15];
    const float* bb0   = (const float*)d_in[16];
    const float* Wb1   = (const float*)d_in[17];
    const float* bb1   = (const float*)d_in[18];
    const float* We_p  = (const float*)d_in[19];
    const float* be_p  = (const float*)d_in[20];
    const float* We_a  = (const float*)d_in[21];
    const float* be_a  = (const float*)d_in[22];

    float* X   = symf(g_x);
    float* T01 = symf(g_t01);
    float* T0  = T01;
    float* T1  = T01 + (long)Tt * Dm;
    float* PA  = symf(g_pa);
    float* Wt  = symf(g_w);
    __half* WHI = symh(g_whi);
    __half* WLO = symh(g_wlo);
    __half* AHI = symh(g_ahi);
    __half* ALO = symh(g_alo);
    __half* MHI = symh(g_mhi);
    __half* MLO = symh(g_mlo);
    __half* QKVH = symh(g_qkvh);
    __half* VT  = symh(g_vt);
    __half* SH  = symh(g_sh);

    cudaFuncSetAttribute(mma_gemm_kernel,
                         cudaFuncAttributeMaxDynamicSharedMemorySize, SMEM_MM);
    cudaFuncSetAttribute(mma_h_kernel,
                         cudaFuncAttributeMaxDynamicSharedMemorySize, SMEM_H);

    // ---- weight transpose + split ----
    wsplit(Wqkv, WHI + OFF_QKV, WLO + OFF_QKV, 1024, 3072, 3072L * 1024, PER_L, Lnum);
    wsplit(Wo,   WHI + OFF_WO,  WLO + OFF_WO,  1024, 1024, SZ1M, PER_L, Lnum);
    wsplit(Wb0,  WHI + OFF_WB0, WLO + OFF_WB0, 1024, 1024, SZ1M, PER_L, Lnum);
    wsplit(Wb1,  WHI + OFF_WB1, WLO + OFF_WB1, 1024, 1024, SZ1M, PER_L, Lnum);
    for (int l = 0; l < Lnum; l++) {
        wsplit(We_p + (long)l * NEXP * SZ1M, WHI + l * PER_L + OFF_WEP,
               WLO + l * PER_L + OFF_WEP, 1024, 1024, SZ1M, SZ1M, NEXP);
        wsplit(We_a + (long)l * NEXP * SZ1M, WHI + l * PER_L + OFF_WEA,
               WLO + l * PER_L + OFF_WEA, 1024, 1024, SZ1M, SZ1M, NEXP);
    }
    wsplit(Wa1, WHI + OFF_WA1, WLO + OFF_WA1, 1024, 4096, 4096L * 1024, PER_L, Lnum);
    wsplit(Wa2, WHI + OFF_WA2, WLO + OFF_WA2, 4096, 1024, 4096L * 1024, PER_L, Lnum);

    cudaMemcpyAsync(X, x_in, (size_t)Tt * Dm * sizeof(float),
                    cudaMemcpyDeviceToDevice, 0);

    for (int l = 0; l < Lnum; l++) {
        const __half* whl = WHI + (long)l * PER_L;
        const __half* wll = WLO + (long)l * PER_L;

        // --- attention ---
        ln_split_kernel<<<Tt, 256>>>(X, ln1_g + l * Dm, ln1_b + l * Dm, AHI, ALO);
        // QKV -> fp16 direct
        tgemm(AHI, ALO, whl + OFF_QKV, wll + OFF_QKV,
              bqkv + (long)l * 3 * INNERd, nullptr,
              nullptr, QKVH, nullptr, 3 * INNERd, Dm, 1, 0, 0, 0);

        // V transpose
        {
            dim3 grid(Nn / 32, DHh / 32, Bb * Hh);
            vtrans_kernel<<<grid, 256>>>(QKVH, VT);
        }
        // S = (Q K^T) / 8  (fp16 out)
        {
            dim3 grid(Nn / HBN, Nn / HBM, Bb * Hh);
            mma_h_kernel<<<grid, 256, SMEM_H>>>(
                QKVH, QKVH + INNERd, SH, nullptr,
                DHh, 3 * INNERd, 3 * INNERd, Nn, Hh,
                (long)Nn * 3 * INNERd, DHh,
                (long)Nn * 3 * INNERd, DHh,
                (long)Hh * Nn * Nn, (long)Nn * Nn,
                0.125f, 0);
        }
        softmax_h_kernel<<<Bb * Hh * Nn, 256>>>(SH);
        // O = P @ V  -> hi/lo into AHI/ALO
        {
            dim3 grid(1, Nn / HBM, Bb * Hh);
            mma_h_kernel<<<grid, 256, SMEM_H>>>(
                SH, VT, AHI, ALO,
                Nn, Nn, Nn, INNERd, Hh,
                (long)Hh * Nn * Nn, (long)Nn * Nn,
                (long)Hh * DHh * Nn, (long)DHh * Nn,
                (long)Nn * INNERd, DHh,
                1.0f, 1);
        }
        // x = O @ Wo + bo + x
        tgemm(AHI, ALO, whl + OFF_WO, wll + OFF_WO,
              bo + (long)l * Dm, X, X, nullptr, nullptr, Dm, INNERd, 1, 0, 0, 0);

        // --- router ---
        router_kernel<<<Tt, 128>>>(X, Wr + (long)l * Dm * Ee, br + (long)l * Ee,
                                   Wt + (long)l * Tt * Ee);

        // --- FiLM trunk ---
        ln_split_kernel<<<Tt, 256>>>(X, ln2_g + l * Dm, ln2_b + l * Dm, AHI, ALO);
        tgemm(AHI, ALO, whl + OFF_WB0, wll + OFF_WB0,
              nullptr, nullptr, T01, nullptr, nullptr,
              Dm, Dm, 2, SZ1M, (long)Tt * Dm, 0);
        film_kernel<<<(Tt * Dm) / 256, 256>>>(T0, T1, bb0 + (long)l * Dm,
                                              bb1 + (long)l * Dm, AHI, ALO);

        // --- 14 expert GEMMs batched ---
        tgemm(AHI, ALO, whl + OFF_WEP, wll + OFF_WEP,
              nullptr, nullptr, PA, nullptr, nullptr,
              Dm, Dm, 2 * NEXP, SZ1M, (long)Tt * Dm, 0);

        // --- mix -> hi/lo ---
        mix_kernel<<<Tt, 256>>>(T0, PA, PA + (long)NEXP * Tt * Dm,
                                be_p + (long)l * NEXP * Dm,
                                be_a + (long)l * NEXP * Dm,
                                Wt + (long)l * Tt * Ee, AHI, ALO);

        // --- adaptor MLP + residual ---
        tgemm(AHI, ALO, whl + OFF_WA1, wll + OFF_WA1,
              ba1 + (long)l * MLPd, nullptr,
              nullptr, MHI, MLO, MLPd, Dm, 1, 0, 0, 1 /*gelu*/);
        tgemm(MHI, MLO, whl + OFF_WA2, wll + OFF_WA2,
              ba2 + (long)l * Dm, X, X, nullptr, nullptr, Dm, MLPd, 1, 0, 0, 0);
    }

    // outputs: x [B,N,D] then stacked router weights [L,B,N,E]
    cudaMemcpyAsync(d_out, X, (size_t)Tt * Dm * sizeof(float),
                    cudaMemcpyDeviceToDevice, 0);
    if (out_size >= Tt * Dm + Lnum * Tt * Ee) {
        cudaMemcpyAsync((float*)d_out + (size_t)Tt * Dm, Wt,
                        (size_t)Lnum * Tt * Ee * sizeof(float),
                        cudaMemcpyDeviceToDevice, 0);
    }
}

// round 7
// speedup vs baseline: 3.2117x; 1.3786x over previous
#include <cuda_runtime.h>
#include <cuda_fp16.h>
#include <cstdint>
#include <math.h>

// ---------------- problem constants ----------------
#define Dm     1024
#define Lnum   2
#define Hh     16
#define DHh    64
#define INNERd 1024
#define MLPd   4096
#define Ee     8
#define Bb     4
#define Nn     1024
#define Tt     (Bb*Nn)
#define NEXP   (Ee-1)

// weight pack offsets (elements, per layer)
#define SZ1M   (1024L*1024L)
#define OFF_QKV 0L
#define OFF_WO  (OFF_QKV + 3072L*1024L)
#define OFF_WB0 (OFF_WO  + SZ1M)
#define OFF_WB1 (OFF_WB0 + SZ1M)
#define OFF_WEP (OFF_WB1 + SZ1M)
#define OFF_WEA (OFF_WEP + 7L*SZ1M)
#define OFF_WA1 (OFF_WEA + 7L*SZ1M)
#define OFF_WA2 (OFF_WA1 + 4096L*1024L)
#define PER_L   (OFF_WA2 + 4096L*1024L)

// ---------------- scratch (device globals) ----------------
__device__ float g_x[Tt*Dm];
__device__ float g_t01[2L*Tt*Dm];                 // T0/T1 (FiLM), T0 also ytf
__device__ float g_pa[(size_t)2*NEXP*Tt*Dm];      // PE then AE (dense layout)
__device__ float g_w[Lnum*Tt*Ee];
__device__ __half g_whi[2L*PER_L];
__device__ __half g_wlo[2L*PER_L];
__device__ __half g_ahi[(size_t)Tt*Dm];
__device__ __half g_alo[(size_t)Tt*Dm];
__device__ __half g_mhi[(size_t)Tt*MLPd];
__device__ __half g_mlo[(size_t)Tt*MLPd];
__device__ __half g_qkvh[(size_t)Tt*3*INNERd];
__device__ __half g_vt[(size_t)Bb*Hh*DHh*Nn];
__device__ __half g_sh[(size_t)Bb*Hh*Nn*Nn];
__device__ int g_cnt[NEXP];                       // per-expert token counts
__device__ int g_eidx[(size_t)NEXP*Tt];           // gathered token indices

__device__ __forceinline__ float gelu_f(float v) {
    return 0.5f * v * (1.0f + erff(v * 0.7071067811865475f));
}

__device__ __forceinline__ uint32_t smem_u32(const void* p) {
    uint32_t a;
    asm("{ .reg .u64 t; cvta.to.shared.u64 t, %1; cvt.u32.u64 %0, t; }"
        : "=r"(a) : "l"(p));
    return a;
}
__device__ __forceinline__ void ldmx4(uint32_t* r, uint32_t addr) {
    asm volatile("ldmatrix.sync.aligned.m8n8.x4.shared.b16 {%0,%1,%2,%3}, [%4];"
        : "=r"(r[0]), "=r"(r[1]), "=r"(r[2]), "=r"(r[3]) : "r"(addr));
}
__device__ __forceinline__ void ldmx2(uint32_t* r, uint32_t addr) {
    asm volatile("ldmatrix.sync.aligned.m8n8.x2.shared.b16 {%0,%1}, [%2];"
        : "=r"(r[0]), "=r"(r[1]) : "r"(addr));
}
__device__ __forceinline__ void mma16816(float* d, const uint32_t* a, const uint32_t* b) {
    asm volatile("mma.sync.aligned.m16n8k16.row.col.f32.f16.f16.f32 "
        "{%0,%1,%2,%3}, {%4,%5,%6,%7}, {%8,%9}, {%0,%1,%2,%3};"
        : "+f"(d[0]), "+f"(d[1]), "+f"(d[2]), "+f"(d[3])
        : "r"(a[0]), "r"(a[1]), "r"(a[2]), "r"(a[3]), "r"(b[0]), "r"(b[1]));
}

// ================= split HMMA GEMM: C = (Ahi+Alo)[M,K] @ (Bhi+Blo)[N,K]^T =================
#define BM 128
#define BN 128
#define BK 32
#define LDT 40
#define TILE_B (128*LDT*2)
#define ST_AHI 0
#define ST_ALO (1*TILE_B)
#define ST_BHI (2*TILE_B)
#define ST_BLO (3*TILE_B)
#define STAGE_B (4*TILE_B)
#define SMEM_MM (2*STAGE_B)

__global__ __launch_bounds__(256, 1) void mma_gemm_kernel(
    const __half* __restrict__ Ahi, const __half* __restrict__ Alo,
    const __half* __restrict__ Bhi, const __half* __restrict__ Blo,
    const float* __restrict__ bias, const float* __restrict__ resid,
    float* __restrict__ C, __half* __restrict__ Chi, __half* __restrict__ Clo,
    int M, int N, int K, long sB, long sC, int act,
    int hasBias, int hasRes, int wantF32, int wantHi, int wantLo)
{
    extern __shared__ char smem[];
    uint32_t sb = smem_u32(smem);
    const int tid = threadIdx.x;
    const int wid = tid >> 5;
    const int lane = tid & 31;
    const long z = blockIdx.z;
    Bhi += z * sB;
    Blo += z * sB;
    if (wantF32) C += z * sC;
    if (wantHi) Chi += z * sC;
    if (wantLo) Clo += z * sC;
    const float* res = hasRes ? (resid + z * sC) : nullptr;
    const int row0 = blockIdx.y * BM;
    const int col0 = blockIdx.x * BN;
    const int wm = wid & 1;
    const int wn = wid >> 1;

    float acc[4][4][4];
#pragma unroll
    for (int a = 0; a < 4; a++)
#pragma unroll
        for (int b = 0; b < 4; b++)
#pragma unroll
            for (int c = 0; c < 4; c++) acc[a][b][c] = 0.f;

    const int nc = K / BK;

    auto load_stage = [&](int s, int kt) {
        uint32_t base = sb + s * STAGE_B;
#pragma unroll
        for (int i = 0; i < 8; i++) {
            int idx = i * 256 + tid;
            int mat = idx >> 9;
            int rem = idx & 511;
            int r = rem >> 2, c = rem & 3;
            uint32_t sa = base + mat * TILE_B + (uint32_t)(r * LDT + c * 8) * 2;
            const __half* gp;
            if (mat == 0)      gp = Ahi + (long)(row0 + r) * K + kt + c * 8;
            else if (mat == 1) gp = Alo + (long)(row0 + r) * K + kt + c * 8;
            else if (mat == 2) gp = Bhi + (long)(col0 + r) * K + kt + c * 8;
            else               gp = Blo + (long)(col0 + r) * K + kt + c * 8;
            asm volatile("cp.async.cg.shared.global [%0], [%1], 16;"
                         :: "r"(sa), "l"(gp));
        }
        asm volatile("cp.async.commit_group;");
    };

    load_stage(0, 0);

    for (int c = 0; c < nc; c++) {
        int s = c & 1;
        if (c + 1 < nc) {
            load_stage(s ^ 1, (c + 1) * BK);
            asm volatile("cp.async.wait_group 1;");
        } else {
            asm volatile("cp.async.wait_group 0;");
        }
        __syncthreads();

        uint32_t base = sb + s * STAGE_B;
#pragma unroll
        for (int ph = 0; ph < 2; ph++) {
            uint32_t ahi[4][4], alo[4][4], bhi[4][2], blo[4][2];
#pragma unroll
            for (int mt = 0; mt < 4; mt++) {
                int rr = wm * 64 + mt * 16 + (lane & 15);
                uint32_t co = (uint32_t)(rr * LDT + ph * 16 + (lane >> 4) * 8) * 2;
                ldmx4(ahi[mt], base + ST_AHI + co);
                ldmx4(alo[mt], base + ST_ALO + co);
            }
#pragma unroll
            for (int nt = 0; nt < 4; nt++) {
                int rr = wn * 32 + nt * 8 + (lane & 7);
                uint32_t co = (uint32_t)(rr * LDT + ph * 16 + ((lane >> 3) & 1) * 8) * 2;
                ldmx2(bhi[nt], base + ST_BHI + co);
                ldmx2(blo[nt], base + ST_BLO + co);
            }
#pragma unroll
            for (int mt = 0; mt < 4; mt++)
#pragma unroll
                for (int nt = 0; nt < 4; nt++) {
                    mma16816(acc[mt][nt], ahi[mt], bhi[nt]);
                    mma16816(acc[mt][nt], ahi[mt], blo[nt]);
                    mma16816(acc[mt][nt], alo[mt], bhi[nt]);
                }
        }
        __syncthreads();
    }

#pragma unroll
    for (int mt = 0; mt < 4; mt++) {
#pragma unroll
        for (int nt = 0; nt < 4; nt++) {
            int rb = row0 + wm * 64 + mt * 16 + (lane >> 2);
            int cc = col0 + wn * 32 + nt * 8 + (lane & 3) * 2;
            float b0 = 0.f, b1 = 0.f;
            if (hasBias) { b0 = bias[cc]; b1 = bias[cc + 1]; }
#pragma unroll
            for (int hf = 0; hf < 2; hf++) {
                int rr = rb + hf * 8;
                float v0 = acc[mt][nt][hf * 2] + b0;
                float v1 = acc[mt][nt][hf * 2 + 1] + b1;
                if (act == 1) { v0 = gelu_f(v0); v1 = gelu_f(v1); }
                if (hasRes) {
                    v0 += res[(long)rr * N + cc];
                    v1 += res[(long)rr * N + cc + 1];
                }
                long o = (long)rr * N + cc;
                if (wantF32) *(float2*)&C[o] = make_float2(v0, v1);
                if (wantHi) {
                    __half h0 = __float2half_rn(v0), h1 = __float2half_rn(v1);
                    *(__half2*)&Chi[o] = __halves2half2(h0, h1);
                    if (wantLo) {
                        __half l0 = __float2half_rn(v0 - __half2float(h0));
                        __half l1 = __float2half_rn(v1 - __half2float(h1));
                        *(__half2*)&Clo[o] = __halves2half2(l0, l1);
                    }
                }
            }
        }
    }
}

// ================= token-gathered sparse expert GEMM =================
// z in [0,14): weights (WEP base + z*1M), expert e = z % 7; only first cnt[e]
// gathered tokens computed. Output scattered to dense PA[z][token][col].
__global__ __launch_bounds__(256, 1) void mma_gather_kernel(
    const __half* __restrict__ Ahi, const __half* __restrict__ Alo,
    const __half* __restrict__ Whi, const __half* __restrict__ Wlo,
    float* __restrict__ PA,
    const int* __restrict__ cnt, const int* __restrict__ eidx)
{
    const int z = blockIdx.z;
    const int e = z % NEXP;
    const int n = cnt[e];
    const int row0 = blockIdx.y * BM;
    if (row0 >= n) return;

    extern __shared__ char smem[];
    uint32_t sb = smem_u32(smem);
    __shared__ int sidx[BM];
    const int tid = threadIdx.x;
    const int wid = tid >> 5;
    const int lane = tid & 31;
    const __half* Bhi = Whi + (long)z * SZ1M;
    const __half* Blo = Wlo + (long)z * SZ1M;
    float* C = PA + (long)z * Tt * Dm;
    const int col0 = blockIdx.x * BN;
    const int wm = wid & 1;
    const int wn = wid >> 1;
    const int K = Dm;

    if (tid < BM) {
        int rr = row0 + tid;
        sidx[tid] = eidx[(long)e * Tt + (rr < n ? rr : n - 1)];
    }
    __syncthreads();

    float acc[4][4][4];
#pragma unroll
    for (int a = 0; a < 4; a++)
#pragma unroll
        for (int b = 0; b < 4; b++)
#pragma unroll
            for (int c = 0; c < 4; c++) acc[a][b][c] = 0.f;

    const int nc = K / BK;

    auto load_stage = [&](int s, int kt) {
        uint32_t base = sb + s * STAGE_B;
#pragma unroll
        for (int i = 0; i < 8; i++) {
            int idx = i * 256 + tid;
            int mat = idx >> 9;
            int rem = idx & 511;
            int r = rem >> 2, c = rem & 3;
            uint32_t sa = base + mat * TILE_B + (uint32_t)(r * LDT + c * 8) * 2;
            const __half* gp;
            if (mat == 0)      gp = Ahi + (long)sidx[r] * K + kt + c * 8;
            else if (mat == 1) gp = Alo + (long)sidx[r] * K + kt + c * 8;
            else if (mat == 2) gp = Bhi + (long)(col0 + r) * K + kt + c * 8;
            else               gp = Blo + (long)(col0 + r) * K + kt + c * 8;
            asm volatile("cp.async.cg.shared.global [%0], [%1], 16;"
                         :: "r"(sa), "l"(gp));
        }
        asm volatile("cp.async.commit_group;");
    };

    load_stage(0, 0);

    for (int c = 0; c < nc; c++) {
        int s = c & 1;
        if (c + 1 < nc) {
            load_stage(s ^ 1, (c + 1) * BK);
            asm volatile("cp.async.wait_group 1;");
        } else {
            asm volatile("cp.async.wait_group 0;");
        }
        __syncthreads();

        uint32_t base = sb + s * STAGE_B;
#pragma unroll
        for (int ph = 0; ph < 2; ph++) {
            uint32_t ahi[4][4], alo[4][4], bhi[4][2], blo[4][2];
#pragma unroll
            for (int mt = 0; mt < 4; mt++) {
                int rr = wm * 64 + mt * 16 + (lane & 15);
                uint32_t co = (uint32_t)(rr * LDT + ph * 16 + (lane >> 4) * 8) * 2;
                ldmx4(ahi[mt], base + ST_AHI + co);
                ldmx4(alo[mt], base + ST_ALO + co);
            }
#pragma unroll
            for (int nt = 0; nt < 4; nt++) {
                int rr = wn * 32 + nt * 8 + (lane & 7);
                uint32_t co = (uint32_t)(rr * LDT + ph * 16 + ((lane >> 3) & 1) * 8) * 2;
                ldmx2(bhi[nt], base + ST_BHI + co);
                ldmx2(blo[nt], base + ST_BLO + co);
            }
#pragma unroll
            for (int mt = 0; mt < 4; mt++)
#pragma unroll
                for (int nt = 0; nt < 4; nt++) {
                    mma16816(acc[mt][nt], ahi[mt], bhi[nt]);
                    mma16816(acc[mt][nt], ahi[mt], blo[nt]);
                    mma16816(acc[mt][nt], alo[mt], bhi[nt]);
                }
        }
        __syncthreads();
    }

#pragma unroll
    for (int mt = 0; mt < 4; mt++) {
#pragma unroll
        for (int nt = 0; nt < 4; nt++) {
            int lr = wm * 64 + mt * 16 + (lane >> 2);
            int cc = col0 + wn * 32 + nt * 8 + (lane & 3) * 2;
#pragma unroll
            for (int hf = 0; hf < 2; hf++) {
                int lrr = lr + hf * 8;
                if (row0 + lrr < n) {
                    long o = (long)sidx[lrr] * Dm + cc;
                    *(float2*)&C[o] = make_float2(acc[mt][nt][hf * 2],
                                                  acc[mt][nt][hf * 2 + 1]);
                }
            }
        }
    }
}

// ================= single-term fp16 HMMA (attention QK^T and P*V) =================
#define HBM 128
#define HBN 64
#define HBK 64
#define LDTH 72
#define H_ATILE (128*LDTH*2)
#define H_BTILE (64*LDTH*2)
#define H_STAGE (H_ATILE + H_BTILE)
#define SMEM_H  (2*H_STAGE)

__global__ __launch_bounds__(256, 1) void mma_h_kernel(
    const __half* __restrict__ A, const __half* __restrict__ B,
    __half* __restrict__ Chi, __half* __restrict__ Clo,
    int K, int lda, int ldb, int ldc, int Hd,
    long sAb, long sAh, long sBb, long sBh, long sCb, long sCh,
    float scale, int wantLo)
{
    extern __shared__ char smem[];
    uint32_t sb = smem_u32(smem);
    const int tid = threadIdx.x;
    const int wid = tid >> 5;
    const int lane = tid & 31;
    const int z = blockIdx.z;
    const int zb = z / Hd, zh = z % Hd;
    A += (long)zb * sAb + (long)zh * sAh;
    B += (long)zb * sBb + (long)zh * sBh;
    Chi += (long)zb * sCb + (long)zh * sCh;
    if (wantLo) Clo += (long)zb * sCb + (long)zh * sCh;
    const int row0 = blockIdx.y * HBM;
    const int col0 = blockIdx.x * HBN;
    const int wm = wid & 1;
    const int wn = wid >> 1;

    float acc[4][2][4];
#pragma unroll
    for (int a = 0; a < 4; a++)
#pragma unroll
        for (int b = 0; b < 2; b++)
#pragma unroll
            for (int c = 0; c < 4; c++) acc[a][b][c] = 0.f;

    const int nc = K / HBK;

    auto load_stage = [&](int s, int kt) {
        uint32_t base = sb + s * H_STAGE;
#pragma unroll
        for (int i = 0; i < 6; i++) {
            int idx = i * 256 + tid;
            if (idx < 1024) {
                int r = idx >> 3, c = idx & 7;
                uint32_t sa = base + (uint32_t)(r * LDTH + c * 8) * 2;
                const __half* gp = A + (long)(row0 + r) * lda + kt + c * 8;
                asm volatile("cp.async.cg.shared.global [%0], [%1], 16;"
                             :: "r"(sa), "l"(gp));
            } else {
                int j = idx - 1024;
                int r = j >> 3, c = j & 7;
                uint32_t sa = base + H_ATILE + (uint32_t)(r * LDTH + c * 8) * 2;
                const __half* gp = B + (long)(col0 + r) * ldb + kt + c * 8;
                asm volatile("cp.async.cg.shared.global [%0], [%1], 16;"
                             :: "r"(sa), "l"(gp));
            }
        }
        asm volatile("cp.async.commit_group;");
    };

    load_stage(0, 0);

    for (int c = 0; c < nc; c++) {
        int s = c & 1;
        if (c + 1 < nc) {
            load_stage(s ^ 1, (c + 1) * HBK);
            asm volatile("cp.async.wait_group 1;");
        } else {
            asm volatile("cp.async.wait_group 0;");
        }
        __syncthreads();

        uint32_t base = sb + s * H_STAGE;
#pragma unroll
        for (int ph = 0; ph < 4; ph++) {
            uint32_t af[4][4], bf[2][2];
#pragma unroll
            for (int mt = 0; mt < 4; mt++) {
                int rr = wm * 64 + mt * 16 + (lane & 15);
                uint32_t co = (uint32_t)(rr * LDTH + ph * 16 + (lane >> 4) * 8) * 2;
                ldmx4(af[mt], base + co);
            }
#pragma unroll
            for (int nt = 0; nt < 2; nt++) {
                int rr = wn * 16 + nt * 8 + (lane & 7);
                uint32_t co = (uint32_t)(rr * LDTH + ph * 16 + ((lane >> 3) & 1) * 8) * 2;
                ldmx2(bf[nt], base + H_ATILE + co);
            }
#pragma unroll
            for (int mt = 0; mt < 4; mt++)
#pragma unroll
                for (int nt = 0; nt < 2; nt++)
                    mma16816(acc[mt][nt], af[mt], bf[nt]);
        }
        __syncthreads();
    }

#pragma unroll
    for (int mt = 0; mt < 4; mt++) {
#pragma unroll
        for (int nt = 0; nt < 2; nt++) {
            int rb = row0 + wm * 64 + mt * 16 + (lane >> 2);
            int cc = col0 + wn * 16 + nt * 8 + (lane & 3) * 2;
#pragma unroll
            for (int hf = 0; hf < 2; hf++) {
                int rr = rb + hf * 8;
                float v0 = acc[mt][nt][hf * 2] * scale;
                float v1 = acc[mt][nt][hf * 2 + 1] * scale;
                __half h0 = __float2half_rn(v0), h1 = __float2half_rn(v1);
                long o = (long)rr * ldc + cc;
                *(__half2*)&Chi[o] = __halves2half2(h0, h1);
                if (wantLo) {
                    __half l0 = __float2half_rn(v0 - __half2float(h0));
                    __half l1 = __float2half_rn(v1 - __half2float(h1));
                    *(__half2*)&Clo[o] = __halves2half2(l0, l1);
                }
            }
        }
    }
}

// ---------------- V transpose ----------------
__global__ __launch_bounds__(256) void vtrans_kernel(const __half* __restrict__ qkvh,
                                                     __half* __restrict__ vt)
{
    __shared__ __half t[32][33];
    int z = blockIdx.z, b = z >> 4, h = z & 15;
    int k0 = blockIdx.x * 32, d0 = blockIdx.y * 32;
    int tx = threadIdx.x & 31, ty = threadIdx.x >> 5;
#pragma unroll
    for (int i = 0; i < 4; i++) {
        int k = k0 + ty + i * 8;
        t[ty + i * 8][tx] = qkvh[(long)(b * Nn + k) * 3072 + 2048 + h * 64 + d0 + tx];
    }
    __syncthreads();
#pragma unroll
    for (int i = 0; i < 4; i++) {
        int d = d0 + ty + i * 8;
        vt[((long)z * 64 + d) * Nn + k0 + tx] = t[tx][ty + i * 8];
    }
}

// ---------------- fp16 softmax ----------------
__global__ __launch_bounds__(256) void softmax_h_kernel(__half* __restrict__ s)
{
    __half2* p = (__half2*)(s + (size_t)blockIdx.x * Nn);
    int tid = threadIdx.x;
    __shared__ float red[256];

    __half2 a = p[tid * 2], b = p[tid * 2 + 1];
    float v[4] = {__low2float(a), __high2float(a), __low2float(b), __high2float(b)};
    float m = fmaxf(fmaxf(v[0], v[1]), fmaxf(v[2], v[3]));
    red[tid] = m; __syncthreads();
    for (int st = 128; st > 0; st >>= 1) {
        if (tid < st) red[tid] = fmaxf(red[tid], red[tid + st]);
        __syncthreads();
    }
    m = red[0]; __syncthreads();

    float sum = 0.f;
#pragma unroll
    for (int i = 0; i < 4; i++) { v[i] = expf(v[i] - m); sum += v[i]; }
    red[tid] = sum; __syncthreads();
    for (int st = 128; st > 0; st >>= 1) {
        if (tid < st) red[tid] += red[tid + st];
        __syncthreads();
    }
    float inv = 1.f / red[0];
    p[tid * 2]     = __halves2half2(__float2half_rn(v[0] * inv), __float2half_rn(v[1] * inv));
    p[tid * 2 + 1] = __halves2half2(__float2half_rn(v[2] * inv), __float2half_rn(v[3] * inv));
}

// ---------------- weight transpose + fp16 split ----------------
__global__ __launch_bounds__(256) void wsplit_kernel(
    const float* __restrict__ W, __half* __restrict__ hi, __half* __restrict__ lo,
    int K, int N, long inStride, long outStride)
{
    __shared__ float tile[32][33];
    const float* Wz = W + blockIdx.z * inStride;
    long ob = blockIdx.z * outStride;
    int k0 = blockIdx.y * 32, n0 = blockIdx.x * 32;
    int tx = threadIdx.x & 31, ty = threadIdx.x >> 5;
#pragma unroll
    for (int i = 0; i < 4; i++)
        tile[ty + i * 8][tx] = Wz[(long)(k0 + ty + i * 8) * N + n0 + tx];
    __syncthreads();
#pragma unroll
    for (int i = 0; i < 4; i++) {
        float v = tile[tx][ty + i * 8];
        __half h = __float2half_rn(v);
        __half l = __float2half_rn(v - __half2float(h));
        long o = ob + (long)(n0 + ty + i * 8) * K + k0 + tx;
        hi[o] = h; lo[o] = l;
    }
}

// ---------------- LayerNorm -> fp16 hi/lo ----------------
__global__ __launch_bounds__(256) void ln_split_kernel(
    const float* __restrict__ x, const float* __restrict__ g,
    const float* __restrict__ bta,
    __half* __restrict__ hi, __half* __restrict__ lo)
{
    int t = blockIdx.x, tid = threadIdx.x;
    const float* xp = x + (long)t * Dm;
    __shared__ float r1[256], r2[256];

    float v[4], s = 0.f, s2 = 0.f;
#pragma unroll
    for (int i = 0; i < 4; i++) { v[i] = xp[tid + i * 256]; s += v[i]; s2 += v[i] * v[i]; }
    r1[tid] = s; r2[tid] = s2; __syncthreads();
    for (int st = 128; st > 0; st >>= 1) {
        if (tid < st) { r1[tid] += r1[tid + st]; r2[tid] += r2[tid + st]; }
        __syncthreads();
    }
    float mean = r1[0] * (1.f / Dm);
    float var = r2[0] * (1.f / Dm) - mean * mean;
    float rstd = rsqrtf(var + 1e-5f);
#pragma unroll
    for (int i = 0; i < 4; i++) {
        int d = tid + i * 256;
        float y = (v[i] - mean) * rstd * g[d] + bta[d];
        __half h = __float2half_rn(y);
        hi[(long)t * Dm + d] = h;
        lo[(long)t * Dm + d] = __float2half_rn(y - __half2float(h));
    }
}

// ---------------- reset expert counters ----------------
__global__ void reset_cnt_kernel(int* cnt)
{
    if (threadIdx.x < NEXP) cnt[threadIdx.x] = 0;
}

// ---------------- router (+ expert token gather) ----------------
__global__ __launch_bounds__(128) void router_kernel(const float* __restrict__ x,
                                                     const float* __restrict__ Wr,
                                                     const float* __restrict__ br,
                                                     float* __restrict__ wout,
                                                     int* __restrict__ cnt,
                                                     int* __restrict__ eidx)
{
    int t = blockIdx.x, tid = threadIdx.x;
    __shared__ float part[128][Ee];
    float acc[Ee];
#pragma unroll
    for (int e = 0; e < Ee; e++) acc[e] = 0.f;
    const float* xp = x + (long)t * Dm;
    for (int d = tid; d < Dm; d += 128) {
        float xv = xp[d];
        const float* wrow = Wr + (long)d * Ee;
#pragma unroll
        for (int e = 0; e < Ee; e++) acc[e] += xv * wrow[e];
    }
#pragma unroll
    for (int e = 0; e < Ee; e++) part[tid][e] = acc[e];
    __syncthreads();
    for (int st = 64; st > 0; st >>= 1) {
        if (tid < st)
#pragma unroll
            for (int e = 0; e < Ee; e++) part[tid][e] += part[tid + st][e];
        __syncthreads();
    }
    if (tid == 0) {
        float lg[Ee];
#pragma unroll
        for (int e = 0; e < Ee; e++) lg[e] = part[0][e] + br[e];
        float m1 = -3.4e38f, m2 = -3.4e38f;
#pragma unroll
        for (int e = 0; e < Ee; e++) {
            float v = lg[e];
            if (v > m1) { m2 = m1; m1 = v; }
            else if (v > m2) m2 = v;
        }
        float sum = 0.f, we[Ee];
#pragma unroll
        for (int e = 0; e < Ee; e++) {
            we[e] = (lg[e] < m2) ? 0.f : expf(lg[e] - m1);
            sum += we[e];
        }
        float inv = 1.f / sum;
#pragma unroll
        for (int e = 0; e < Ee; e++) wout[(long)t * Ee + e] = we[e] * inv;
        // gather token into active FiLM expert lists
#pragma unroll
        for (int e = 0; e < NEXP; e++) {
            if (we[e + 1] != 0.f) {
                int p = atomicAdd(&cnt[e], 1);
                eidx[(long)e * Tt + p] = t;
            }
        }
    }
}

// ---------------- FiLM: ytf = gelu(t0+b0)*(t1+b1); write fp32 + hi/lo ----------------
__global__ __launch_bounds__(256) void film_kernel(float* __restrict__ t0,
                                                   const float* __restrict__ t1,
                                                   const float* __restrict__ b0,
                                                   const float* __restrict__ b1,
                                                   __half* __restrict__ hi,
                                                   __half* __restrict__ lo)
{
    long i = (long)blockIdx.x * 256 + threadIdx.x;
    int d = (int)(i & (Dm - 1));
    float y = gelu_f(t0[i] + b0[d]) * (t1[i] + b1[d]);
    t0[i] = y;
    __half h = __float2half_rn(y);
    hi[i] = h;
    lo[i] = __float2half_rn(y - __half2float(h));
}

// ---------------- expert mixing -> hi/lo ----------------
__global__ __launch_bounds__(256) void mix_kernel(const float* __restrict__ ytf,
                                                  const float* __restrict__ pe,
                                                  const float* __restrict__ ae,
                                                  const float* __restrict__ Pb,
                                                  const float* __restrict__ Ab,
                                                  const float* __restrict__ w,
                                                  __half* __restrict__ hi,
                                                  __half* __restrict__ lo)
{
    int t = blockIdx.x;
    __shared__ float ws[Ee];
    if (threadIdx.x < Ee) ws[threadIdx.x] = w[(long)t * Ee + threadIdx.x];
    __syncthreads();
#pragma unroll
    for (int it = 0; it < 4; it++) {
        int d = threadIdx.x + it * 256;
        long td = (long)t * Dm + d;
        float yv = ytf[td];
        float out = ws[0] * gelu_f(yv);
#pragma unroll
        for (int e = 0; e < NEXP; e++) {
            float we = ws[e + 1];
            if (we != 0.f) {
                float p = pe[(long)e * Tt * Dm + td] + Pb[e * Dm + d];
                float a = ae[(long)e * Tt * Dm + td] + Ab[e * Dm + d];
                out += we * (p * yv + a);
            }
        }
        __half h = __float2half_rn(out);
        hi[td] = h;
        lo[td] = __float2half_rn(out - __half2float(h));
    }
}

// ---------------- host helpers ----------------
static float* symf(const void* s) { void* p = nullptr; cudaGetSymbolAddress(&p, s); return (float*)p; }
static __half* symh(const void* s) { void* p = nullptr; cudaGetSymbolAddress(&p, s); return (__half*)p; }
static int* symi(const void* s) { void* p = nullptr; cudaGetSymbolAddress(&p, s); return (int*)p; }

static void wsplit(const float* W, __half* hi, __half* lo, int K, int N,
                   long inStride, long outStride, int z)
{
    dim3 grid(N / 32, K / 32, z);
    wsplit_kernel<<<grid, 256>>>(W, hi, lo, K, N, inStride, outStride);
}

static void tgemm(const __half* ahi, const __half* alo,
                  const __half* bhi, const __half* blo,
                  const float* bias, const float* resid,
                  float* C, __half* Chi, __half* Clo,
                  int N, int K, int Z, long sB, long sC, int act)
{
    dim3 grid(N / BN, Tt / BM, Z);
    mma_gemm_kernel<<<grid, 256, SMEM_MM>>>(ahi, alo, bhi, blo, bias, resid,
                                            C, Chi, Clo, Tt, N, K, sB, sC, act,
                                            bias != nullptr, resid != nullptr,
                                            C != nullptr, Chi != nullptr, Clo != nullptr);
}

extern "C" void kernel_launch(void* const* d_in, const int* in_sizes, int n_in,
                              void* d_out, int out_size)
{
    const float* x_in  = (const float*)d_in[0];
    const float* ln1_g = (const float*)d_in[1];
    const float* ln1_b = (const float*)d_in[2];
    const float* Wqkv  = (const float*)d_in[3];
    const float* bqkv  = (const float*)d_in[4];
    const float* Wo    = (const float*)d_in[5];
    const float* bo    = (const float*)d_in[6];
    const float* Wr    = (const float*)d_in[7];
    const float* br    = (const float*)d_in[8];
    const float* Wa1   = (const float*)d_in[9];
    const float* ba1   = (const float*)d_in[10];
    const float* Wa2   = (const float*)d_in[11];
    const float* ba2   = (const float*)d_in[12];
    const float* ln2_g = (const float*)d_in[13];
    const float* ln2_b = (const float*)d_in[14];
    const float* Wb0   = (const float*)d_in[15];
    const float* bb0   = (const float*)d_in[16];
    const float* Wb1   = (const float*)d_in[17];
    const float* bb1   = (const float*)d_in[18];
    const float* We_p  = (const float*)d_in[19];
    const float* be_p  = (const float*)d_in[20];
    const float* We_a  = (const float*)d_in[21];
    const float* be_a  = (const float*)d_in[22];

    float* X   = symf(g_x);
    float* T01 = symf(g_t01);
    float* T0  = T01;
    float* T1  = T01 + (long)Tt * Dm;
    float* PA  = symf(g_pa);
    float* Wt  = symf(g_w);
    __half* WHI = symh(g_whi);
    __half* WLO = symh(g_wlo);
    __half* AHI = symh(g_ahi);
    __half* ALO = symh(g_alo);
    __half* MHI = symh(g_mhi);
    __half* MLO = symh(g_mlo);
    __half* QKVH = symh(g_qkvh);
    __half* VT  = symh(g_vt);
    __half* SH  = symh(g_sh);
    int* CNT = symi(g_cnt);
    int* EIDX = symi(g_eidx);

    cudaFuncSetAttribute(mma_gemm_kernel,
                         cudaFuncAttributeMaxDynamicSharedMemorySize, SMEM_MM);
    cudaFuncSetAttribute(mma_gather_kernel,
                         cudaFuncAttributeMaxDynamicSharedMemorySize, SMEM_MM);
    cudaFuncSetAttribute(mma_h_kernel,
                         cudaFuncAttributeMaxDynamicSharedMemorySize, SMEM_H);

    // ---- weight transpose + split ----
    wsplit(Wqkv, WHI + OFF_QKV, WLO + OFF_QKV, 1024, 3072, 3072L * 1024, PER_L, Lnum);
    wsplit(Wo,   WHI + OFF_WO,  WLO + OFF_WO,  1024, 1024, SZ1M, PER_L, Lnum);
    wsplit(Wb0,  WHI + OFF_WB0, WLO + OFF_WB0, 1024, 1024, SZ1M, PER_L, Lnum);
    wsplit(Wb1,  WHI + OFF_WB1, WLO + OFF_WB1, 1024, 1024, SZ1M, PER_L, Lnum);
    for (int l = 0; l < Lnum; l++) {
        wsplit(We_p + (long)l * NEXP * SZ1M, WHI + l * PER_L + OFF_WEP,
               WLO + l * PER_L + OFF_WEP, 1024, 1024, SZ1M, SZ1M, NEXP);
        wsplit(We_a + (long)l * NEXP * SZ1M, WHI + l * PER_L + OFF_WEA,
               WLO + l * PER_L + OFF_WEA, 1024, 1024, SZ1M, SZ1M, NEXP);
    }
    wsplit(Wa1, WHI + OFF_WA1, WLO + OFF_WA1, 1024, 4096, 4096L * 1024, PER_L, Lnum);
    wsplit(Wa2, WHI + OFF_WA2, WLO + OFF_WA2, 4096, 1024, 4096L * 1024, PER_L, Lnum);

    cudaMemcpyAsync(X, x_in, (size_t)Tt * Dm * sizeof(float),
                    cudaMemcpyDeviceToDevice, 0);

    for (int l = 0; l < Lnum; l++) {
        const __half* whl = WHI + (long)l * PER_L;
        const __half* wll = WLO + (long)l * PER_L;

        // --- attention ---
        ln_split_kernel<<<Tt, 256>>>(X, ln1_g + l * Dm, ln1_b + l * Dm, AHI, ALO);
        tgemm(AHI, ALO, whl + OFF_QKV, wll + OFF_QKV,
              bqkv + (long)l * 3 * INNERd, nullptr,
              nullptr, QKVH, nullptr, 3 * INNERd, Dm, 1, 0, 0, 0);

        {
            dim3 grid(Nn / 32, DHh / 32, Bb * Hh);
            vtrans_kernel<<<grid, 256>>>(QKVH, VT);
        }
        {
            dim3 grid(Nn / HBN, Nn / HBM, Bb * Hh);
            mma_h_kernel<<<grid, 256, SMEM_H>>>(
                QKVH, QKVH + INNERd, SH, nullptr,
                DHh, 3 * INNERd, 3 * INNERd, Nn, Hh,
                (long)Nn * 3 * INNERd, DHh,
                (long)Nn * 3 * INNERd, DHh,
                (long)Hh * Nn * Nn, (long)Nn * Nn,
                0.125f, 0);
        }
        softmax_h_kernel<<<Bb * Hh * Nn, 256>>>(SH);
        {
            dim3 grid(1, Nn / HBM, Bb * Hh);
            mma_h_kernel<<<grid, 256, SMEM_H>>>(
                SH, VT, AHI, ALO,
                Nn, Nn, Nn, INNERd, Hh,
                (long)Hh * Nn * Nn, (long)Nn * Nn,
                (long)Hh * DHh * Nn, (long)DHh * Nn,
                (long)Nn * INNERd, DHh,
                1.0f, 1);
        }
        tgemm(AHI, ALO, whl + OFF_WO, wll + OFF_WO,
              bo + (long)l * Dm, X, X, nullptr, nullptr, Dm, INNERd, 1, 0, 0, 0);

        // --- router + expert gather ---
        reset_cnt_kernel<<<1, 32>>>(CNT);
        router_kernel<<<Tt, 128>>>(X, Wr + (long)l * Dm * Ee, br + (long)l * Ee,
                                   Wt + (long)l * Tt * Ee, CNT, EIDX);

        // --- FiLM trunk ---
        ln_split_kernel<<<Tt, 256>>>(X, ln2_g + l * Dm, ln2_b + l * Dm, AHI, ALO);
        tgemm(AHI, ALO, whl + OFF_WB0, wll + OFF_WB0,
              nullptr, nullptr, T01, nullptr, nullptr,
              Dm, Dm, 2, SZ1M, (long)Tt * Dm, 0);
        film_kernel<<<(Tt * Dm) / 256, 256>>>(T0, T1, bb0 + (long)l * Dm,
                                              bb1 + (long)l * Dm, AHI, ALO);

        // --- sparse gathered expert GEMMs (14 z-slices, early-exit on count) ---
        {
            dim3 grid(Dm / BN, Tt / BM, 2 * NEXP);
            mma_gather_kernel<<<grid, 256, SMEM_MM>>>(
                AHI, ALO, whl + OFF_WEP, wll + OFF_WEP, PA, CNT, EIDX);
        }

        // --- mix -> hi/lo ---
        mix_kernel<<<Tt, 256>>>(T0, PA, PA + (long)NEXP * Tt * Dm,
                                be_p + (long)l * NEXP * Dm,
                                be_a + (long)l * NEXP * Dm,
                                Wt + (long)l * Tt * Ee, AHI, ALO);

        // --- adaptor MLP + residual ---
        tgemm(AHI, ALO, whl + OFF_WA1, wll + OFF_WA1,
              ba1 + (long)l * MLPd, nullptr,
              nullptr, MHI, MLO, MLPd, Dm, 1, 0, 0, 1 /*gelu*/);
        tgemm(MHI, MLO, whl + OFF_WA2, wll + OFF_WA2,
              ba2 + (long)l * Dm, X, X, nullptr, nullptr, Dm, MLPd, 1, 0, 0, 0);
    }

    // outputs: x [B,N,D] then stacked router weights [L,B,N,E]
    cudaMemcpyAsync(d_out, X, (size_t)Tt * Dm * sizeof(float),
                    cudaMemcpyDeviceToDevice, 0);
    if (out_size >= Tt * Dm + Lnum * Tt * Ee) {
        cudaMemcpyAsync((float*)d_out + (size_t)Tt * Dm, Wt,
                        (size_t)Lnum * Tt * Ee * sizeof(float),
                        cudaMemcpyDeviceToDevice, 0);
    }
}

// round 8
// speedup vs baseline: 3.2424x; 1.0095x over previous
#include <cuda_runtime.h>
#include <cuda_fp16.h>
#include <cstdint>
#include <math.h>

// ---------------- problem constants ----------------
#define Dm     1024
#define Lnum   2
#define Hh     16
#define DHh    64
#define INNERd 1024
#define MLPd   4096
#define Ee     8
#define Bb     4
#define Nn     1024
#define Tt     (Bb*Nn)
#define NEXP   (Ee-1)

// weight pack offsets (elements, per layer)
#define SZ1M   (1024L*1024L)
#define OFF_QKV 0L
#define OFF_WO  (OFF_QKV + 3072L*1024L)
#define OFF_WB0 (OFF_WO  + SZ1M)
#define OFF_WB1 (OFF_WB0 + SZ1M)
#define OFF_WEP (OFF_WB1 + SZ1M)
#define OFF_WEA (OFF_WEP + 7L*SZ1M)
#define OFF_WA1 (OFF_WEA + 7L*SZ1M)
#define OFF_WA2 (OFF_WA1 + 4096L*1024L)
#define PER_L   (OFF_WA2 + 4096L*1024L)

// ---------------- scratch (device globals) ----------------
__device__ float g_x[Tt*Dm];
__device__ float g_t01[2L*Tt*Dm];
__device__ float g_pa[(size_t)2*NEXP*Tt*Dm];
__device__ float g_w[Lnum*Tt*Ee];
__device__ __half g_whi[2L*PER_L];
__device__ __half g_wlo[2L*PER_L];
__device__ __half g_ahi[(size_t)Tt*Dm];
__device__ __half g_alo[(size_t)Tt*Dm];
__device__ __half g_mhi[(size_t)Tt*MLPd];
__device__ __half g_mlo[(size_t)Tt*MLPd];
__device__ __half g_qkvh[(size_t)Tt*3*INNERd];
__device__ __half g_vt[(size_t)Bb*Hh*DHh*Nn];
__device__ __half g_sh[(size_t)Bb*Hh*Nn*Nn];
__device__ int g_cnt[NEXP];
__device__ int g_eidx[(size_t)NEXP*Tt];

__device__ __forceinline__ float gelu_f(float v) {
    return 0.5f * v * (1.0f + erff(v * 0.7071067811865475f));
}

__device__ __forceinline__ uint32_t smem_u32(const void* p) {
    uint32_t a;
    asm("{ .reg .u64 t; cvta.to.shared.u64 t, %1; cvt.u32.u64 %0, t; }"
        : "=r"(a) : "l"(p));
    return a;
}
__device__ __forceinline__ void ldmx4(uint32_t* r, uint32_t addr) {
    asm volatile("ldmatrix.sync.aligned.m8n8.x4.shared.b16 {%0,%1,%2,%3}, [%4];"
        : "=r"(r[0]), "=r"(r[1]), "=r"(r[2]), "=r"(r[3]) : "r"(addr));
}
__device__ __forceinline__ void ldmx2(uint32_t* r, uint32_t addr) {
    asm volatile("ldmatrix.sync.aligned.m8n8.x2.shared.b16 {%0,%1}, [%2];"
        : "=r"(r[0]), "=r"(r[1]) : "r"(addr));
}
__device__ __forceinline__ void mma16816(float* d, const uint32_t* a, const uint32_t* b) {
    asm volatile("mma.sync.aligned.m16n8k16.row.col.f32.f16.f16.f32 "
        "{%0,%1,%2,%3}, {%4,%5,%6,%7}, {%8,%9}, {%0,%1,%2,%3};"
        : "+f"(d[0]), "+f"(d[1]), "+f"(d[2]), "+f"(d[3])
        : "r"(a[0]), "r"(a[1]), "r"(a[2]), "r"(a[3]), "r"(b[0]), "r"(b[1]));
}

// ================= split HMMA GEMM (2 or 3 terms), 3-stage cp.async =================
#define BM 128
#define BN 128
#define BK 32
#define LDT 40
#define TILE_B (128*LDT*2)
#define ST_AHI 0
#define ST_ALO (1*TILE_B)
#define ST_BHI (2*TILE_B)
#define ST_BLO (3*TILE_B)
#define STAGE_B (4*TILE_B)
#define SMEM_MM (3*STAGE_B)

__global__ __launch_bounds__(256, 1) void mma_gemm_kernel(
    const __half* __restrict__ Ahi, const __half* __restrict__ Alo,
    const __half* __restrict__ Bhi, const __half* __restrict__ Blo,
    const float* __restrict__ bias, const float* __restrict__ resid,
    float* __restrict__ C, __half* __restrict__ Chi, __half* __restrict__ Clo,
    int M, int N, int K, long sB, long sC, int act,
    int hasBias, int hasRes, int wantF32, int wantHi, int wantLo, int terms)
{
    extern __shared__ char smem[];
    uint32_t sb = smem_u32(smem);
    const int tid = threadIdx.x;
    const int wid = tid >> 5;
    const int lane = tid & 31;
    const long z = blockIdx.z;
    Bhi += z * sB;
    Blo += z * sB;
    if (wantF32) C += z * sC;
    if (wantHi) Chi += z * sC;
    if (wantLo) Clo += z * sC;
    const float* res = hasRes ? (resid + z * sC) : nullptr;
    const int row0 = blockIdx.y * BM;
    const int col0 = blockIdx.x * BN;
    const int wm = wid & 1;
    const int wn = wid >> 1;

    float acc[4][4][4];
#pragma unroll
    for (int a = 0; a < 4; a++)
#pragma unroll
        for (int b = 0; b < 4; b++)
#pragma unroll
            for (int c = 0; c < 4; c++) acc[a][b][c] = 0.f;

    const int nc = K / BK;

    auto load_stage = [&](int s, int kt) {
        uint32_t base = sb + s * STAGE_B;
#pragma unroll
        for (int i = 0; i < 8; i++) {
            int idx = i * 256 + tid;
            int mat = idx >> 9;
            if (terms == 2 && mat == 1) continue;   // skip A_lo tile
            int rem = idx & 511;
            int r = rem >> 2, c = rem & 3;
            uint32_t sa = base + mat * TILE_B + (uint32_t)(r * LDT + c * 8) * 2;
            const __half* gp;
            if (mat == 0)      gp = Ahi + (long)(row0 + r) * K + kt + c * 8;
            else if (mat == 1) gp = Alo + (long)(row0 + r) * K + kt + c * 8;
            else if (mat == 2) gp = Bhi + (long)(col0 + r) * K + kt + c * 8;
            else               gp = Blo + (long)(col0 + r) * K + kt + c * 8;
            asm volatile("cp.async.cg.shared.global [%0], [%1], 16;"
                         :: "r"(sa), "l"(gp));
        }
        asm volatile("cp.async.commit_group;");
    };

    load_stage(0, 0);
    load_stage(1, BK);

    for (int c = 0; c < nc; c++) {
        int s = c % 3;
        if (c + 2 < nc) {
            load_stage((c + 2) % 3, (c + 2) * BK);
            asm volatile("cp.async.wait_group 2;");
        } else if (c + 1 < nc) {
            asm volatile("cp.async.wait_group 1;");
        } else {
            asm volatile("cp.async.wait_group 0;");
        }
        __syncthreads();

        uint32_t base = sb + s * STAGE_B;
#pragma unroll
        for (int ph = 0; ph < 2; ph++) {
            uint32_t ahi[4][4], alo[4][4], bhi[4][2], blo[4][2];
#pragma unroll
            for (int mt = 0; mt < 4; mt++) {
                int rr = wm * 64 + mt * 16 + (lane & 15);
                uint32_t co = (uint32_t)(rr * LDT + ph * 16 + (lane >> 4) * 8) * 2;
                ldmx4(ahi[mt], base + ST_AHI + co);
                if (terms == 3) ldmx4(alo[mt], base + ST_ALO + co);
            }
#pragma unroll
            for (int nt = 0; nt < 4; nt++) {
                int rr = wn * 32 + nt * 8 + (lane & 7);
                uint32_t co = (uint32_t)(rr * LDT + ph * 16 + ((lane >> 3) & 1) * 8) * 2;
                ldmx2(bhi[nt], base + ST_BHI + co);
                ldmx2(blo[nt], base + ST_BLO + co);
            }
#pragma unroll
            for (int mt = 0; mt < 4; mt++)
#pragma unroll
                for (int nt = 0; nt < 4; nt++) {
                    mma16816(acc[mt][nt], ahi[mt], bhi[nt]);
                    mma16816(acc[mt][nt], ahi[mt], blo[nt]);
                    if (terms == 3) mma16816(acc[mt][nt], alo[mt], bhi[nt]);
                }
        }
        __syncthreads();
    }

#pragma unroll
    for (int mt = 0; mt < 4; mt++) {
#pragma unroll
        for (int nt = 0; nt < 4; nt++) {
            int rb = row0 + wm * 64 + mt * 16 + (lane >> 2);
            int cc = col0 + wn * 32 + nt * 8 + (lane & 3) * 2;
            float b0 = 0.f, b1 = 0.f;
            if (hasBias) { b0 = bias[cc]; b1 = bias[cc + 1]; }
#pragma unroll
            for (int hf = 0; hf < 2; hf++) {
                int rr = rb + hf * 8;
                float v0 = acc[mt][nt][hf * 2] + b0;
                float v1 = acc[mt][nt][hf * 2 + 1] + b1;
                if (act == 1) { v0 = gelu_f(v0); v1 = gelu_f(v1); }
                if (hasRes) {
                    v0 += res[(long)rr * N + cc];
                    v1 += res[(long)rr * N + cc + 1];
                }
                long o = (long)rr * N + cc;
                if (wantF32) *(float2*)&C[o] = make_float2(v0, v1);
                if (wantHi) {
                    __half h0 = __float2half_rn(v0), h1 = __float2half_rn(v1);
                    *(__half2*)&Chi[o] = __halves2half2(h0, h1);
                    if (wantLo) {
                        __half l0 = __float2half_rn(v0 - __half2float(h0));
                        __half l1 = __float2half_rn(v1 - __half2float(h1));
                        *(__half2*)&Clo[o] = __halves2half2(l0, l1);
                    }
                }
            }
        }
    }
}

// ================= token-gathered sparse expert GEMM (2/3 terms, 3-stage) =================
__global__ __launch_bounds__(256, 1) void mma_gather_kernel(
    const __half* __restrict__ Ahi, const __half* __restrict__ Alo,
    const __half* __restrict__ Whi, const __half* __restrict__ Wlo,
    float* __restrict__ PA,
    const int* __restrict__ cnt, const int* __restrict__ eidx, int terms)
{
    const int z = blockIdx.z;
    const int e = z % NEXP;
    const int n = cnt[e];
    const int row0 = blockIdx.y * BM;
    if (row0 >= n) return;

    extern __shared__ char smem[];
    uint32_t sb = smem_u32(smem);
    __shared__ int sidx[BM];
    const int tid = threadIdx.x;
    const int wid = tid >> 5;
    const int lane = tid & 31;
    const __half* Bhi = Whi + (long)z * SZ1M;
    const __half* Blo = Wlo + (long)z * SZ1M;
    float* C = PA + (long)z * Tt * Dm;
    const int col0 = blockIdx.x * BN;
    const int wm = wid & 1;
    const int wn = wid >> 1;
    const int K = Dm;

    if (tid < BM) {
        int rr = row0 + tid;
        sidx[tid] = eidx[(long)e * Tt + (rr < n ? rr : n - 1)];
    }
    __syncthreads();

    float acc[4][4][4];
#pragma unroll
    for (int a = 0; a < 4; a++)
#pragma unroll
        for (int b = 0; b < 4; b++)
#pragma unroll
            for (int c = 0; c < 4; c++) acc[a][b][c] = 0.f;

    const int nc = K / BK;

    auto load_stage = [&](int s, int kt) {
        uint32_t base = sb + s * STAGE_B;
#pragma unroll
        for (int i = 0; i < 8; i++) {
            int idx = i * 256 + tid;
            int mat = idx >> 9;
            if (terms == 2 && mat == 1) continue;
            int rem = idx & 511;
            int r = rem >> 2, c = rem & 3;
            uint32_t sa = base + mat * TILE_B + (uint32_t)(r * LDT + c * 8) * 2;
            const __half* gp;
            if (mat == 0)      gp = Ahi + (long)sidx[r] * K + kt + c * 8;
            else if (mat == 1) gp = Alo + (long)sidx[r] * K + kt + c * 8;
            else if (mat == 2) gp = Bhi + (long)(col0 + r) * K + kt + c * 8;
            else               gp = Blo + (long)(col0 + r) * K + kt + c * 8;
            asm volatile("cp.async.cg.shared.global [%0], [%1], 16;"
                         :: "r"(sa), "l"(gp));
        }
        asm volatile("cp.async.commit_group;");
    };

    load_stage(0, 0);
    load_stage(1, BK);

    for (int c = 0; c < nc; c++) {
        int s = c % 3;
        if (c + 2 < nc) {
            load_stage((c + 2) % 3, (c + 2) * BK);
            asm volatile("cp.async.wait_group 2;");
        } else if (c + 1 < nc) {
            asm volatile("cp.async.wait_group 1;");
        } else {
            asm volatile("cp.async.wait_group 0;");
        }
        __syncthreads();

        uint32_t base = sb + s * STAGE_B;
#pragma unroll
        for (int ph = 0; ph < 2; ph++) {
            uint32_t ahi[4][4], alo[4][4], bhi[4][2], blo[4][2];
#pragma unroll
            for (int mt = 0; mt < 4; mt++) {
                int rr = wm * 64 + mt * 16 + (lane & 15);
                uint32_t co = (uint32_t)(rr * LDT + ph * 16 + (lane >> 4) * 8) * 2;
                ldmx4(ahi[mt], base + ST_AHI + co);
                if (terms == 3) ldmx4(alo[mt], base + ST_ALO + co);
            }
#pragma unroll
            for (int nt = 0; nt < 4; nt++) {
                int rr = wn * 32 + nt * 8 + (lane & 7);
                uint32_t co = (uint32_t)(rr * LDT + ph * 16 + ((lane >> 3) & 1) * 8) * 2;
                ldmx2(bhi[nt], base + ST_BHI + co);
                ldmx2(blo[nt], base + ST_BLO + co);
            }
#pragma unroll
            for (int mt = 0; mt < 4; mt++)
#pragma unroll
                for (int nt = 0; nt < 4; nt++) {
                    mma16816(acc[mt][nt], ahi[mt], bhi[nt]);
                    mma16816(acc[mt][nt], ahi[mt], blo[nt]);
                    if (terms == 3) mma16816(acc[mt][nt], alo[mt], bhi[nt]);
                }
        }
        __syncthreads();
    }

#pragma unroll
    for (int mt = 0; mt < 4; mt++) {
#pragma unroll
        for (int nt = 0; nt < 4; nt++) {
            int lr = wm * 64 + mt * 16 + (lane >> 2);
            int cc = col0 + wn * 32 + nt * 8 + (lane & 3) * 2;
#pragma unroll
            for (int hf = 0; hf < 2; hf++) {
                int lrr = lr + hf * 8;
                if (row0 + lrr < n) {
                    long o = (long)sidx[lrr] * Dm + cc;
                    *(float2*)&C[o] = make_float2(acc[mt][nt][hf * 2],
                                                  acc[mt][nt][hf * 2 + 1]);
                }
            }
        }
    }
}

// ================= single-term fp16 HMMA (attention QK^T and P*V) =================
#define HBM 128
#define HBN 64
#define HBK 64
#define LDTH 72
#define H_ATILE (128*LDTH*2)
#define H_BTILE (64*LDTH*2)
#define H_STAGE (H_ATILE + H_BTILE)
#define SMEM_H  (2*H_STAGE)

__global__ __launch_bounds__(256, 1) void mma_h_kernel(
    const __half* __restrict__ A, const __half* __restrict__ B,
    __half* __restrict__ Chi, __half* __restrict__ Clo,
    int K, int lda, int ldb, int ldc, int Hd,
    long sAb, long sAh, long sBb, long sBh, long sCb, long sCh,
    float scale, int wantLo)
{
    extern __shared__ char smem[];
    uint32_t sb = smem_u32(smem);
    const int tid = threadIdx.x;
    const int wid = tid >> 5;
    const int lane = tid & 31;
    const int z = blockIdx.z;
    const int zb = z / Hd, zh = z % Hd;
    A += (long)zb * sAb + (long)zh * sAh;
    B += (long)zb * sBb + (long)zh * sBh;
    Chi += (long)zb * sCb + (long)zh * sCh;
    if (wantLo) Clo += (long)zb * sCb + (long)zh * sCh;
    const int row0 = blockIdx.y * HBM;
    const int col0 = blockIdx.x * HBN;
    const int wm = wid & 1;
    const int wn = wid >> 1;

    float acc[4][2][4];
#pragma unroll
    for (int a = 0; a < 4; a++)
#pragma unroll
        for (int b = 0; b < 2; b++)
#pragma unroll
            for (int c = 0; c < 4; c++) acc[a][b][c] = 0.f;

    const int nc = K / HBK;

    auto load_stage = [&](int s, int kt) {
        uint32_t base = sb + s * H_STAGE;
#pragma unroll
        for (int i = 0; i < 6; i++) {
            int idx = i * 256 + tid;
            if (idx < 1024) {
                int r = idx >> 3, c = idx & 7;
                uint32_t sa = base + (uint32_t)(r * LDTH + c * 8) * 2;
                const __half* gp = A + (long)(row0 + r) * lda + kt + c * 8;
                asm volatile("cp.async.cg.shared.global [%0], [%1], 16;"
                             :: "r"(sa), "l"(gp));
            } else {
                int j = idx - 1024;
                int r = j >> 3, c = j & 7;
                uint32_t sa = base + H_ATILE + (uint32_t)(r * LDTH + c * 8) * 2;
                const __half* gp = B + (long)(col0 + r) * ldb + kt + c * 8;
                asm volatile("cp.async.cg.shared.global [%0], [%1], 16;"
                             :: "r"(sa), "l"(gp));
            }
        }
        asm volatile("cp.async.commit_group;");
    };

    load_stage(0, 0);

    for (int c = 0; c < nc; c++) {
        int s = c & 1;
        if (c + 1 < nc) {
            load_stage(s ^ 1, (c + 1) * HBK);
            asm volatile("cp.async.wait_group 1;");
        } else {
            asm volatile("cp.async.wait_group 0;");
        }
        __syncthreads();

        uint32_t base = sb + s * H_STAGE;
#pragma unroll
        for (int ph = 0; ph < 4; ph++) {
            uint32_t af[4][4], bf[2][2];
#pragma unroll
            for (int mt = 0; mt < 4; mt++) {
                int rr = wm * 64 + mt * 16 + (lane & 15);
                uint32_t co = (uint32_t)(rr * LDTH + ph * 16 + (lane >> 4) * 8) * 2;
                ldmx4(af[mt], base + co);
            }
#pragma unroll
            for (int nt = 0; nt < 2; nt++) {
                int rr = wn * 16 + nt * 8 + (lane & 7);
                uint32_t co = (uint32_t)(rr * LDTH + ph * 16 + ((lane >> 3) & 1) * 8) * 2;
                ldmx2(bf[nt], base + H_ATILE + co);
            }
#pragma unroll
            for (int mt = 0; mt < 4; mt++)
#pragma unroll
                for (int nt = 0; nt < 2; nt++)
                    mma16816(acc[mt][nt], af[mt], bf[nt]);
        }
        __syncthreads();
    }

#pragma unroll
    for (int mt = 0; mt < 4; mt++) {
#pragma unroll
        for (int nt = 0; nt < 2; nt++) {
            int rb = row0 + wm * 64 + mt * 16 + (lane >> 2);
            int cc = col0 + wn * 16 + nt * 8 + (lane & 3) * 2;
#pragma unroll
            for (int hf = 0; hf < 2; hf++) {
                int rr = rb + hf * 8;
                float v0 = acc[mt][nt][hf * 2] * scale;
                float v1 = acc[mt][nt][hf * 2 + 1] * scale;
                __half h0 = __float2half_rn(v0), h1 = __float2half_rn(v1);
                long o = (long)rr * ldc + cc;
                *(__half2*)&Chi[o] = __halves2half2(h0, h1);
                if (wantLo) {
                    __half l0 = __float2half_rn(v0 - __half2float(h0));
                    __half l1 = __float2half_rn(v1 - __half2float(h1));
                    *(__half2*)&Clo[o] = __halves2half2(l0, l1);
                }
            }
        }
    }
}

// ---------------- V transpose ----------------
__global__ __launch_bounds__(256) void vtrans_kernel(const __half* __restrict__ qkvh,
                                                     __half* __restrict__ vt)
{
    __shared__ __half t[32][33];
    int z = blockIdx.z, b = z >> 4, h = z & 15;
    int k0 = blockIdx.x * 32, d0 = blockIdx.y * 32;
    int tx = threadIdx.x & 31, ty = threadIdx.x >> 5;
#pragma unroll
    for (int i = 0; i < 4; i++) {
        int k = k0 + ty + i * 8;
        t[ty + i * 8][tx] = qkvh[(long)(b * Nn + k) * 3072 + 2048 + h * 64 + d0 + tx];
    }
    __syncthreads();
#pragma unroll
    for (int i = 0; i < 4; i++) {
        int d = d0 + ty + i * 8;
        vt[((long)z * 64 + d) * Nn + k0 + tx] = t[tx][ty + i * 8];
    }
}

// ---------------- fp16 softmax ----------------
__global__ __launch_bounds__(256) void softmax_h_kernel(__half* __restrict__ s)
{
    __half2* p = (__half2*)(s + (size_t)blockIdx.x * Nn);
    int tid = threadIdx.x;
    __shared__ float red[256];

    __half2 a = p[tid * 2], b = p[tid * 2 + 1];
    float v[4] = {__low2float(a), __high2float(a), __low2float(b), __high2float(b)};
    float m = fmaxf(fmaxf(v[0], v[1]), fmaxf(v[2], v[3]));
    red[tid] = m; __syncthreads();
    for (int st = 128; st > 0; st >>= 1) {
        if (tid < st) red[tid] = fmaxf(red[tid], red[tid + st]);
        __syncthreads();
    }
    m = red[0]; __syncthreads();

    float sum = 0.f;
#pragma unroll
    for (int i = 0; i < 4; i++) { v[i] = expf(v[i] - m); sum += v[i]; }
    red[tid] = sum; __syncthreads();
    for (int st = 128; st > 0; st >>= 1) {
        if (tid < st) red[tid] += red[tid + st];
        __syncthreads();
    }
    float inv = 1.f / red[0];
    p[tid * 2]     = __halves2half2(__float2half_rn(v[0] * inv), __float2half_rn(v[1] * inv));
    p[tid * 2 + 1] = __halves2half2(__float2half_rn(v[2] * inv), __float2half_rn(v[3] * inv));
}

// ---------------- weight transpose + fp16 split (vectorized 64x64) ----------------
__global__ __launch_bounds__(256) void wsplit_kernel(
    const float* __restrict__ W, __half* __restrict__ hi, __half* __restrict__ lo,
    int K, int N, long inStride, long outStride)
{
    __shared__ float tile[64][65];
    const float* Wz = W + blockIdx.z * inStride;
    long ob = (long)blockIdx.z * outStride;
    int k0 = blockIdx.y * 64, n0 = blockIdx.x * 64;
    int tid = threadIdx.x;
    // read: 64 K-rows x 16 float4
#pragma unroll
    for (int i = 0; i < 4; i++) {
        int idx = i * 256 + tid;
        int r = idx >> 4, c4 = idx & 15;
        float4 v = *(const float4*)(Wz + (long)(k0 + r) * N + n0 + c4 * 4);
        tile[r][c4 * 4 + 0] = v.x; tile[r][c4 * 4 + 1] = v.y;
        tile[r][c4 * 4 + 2] = v.z; tile[r][c4 * 4 + 3] = v.w;
    }
    __syncthreads();
    // write: 64 N-rows x 8 k-groups of 8 halves (16B vector stores)
#pragma unroll
    for (int i = 0; i < 2; i++) {
        int idx = i * 256 + tid;
        int nn = idx >> 3, kg = idx & 7;
        __half hbuf[8], lbuf[8];
#pragma unroll
        for (int j = 0; j < 8; j++) {
            float v = tile[kg * 8 + j][nn];
            __half h = __float2half_rn(v);
            hbuf[j] = h;
            lbuf[j] = __float2half_rn(v - __half2float(h));
        }
        long o = ob + (long)(n0 + nn) * K + k0 + kg * 8;
        *(uint4*)(hi + o) = *(uint4*)hbuf;
        *(uint4*)(lo + o) = *(uint4*)lbuf;
    }
}

// ---------------- LayerNorm -> fp16 hi(/lo) ----------------
__global__ __launch_bounds__(256) void ln_split_kernel(
    const float* __restrict__ x, const float* __restrict__ g,
    const float* __restrict__ bta,
    __half* __restrict__ hi, __half* __restrict__ lo, int wantLo)
{
    int t = blockIdx.x, tid = threadIdx.x;
    const float* xp = x + (long)t * Dm;
    __shared__ float r1[256], r2[256];

    float v[4], s = 0.f, s2 = 0.f;
#pragma unroll
    for (int i = 0; i < 4; i++) { v[i] = xp[tid + i * 256]; s += v[i]; s2 += v[i] * v[i]; }
    r1[tid] = s; r2[tid] = s2; __syncthreads();
    for (int st = 128; st > 0; st >>= 1) {
        if (tid < st) { r1[tid] += r1[tid + st]; r2[tid] += r2[tid + st]; }
        __syncthreads();
    }
    float mean = r1[0] * (1.f / Dm);
    float var = r2[0] * (1.f / Dm) - mean * mean;
    float rstd = rsqrtf(var + 1e-5f);
#pragma unroll
    for (int i = 0; i < 4; i++) {
        int d = tid + i * 256;
        float y = (v[i] - mean) * rstd * g[d] + bta[d];
        __half h = __float2half_rn(y);
        hi[(long)t * Dm + d] = h;
        if (wantLo) lo[(long)t * Dm + d] = __float2half_rn(y - __half2float(h));
    }
}

// ---------------- reset expert counters ----------------
__global__ void reset_cnt_kernel(int* cnt)
{
    if (threadIdx.x < NEXP) cnt[threadIdx.x] = 0;
}

// ---------------- router (+ expert token gather) ----------------
__global__ __launch_bounds__(128) void router_kernel(const float* __restrict__ x,
                                                     const float* __restrict__ Wr,
                                                     const float* __restrict__ br,
                                                     float* __restrict__ wout,
                                                     int* __restrict__ cnt,
                                                     int* __restrict__ eidx)
{
    int t = blockIdx.x, tid = threadIdx.x;
    __shared__ float part[128][Ee];
    float acc[Ee];
#pragma unroll
    for (int e = 0; e < Ee; e++) acc[e] = 0.f;
    const float* xp = x + (long)t * Dm;
    for (int d = tid; d < Dm; d += 128) {
        float xv = xp[d];
        const float* wrow = Wr + (long)d * Ee;
#pragma unroll
        for (int e = 0; e < Ee; e++) acc[e] += xv * wrow[e];
    }
#pragma unroll
    for (int e = 0; e < Ee; e++) part[tid][e] = acc[e];
    __syncthreads();
    for (int st = 64; st > 0; st >>= 1) {
        if (tid < st)
#pragma unroll
            for (int e = 0; e < Ee; e++) part[tid][e] += part[tid + st][e];
        __syncthreads();
    }
    if (tid == 0) {
        float lg[Ee];
#pragma unroll
        for (int e = 0; e < Ee; e++) lg[e] = part[0][e] + br[e];
        float m1 = -3.4e38f, m2 = -3.4e38f;
#pragma unroll
        for (int e = 0; e < Ee; e++) {
            float v = lg[e];
            if (v > m1) { m2 = m1; m1 = v; }
            else if (v > m2) m2 = v;
        }
        float sum = 0.f, we[Ee];
#pragma unroll
        for (int e = 0; e < Ee; e++) {
            we[e] = (lg[e] < m2) ? 0.f : expf(lg[e] - m1);
            sum += we[e];
        }
        float inv = 1.f / sum;
#pragma unroll
        for (int e = 0; e < Ee; e++) wout[(long)t * Ee + e] = we[e] * inv;
#pragma unroll
        for (int e = 0; e < NEXP; e++) {
            if (we[e + 1] != 0.f) {
                int p = atomicAdd(&cnt[e], 1);
                eidx[(long)e * Tt + p] = t;
            }
        }
    }
}

// ---------------- FiLM: ytf = gelu(t0+b0)*(t1+b1); write fp32 + hi(/lo) ----------------
__global__ __launch_bounds__(256) void film_kernel(float* __restrict__ t0,
                                                   const float* __restrict__ t1,
                                                   const float* __restrict__ b0,
                                                   const float* __restrict__ b1,
                                                   __half* __restrict__ hi,
                                                   __half* __restrict__ lo, int wantLo)
{
    long i = (long)blockIdx.x * 256 + threadIdx.x;
    int d = (int)(i & (Dm - 1));
    float y = gelu_f(t0[i] + b0[d]) * (t1[i] + b1[d]);
    t0[i] = y;
    __half h = __float2half_rn(y);
    hi[i] = h;
    if (wantLo) lo[i] = __float2half_rn(y - __half2float(h));
}

// ---------------- expert mixing -> hi(/lo) ----------------
__global__ __launch_bounds__(256) void mix_kernel(const float* __restrict__ ytf,
                                                  const float* __restrict__ pe,
                                                  const float* __restrict__ ae,
                                                  const float* __restrict__ Pb,
                                                  const float* __restrict__ Ab,
                                                  const float* __restrict__ w,
                                                  __half* __restrict__ hi,
                                                  __half* __restrict__ lo, int wantLo)
{
    int t = blockIdx.x;
    __shared__ float ws[Ee];
    if (threadIdx.x < Ee) ws[threadIdx.x] = w[(long)t * Ee + threadIdx.x];
    __syncthreads();
#pragma unroll
    for (int it = 0; it < 4; it++) {
        int d = threadIdx.x + it * 256;
        long td = (long)t * Dm + d;
        float yv = ytf[td];
        float out = ws[0] * gelu_f(yv);
#pragma unroll
        for (int e = 0; e < NEXP; e++) {
            float we = ws[e + 1];
            if (we != 0.f) {
                float p = pe[(long)e * Tt * Dm + td] + Pb[e * Dm + d];
                float a = ae[(long)e * Tt * Dm + td] + Ab[e * Dm + d];
                out += we * (p * yv + a);
            }
        }
        __half h = __float2half_rn(out);
        hi[td] = h;
        if (wantLo) lo[td] = __float2half_rn(out - __half2float(h));
    }
}

// ---------------- host helpers ----------------
static float* symf(const void* s) { void* p = nullptr; cudaGetSymbolAddress(&p, s); return (float*)p; }
static __half* symh(const void* s) { void* p = nullptr; cudaGetSymbolAddress(&p, s); return (__half*)p; }
static int* symi(const void* s) { void* p = nullptr; cudaGetSymbolAddress(&p, s); return (int*)p; }

static void wsplit(const float* W, __half* hi, __half* lo, int K, int N,
                   long inStride, long outStride, int z)
{
    dim3 grid(N / 64, K / 64, z);
    wsplit_kernel<<<grid, 256>>>(W, hi, lo, K, N, inStride, outStride);
}

static void tgemm(const __half* ahi, const __half* alo,
                  const __half* bhi, const __half* blo,
                  const float* bias, const float* resid,
                  float* C, __half* Chi, __half* Clo,
                  int N, int K, int Z, long sB, long sC, int act, int terms)
{
    dim3 grid(N / BN, Tt / BM, Z);
    mma_gemm_kernel<<<grid, 256, SMEM_MM>>>(ahi, alo, bhi, blo, bias, resid,
                                            C, Chi, Clo, Tt, N, K, sB, sC, act,
                                            bias != nullptr, resid != nullptr,
                                            C != nullptr, Chi != nullptr, Clo != nullptr,
                                            terms);
}

extern "C" void kernel_launch(void* const* d_in, const int* in_sizes, int n_in,
                              void* d_out, int out_size)
{
    const float* x_in  = (const float*)d_in[0];
    const float* ln1_g = (const float*)d_in[1];
    const float* ln1_b = (const float*)d_in[2];
    const float* Wqkv  = (const float*)d_in[3];
    const float* bqkv  = (const float*)d_in[4];
    const float* Wo    = (const float*)d_in[5];
    const float* bo    = (const float*)d_in[6];
    const float* Wr    = (const float*)d_in[7];
    const float* br    = (const float*)d_in[8];
    const float* Wa1   = (const float*)d_in[9];
    const float* ba1   = (const float*)d_in[10];
    const float* Wa2   = (const float*)d_in[11];
    const float* ba2   = (const float*)d_in[12];
    const float* ln2_g = (const float*)d_in[13];
    const float* ln2_b = (const float*)d_in[14];
    const float* Wb0   = (const float*)d_in[15];
    const float* bb0   = (const float*)d_in[16];
    const float* Wb1   = (const float*)d_in[17];
    const float* bb1   = (const float*)d_in[18];
    const float* We_p  = (const float*)d_in[19];
    const float* be_p  = (const float*)d_in[20];
    const float* We_a  = (const float*)d_in[21];
    const float* be_a  = (const float*)d_in[22];

    float* X   = symf(g_x);
    float* T01 = symf(g_t01);
    float* T0  = T01;
    float* T1  = T01 + (long)Tt * Dm;
    float* PA  = symf(g_pa);
    float* Wt  = symf(g_w);
    __half* WHI = symh(g_whi);
    __half* WLO = symh(g_wlo);
    __half* AHI = symh(g_ahi);
    __half* ALO = symh(g_alo);
    __half* MHI = symh(g_mhi);
    __half* MLO = symh(g_mlo);
    __half* QKVH = symh(g_qkvh);
    __half* VT  = symh(g_vt);
    __half* SH  = symh(g_sh);
    int* CNT = symi(g_cnt);
    int* EIDX = symi(g_eidx);

    cudaFuncSetAttribute(mma_gemm_kernel,
                         cudaFuncAttributeMaxDynamicSharedMemorySize, SMEM_MM);
    cudaFuncSetAttribute(mma_gather_kernel,
                         cudaFuncAttributeMaxDynamicSharedMemorySize, SMEM_MM);
    cudaFuncSetAttribute(mma_h_kernel,
                         cudaFuncAttributeMaxDynamicSharedMemorySize, SMEM_H);

    // ---- weight transpose + split ----
    wsplit(Wqkv, WHI + OFF_QKV, WLO + OFF_QKV, 1024, 3072, 3072L * 1024, PER_L, Lnum);
    wsplit(Wo,   WHI + OFF_WO,  WLO + OFF_WO,  1024, 1024, SZ1M, PER_L, Lnum);
    wsplit(Wb0,  WHI + OFF_WB0, WLO + OFF_WB0, 1024, 1024, SZ1M, PER_L, Lnum);
    wsplit(Wb1,  WHI + OFF_WB1, WLO + OFF_WB1, 1024, 1024, SZ1M, PER_L, Lnum);
    for (int l = 0; l < Lnum; l++) {
        wsplit(We_p + (long)l * NEXP * SZ1M, WHI + l * PER_L + OFF_WEP,
               WLO + l * PER_L + OFF_WEP, 1024, 1024, SZ1M, SZ1M, NEXP);
        wsplit(We_a + (long)l * NEXP * SZ1M, WHI + l * PER_L + OFF_WEA,
               WLO + l * PER_L + OFF_WEA, 1024, 1024, SZ1M, SZ1M, NEXP);
    }
    wsplit(Wa1, WHI + OFF_WA1, WLO + OFF_WA1, 1024, 4096, 4096L * 1024, PER_L, Lnum);
    wsplit(Wa2, WHI + OFF_WA2, WLO + OFF_WA2, 4096, 1024, 4096L * 1024, PER_L, Lnum);

    cudaMemcpyAsync(X, x_in, (size_t)Tt * Dm * sizeof(float),
                    cudaMemcpyDeviceToDevice, 0);

    for (int l = 0; l < Lnum; l++) {
        const __half* whl = WHI + (long)l * PER_L;
        const __half* wll = WLO + (long)l * PER_L;
        // Last layer's post-router GEMMs affect no router -> 2-term split is safe.
        const int tpost = (l == Lnum - 1) ? 2 : 3;
        const int loPost = (tpost == 3) ? 1 : 0;

        // --- attention ---
        ln_split_kernel<<<Tt, 256>>>(X, ln1_g + l * Dm, ln1_b + l * Dm, AHI, ALO, 1);
        tgemm(AHI, ALO, whl + OFF_QKV, wll + OFF_QKV,
              bqkv + (long)l * 3 * INNERd, nullptr,
              nullptr, QKVH, nullptr, 3 * INNERd, Dm, 1, 0, 0, 0, 3);

        {
            dim3 grid(Nn / 32, DHh / 32, Bb * Hh);
            vtrans_kernel<<<grid, 256>>>(QKVH, VT);
        }
        {
            dim3 grid(Nn / HBN, Nn / HBM, Bb * Hh);
            mma_h_kernel<<<grid, 256, SMEM_H>>>(
                QKVH, QKVH + INNERd, SH, nullptr,
                DHh, 3 * INNERd, 3 * INNERd, Nn, Hh,
                (long)Nn * 3 * INNERd, DHh,
                (long)Nn * 3 * INNERd, DHh,
                (long)Hh * Nn * Nn, (long)Nn * Nn,
                0.125f, 0);
        }
        softmax_h_kernel<<<Bb * Hh * Nn, 256>>>(SH);
        {
            dim3 grid(1, Nn / HBM, Bb * Hh);
            mma_h_kernel<<<grid, 256, SMEM_H>>>(
                SH, VT, AHI, ALO,
                Nn, Nn, Nn, INNERd, Hh,
                (long)Hh * Nn * Nn, (long)Nn * Nn,
                (long)Hh * DHh * Nn, (long)DHh * Nn,
                (long)Nn * INNERd, DHh,
                1.0f, 1);
        }
        tgemm(AHI, ALO, whl + OFF_WO, wll + OFF_WO,
              bo + (long)l * Dm, X, X, nullptr, nullptr, Dm, INNERd, 1, 0, 0, 0, 3);

        // --- router + expert gather ---
        reset_cnt_kernel<<<1, 32>>>(CNT);
        router_kernel<<<Tt, 128>>>(X, Wr + (long)l * Dm * Ee, br + (long)l * Ee,
                                   Wt + (long)l * Tt * Ee, CNT, EIDX);

        // --- FiLM trunk ---
        ln_split_kernel<<<Tt, 256>>>(X, ln2_g + l * Dm, ln2_b + l * Dm, AHI, ALO, loPost);
        tgemm(AHI, ALO, whl + OFF_WB0, wll + OFF_WB0,
              nullptr, nullptr, T01, nullptr, nullptr,
              Dm, Dm, 2, SZ1M, (long)Tt * Dm, 0, tpost);
        film_kernel<<<(Tt * Dm) / 256, 256>>>(T0, T1, bb0 + (long)l * Dm,
                                              bb1 + (long)l * Dm, AHI, ALO, loPost);

        // --- sparse gathered expert GEMMs ---
        {
            dim3 grid(Dm / BN, Tt / BM, 2 * NEXP);
            mma_gather_kernel<<<grid, 256, SMEM_MM>>>(
                AHI, ALO, whl + OFF_WEP, wll + OFF_WEP, PA, CNT, EIDX, tpost);
        }

        // --- mix -> hi(/lo) ---
        mix_kernel<<<Tt, 256>>>(T0, PA, PA + (long)NEXP * Tt * Dm,
                                be_p + (long)l * NEXP * Dm,
                                be_a + (long)l * NEXP * Dm,
                                Wt + (long)l * Tt * Ee, AHI, ALO, loPost);

        // --- adaptor MLP + residual ---
        tgemm(AHI, ALO, whl + OFF_WA1, wll + OFF_WA1,
              ba1 + (long)l * MLPd, nullptr,
              nullptr, MHI, (loPost ? MLO : nullptr), MLPd, Dm, 1, 0, 0, 1, tpost);
        tgemm(MHI, MLO, whl + OFF_WA2, wll + OFF_WA2,
              ba2 + (long)l * Dm, X, X, nullptr, nullptr, Dm, MLPd, 1, 0, 0, 0, tpost);
    }

    // outputs: x [B,N,D] then stacked router weights [L,B,N,E]
    cudaMemcpyAsync(d_out, X, (size_t)Tt * Dm * sizeof(float),
                    cudaMemcpyDeviceToDevice, 0);
    if (out_size >= Tt * Dm + Lnum * Tt * Ee) {
        cudaMemcpyAsync((float*)d_out + (size_t)Tt * Dm, Wt,
                        (size_t)Lnum * Tt * Ee * sizeof(float),
                        cudaMemcpyDeviceToDevice, 0);
    }
}

// round 9
// speedup vs baseline: 3.9307x; 1.2123x over previous
#include <cuda_runtime.h>
#include <cuda_fp16.h>
#include <cstdint>
#include <math.h>

// ---------------- problem constants ----------------
#define Dm     1024
#define Lnum   2
#define Hh     16
#define DHh    64
#define INNERd 1024
#define MLPd   4096
#define Ee     8
#define Bb     4
#define Nn     1024
#define Tt     (Bb*Nn)
#define NEXP   (Ee-1)

// weight pack offsets (elements, per layer)
#define SZ1M   (1024L*1024L)
#define OFF_QKV 0L
#define OFF_WO  (OFF_QKV + 3072L*1024L)
#define OFF_WB0 (OFF_WO  + SZ1M)
#define OFF_WB1 (OFF_WB0 + SZ1M)
#define OFF_WEP (OFF_WB1 + SZ1M)
#define OFF_WEA (OFF_WEP + 7L*SZ1M)
#define OFF_WA1 (OFF_WEA + 7L*SZ1M)
#define OFF_WA2 (OFF_WA1 + 4096L*1024L)
#define PER_L   (OFF_WA2 + 4096L*1024L)

// ---------------- scratch (device globals) ----------------
__device__ float g_x[Tt*Dm];
__device__ float g_t01[2L*Tt*Dm];
__device__ float g_pa[(size_t)2*NEXP*Tt*Dm];
__device__ float g_w[Lnum*Tt*Ee];
__device__ __half g_whi[2L*PER_L];
__device__ __half g_wlo[2L*PER_L];
__device__ __half g_ahi[(size_t)Tt*Dm];
__device__ __half g_alo[(size_t)Tt*Dm];
__device__ __half g_mhi[(size_t)Tt*MLPd];
__device__ __half g_mlo[(size_t)Tt*MLPd];
__device__ __half g_qkvh[(size_t)Tt*3*INNERd];
__device__ __half g_vt[(size_t)Bb*Hh*DHh*Nn];
__device__ __half g_sh[(size_t)Bb*Hh*Nn*Nn];
__device__ int g_cnt[NEXP];
__device__ int g_eidx[(size_t)NEXP*Tt];

__device__ __forceinline__ float gelu_f(float v) {
    return 0.5f * v * (1.0f + erff(v * 0.7071067811865475f));
}

__device__ __forceinline__ uint32_t smem_u32(const void* p) {
    uint32_t a;
    asm("{ .reg .u64 t; cvta.to.shared.u64 t, %1; cvt.u32.u64 %0, t; }"
        : "=r"(a) : "l"(p));
    return a;
}
__device__ __forceinline__ void ldmx4(uint32_t* r, uint32_t addr) {
    asm volatile("ldmatrix.sync.aligned.m8n8.x4.shared.b16 {%0,%1,%2,%3}, [%4];"
        : "=r"(r[0]), "=r"(r[1]), "=r"(r[2]), "=r"(r[3]) : "r"(addr));
}
__device__ __forceinline__ void ldmx2(uint32_t* r, uint32_t addr) {
    asm volatile("ldmatrix.sync.aligned.m8n8.x2.shared.b16 {%0,%1}, [%2];"
        : "=r"(r[0]), "=r"(r[1]) : "r"(addr));
}
__device__ __forceinline__ void mma16816(float* d, const uint32_t* a, const uint32_t* b) {
    asm volatile("mma.sync.aligned.m16n8k16.row.col.f32.f16.f16.f32 "
        "{%0,%1,%2,%3}, {%4,%5,%6,%7}, {%8,%9}, {%0,%1,%2,%3};"
        : "+f"(d[0]), "+f"(d[1]), "+f"(d[2]), "+f"(d[3])
        : "r"(a[0]), "r"(a[1]), "r"(a[2]), "r"(a[3]), "r"(b[0]), "r"(b[1]));
}

// ================= split HMMA GEMM (2 or 3 terms), 2-stage, 2 CTAs/SM =================
#define BM 128
#define BN 128
#define BK 32
#define LDT 40
#define TILE_B (128*LDT*2)
#define ST_AHI 0
#define ST_ALO (1*TILE_B)
#define ST_BHI (2*TILE_B)
#define ST_BLO (3*TILE_B)
#define STAGE_B (4*TILE_B)
#define SMEM_MM (2*STAGE_B)

// inner compute phase shared by both GEMM kernels (register-lean: A regs reused)
#define GEMM_PHASE(base, ph)                                                      \
    do {                                                                          \
        uint32_t bhi[4][2], blo[4][2], af[4][4];                                  \
        _Pragma("unroll")                                                         \
        for (int nt = 0; nt < 4; nt++) {                                          \
            int rr = wn * 32 + nt * 8 + (lane & 7);                               \
            uint32_t co = (uint32_t)(rr * LDT + (ph) * 16 + ((lane >> 3) & 1) * 8) * 2; \
            ldmx2(bhi[nt], (base) + ST_BHI + co);                                 \
            ldmx2(blo[nt], (base) + ST_BLO + co);                                 \
        }                                                                         \
        _Pragma("unroll")                                                         \
        for (int mt = 0; mt < 4; mt++) {                                          \
            int rr = wm * 64 + mt * 16 + (lane & 15);                             \
            uint32_t co = (uint32_t)(rr * LDT + (ph) * 16 + (lane >> 4) * 8) * 2; \
            ldmx4(af[mt], (base) + ST_AHI + co);                                  \
        }                                                                         \
        _Pragma("unroll")                                                         \
        for (int mt = 0; mt < 4; mt++)                                            \
            _Pragma("unroll")                                                     \
            for (int nt = 0; nt < 4; nt++) {                                      \
                mma16816(acc[mt][nt], af[mt], bhi[nt]);                           \
                mma16816(acc[mt][nt], af[mt], blo[nt]);                           \
            }                                                                     \
        if (terms == 3) {                                                         \
            _Pragma("unroll")                                                     \
            for (int mt = 0; mt < 4; mt++) {                                      \
                int rr = wm * 64 + mt * 16 + (lane & 15);                         \
                uint32_t co = (uint32_t)(rr * LDT + (ph) * 16 + (lane >> 4) * 8) * 2; \
                ldmx4(af[mt], (base) + ST_ALO + co);                              \
            }                                                                     \
            _Pragma("unroll")                                                     \
            for (int mt = 0; mt < 4; mt++)                                        \
                _Pragma("unroll")                                                 \
                for (int nt = 0; nt < 4; nt++)                                    \
                    mma16816(acc[mt][nt], af[mt], bhi[nt]);                       \
        }                                                                         \
    } while (0)

__global__ __launch_bounds__(256, 2) void mma_gemm_kernel(
    const __half* __restrict__ Ahi, const __half* __restrict__ Alo,
    const __half* __restrict__ Bhi, const __half* __restrict__ Blo,
    const float* __restrict__ bias, const float* __restrict__ resid,
    float* __restrict__ C, __half* __restrict__ Chi, __half* __restrict__ Clo,
    int M, int N, int K, long sB, long sC, int act,
    int hasBias, int hasRes, int wantF32, int wantHi, int wantLo, int terms)
{
    extern __shared__ char smem[];
    uint32_t sb = smem_u32(smem);
    const int tid = threadIdx.x;
    const int wid = tid >> 5;
    const int lane = tid & 31;
    const long z = blockIdx.z;
    Bhi += z * sB;
    Blo += z * sB;
    if (wantF32) C += z * sC;
    if (wantHi) Chi += z * sC;
    if (wantLo) Clo += z * sC;
    const float* res = hasRes ? (resid + z * sC) : nullptr;
    const int row0 = blockIdx.y * BM;
    const int col0 = blockIdx.x * BN;
    const int wm = wid & 1;
    const int wn = wid >> 1;

    float acc[4][4][4];
#pragma unroll
    for (int a = 0; a < 4; a++)
#pragma unroll
        for (int b = 0; b < 4; b++)
#pragma unroll
            for (int c = 0; c < 4; c++) acc[a][b][c] = 0.f;

    const int nc = K / BK;

    auto load_stage = [&](int s, int kt) {
        uint32_t base = sb + s * STAGE_B;
#pragma unroll
        for (int i = 0; i < 8; i++) {
            int idx = i * 256 + tid;
            int mat = idx >> 9;
            if (terms == 2 && mat == 1) continue;
            int rem = idx & 511;
            int r = rem >> 2, c = rem & 3;
            uint32_t sa = base + mat * TILE_B + (uint32_t)(r * LDT + c * 8) * 2;
            const __half* gp;
            if (mat == 0)      gp = Ahi + (long)(row0 + r) * K + kt + c * 8;
            else if (mat == 1) gp = Alo + (long)(row0 + r) * K + kt + c * 8;
            else if (mat == 2) gp = Bhi + (long)(col0 + r) * K + kt + c * 8;
            else               gp = Blo + (long)(col0 + r) * K + kt + c * 8;
            asm volatile("cp.async.cg.shared.global [%0], [%1], 16;"
                         :: "r"(sa), "l"(gp));
        }
        asm volatile("cp.async.commit_group;");
    };

    load_stage(0, 0);

    for (int c = 0; c < nc; c++) {
        int s = c & 1;
        if (c + 1 < nc) {
            load_stage(s ^ 1, (c + 1) * BK);
            asm volatile("cp.async.wait_group 1;");
        } else {
            asm volatile("cp.async.wait_group 0;");
        }
        __syncthreads();
        uint32_t base = sb + s * STAGE_B;
        GEMM_PHASE(base, 0);
        GEMM_PHASE(base, 1);
        __syncthreads();
    }

#pragma unroll
    for (int mt = 0; mt < 4; mt++) {
#pragma unroll
        for (int nt = 0; nt < 4; nt++) {
            int rb = row0 + wm * 64 + mt * 16 + (lane >> 2);
            int cc = col0 + wn * 32 + nt * 8 + (lane & 3) * 2;
            float b0 = 0.f, b1 = 0.f;
            if (hasBias) { b0 = bias[cc]; b1 = bias[cc + 1]; }
#pragma unroll
            for (int hf = 0; hf < 2; hf++) {
                int rr = rb + hf * 8;
                float v0 = acc[mt][nt][hf * 2] + b0;
                float v1 = acc[mt][nt][hf * 2 + 1] + b1;
                if (act == 1) { v0 = gelu_f(v0); v1 = gelu_f(v1); }
                if (hasRes) {
                    v0 += res[(long)rr * N + cc];
                    v1 += res[(long)rr * N + cc + 1];
                }
                long o = (long)rr * N + cc;
                if (wantF32) *(float2*)&C[o] = make_float2(v0, v1);
                if (wantHi) {
                    __half h0 = __float2half_rn(v0), h1 = __float2half_rn(v1);
                    *(__half2*)&Chi[o] = __halves2half2(h0, h1);
                    if (wantLo) {
                        __half l0 = __float2half_rn(v0 - __half2float(h0));
                        __half l1 = __float2half_rn(v1 - __half2float(h1));
                        *(__half2*)&Clo[o] = __halves2half2(l0, l1);
                    }
                }
            }
        }
    }
}

// ================= token-gathered sparse expert GEMM =================
__global__ __launch_bounds__(256, 2) void mma_gather_kernel(
    const __half* __restrict__ Ahi, const __half* __restrict__ Alo,
    const __half* __restrict__ Whi, const __half* __restrict__ Wlo,
    float* __restrict__ PA,
    const int* __restrict__ cnt, const int* __restrict__ eidx, int terms)
{
    const int z = blockIdx.z;
    const int e = z % NEXP;
    const int n = cnt[e];
    const int row0 = blockIdx.y * BM;
    if (row0 >= n) return;

    extern __shared__ char smem[];
    uint32_t sb = smem_u32(smem);
    __shared__ int sidx[BM];
    const int tid = threadIdx.x;
    const int wid = tid >> 5;
    const int lane = tid & 31;
    const __half* Bhi = Whi + (long)z * SZ1M;
    const __half* Blo = Wlo + (long)z * SZ1M;
    float* C = PA + (long)z * Tt * Dm;
    const int col0 = blockIdx.x * BN;
    const int wm = wid & 1;
    const int wn = wid >> 1;
    const int K = Dm;

    if (tid < BM) {
        int rr = row0 + tid;
        sidx[tid] = eidx[(long)e * Tt + (rr < n ? rr : n - 1)];
    }
    __syncthreads();

    float acc[4][4][4];
#pragma unroll
    for (int a = 0; a < 4; a++)
#pragma unroll
        for (int b = 0; b < 4; b++)
#pragma unroll
            for (int c = 0; c < 4; c++) acc[a][b][c] = 0.f;

    const int nc = K / BK;

    auto load_stage = [&](int s, int kt) {
        uint32_t base = sb + s * STAGE_B;
#pragma unroll
        for (int i = 0; i < 8; i++) {
            int idx = i * 256 + tid;
            int mat = idx >> 9;
            if (terms == 2 && mat == 1) continue;
            int rem = idx & 511;
            int r = rem >> 2, c = rem & 3;
            uint32_t sa = base + mat * TILE_B + (uint32_t)(r * LDT + c * 8) * 2;
            const __half* gp;
            if (mat == 0)      gp = Ahi + (long)sidx[r] * K + kt + c * 8;
            else if (mat == 1) gp = Alo + (long)sidx[r] * K + kt + c * 8;
            else if (mat == 2) gp = Bhi + (long)(col0 + r) * K + kt + c * 8;
            else               gp = Blo + (long)(col0 + r) * K + kt + c * 8;
            asm volatile("cp.async.cg.shared.global [%0], [%1], 16;"
                         :: "r"(sa), "l"(gp));
        }
        asm volatile("cp.async.commit_group;");
    };

    load_stage(0, 0);

    for (int c = 0; c < nc; c++) {
        int s = c & 1;
        if (c + 1 < nc) {
            load_stage(s ^ 1, (c + 1) * BK);
            asm volatile("cp.async.wait_group 1;");
        } else {
            asm volatile("cp.async.wait_group 0;");
        }
        __syncthreads();
        uint32_t base = sb + s * STAGE_B;
        GEMM_PHASE(base, 0);
        GEMM_PHASE(base, 1);
        __syncthreads();
    }

#pragma unroll
    for (int mt = 0; mt < 4; mt++) {
#pragma unroll
        for (int nt = 0; nt < 4; nt++) {
            int lr = wm * 64 + mt * 16 + (lane >> 2);
            int cc = col0 + wn * 32 + nt * 8 + (lane & 3) * 2;
#pragma unroll
            for (int hf = 0; hf < 2; hf++) {
                int lrr = lr + hf * 8;
                if (row0 + lrr < n) {
                    long o = (long)sidx[lrr] * Dm + cc;
                    *(float2*)&C[o] = make_float2(acc[mt][nt][hf * 2],
                                                  acc[mt][nt][hf * 2 + 1]);
                }
            }
        }
    }
}

// ================= single-term fp16 HMMA (attention QK^T and P*V) =================
#define HBM 128
#define HBN 64
#define HBK 64
#define LDTH 72
#define H_ATILE (128*LDTH*2)
#define H_BTILE (64*LDTH*2)
#define H_STAGE (H_ATILE + H_BTILE)
#define SMEM_H  (2*H_STAGE)

__global__ __launch_bounds__(256, 2) void mma_h_kernel(
    const __half* __restrict__ A, const __half* __restrict__ B,
    __half* __restrict__ Chi, __half* __restrict__ Clo,
    int K, int lda, int ldb, int ldc, int Hd,
    long sAb, long sAh, long sBb, long sBh, long sCb, long sCh,
    float scale, int wantLo)
{
    extern __shared__ char smem[];
    uint32_t sb = smem_u32(smem);
    const int tid = threadIdx.x;
    const int wid = tid >> 5;
    const int lane = tid & 31;
    const int z = blockIdx.z;
    const int zb = z / Hd, zh = z % Hd;
    A += (long)zb * sAb + (long)zh * sAh;
    B += (long)zb * sBb + (long)zh * sBh;
    Chi += (long)zb * sCb + (long)zh * sCh;
    if (wantLo) Clo += (long)zb * sCb + (long)zh * sCh;
    const int row0 = blockIdx.y * HBM;
    const int col0 = blockIdx.x * HBN;
    const int wm = wid & 1;
    const int wn = wid >> 1;

    float acc[4][2][4];
#pragma unroll
    for (int a = 0; a < 4; a++)
#pragma unroll
        for (int b = 0; b < 2; b++)
#pragma unroll
            for (int c = 0; c < 4; c++) acc[a][b][c] = 0.f;

    const int nc = K / HBK;

    auto load_stage = [&](int s, int kt) {
        uint32_t base = sb + s * H_STAGE;
#pragma unroll
        for (int i = 0; i < 6; i++) {
            int idx = i * 256 + tid;
            if (idx < 1024) {
                int r = idx >> 3, c = idx & 7;
                uint32_t sa = base + (uint32_t)(r * LDTH + c * 8) * 2;
                const __half* gp = A + (long)(row0 + r) * lda + kt + c * 8;
                asm volatile("cp.async.cg.shared.global [%0], [%1], 16;"
                             :: "r"(sa), "l"(gp));
            } else {
                int j = idx - 1024;
                int r = j >> 3, c = j & 7;
                uint32_t sa = base + H_ATILE + (uint32_t)(r * LDTH + c * 8) * 2;
                const __half* gp = B + (long)(col0 + r) * ldb + kt + c * 8;
                asm volatile("cp.async.cg.shared.global [%0], [%1], 16;"
                             :: "r"(sa), "l"(gp));
            }
        }
        asm volatile("cp.async.commit_group;");
    };

    load_stage(0, 0);

    for (int c = 0; c < nc; c++) {
        int s = c & 1;
        if (c + 1 < nc) {
            load_stage(s ^ 1, (c + 1) * HBK);
            asm volatile("cp.async.wait_group 1;");
        } else {
            asm volatile("cp.async.wait_group 0;");
        }
        __syncthreads();

        uint32_t base = sb + s * H_STAGE;
#pragma unroll
        for (int ph = 0; ph < 4; ph++) {
            uint32_t af[4][4], bf[2][2];
#pragma unroll
            for (int mt = 0; mt < 4; mt++) {
                int rr = wm * 64 + mt * 16 + (lane & 15);
                uint32_t co = (uint32_t)(rr * LDTH + ph * 16 + (lane >> 4) * 8) * 2;
                ldmx4(af[mt], base + co);
            }
#pragma unroll
            for (int nt = 0; nt < 2; nt++) {
                int rr = wn * 16 + nt * 8 + (lane & 7);
                uint32_t co = (uint32_t)(rr * LDTH + ph * 16 + ((lane >> 3) & 1) * 8) * 2;
                ldmx2(bf[nt], base + H_ATILE + co);
            }
#pragma unroll
            for (int mt = 0; mt < 4; mt++)
#pragma unroll
                for (int nt = 0; nt < 2; nt++)
                    mma16816(acc[mt][nt], af[mt], bf[nt]);
        }
        __syncthreads();
    }

#pragma unroll
    for (int mt = 0; mt < 4; mt++) {
#pragma unroll
        for (int nt = 0; nt < 2; nt++) {
            int rb = row0 + wm * 64 + mt * 16 + (lane >> 2);
            int cc = col0 + wn * 16 + nt * 8 + (lane & 3) * 2;
#pragma unroll
            for (int hf = 0; hf < 2; hf++) {
                int rr = rb + hf * 8;
                float v0 = acc[mt][nt][hf * 2] * scale;
                float v1 = acc[mt][nt][hf * 2 + 1] * scale;
                __half h0 = __float2half_rn(v0), h1 = __float2half_rn(v1);
                long o = (long)rr * ldc + cc;
                *(__half2*)&Chi[o] = __halves2half2(h0, h1);
                if (wantLo) {
                    __half l0 = __float2half_rn(v0 - __half2float(h0));
                    __half l1 = __float2half_rn(v1 - __half2float(h1));
                    *(__half2*)&Clo[o] = __halves2half2(l0, l1);
                }
            }
        }
    }
}

// ---------------- V transpose ----------------
__global__ __launch_bounds__(256) void vtrans_kernel(const __half* __restrict__ qkvh,
                                                     __half* __restrict__ vt)
{
    __shared__ __half t[32][33];
    int z = blockIdx.z, b = z >> 4, h = z & 15;
    int k0 = blockIdx.x * 32, d0 = blockIdx.y * 32;
    int tx = threadIdx.x & 31, ty = threadIdx.x >> 5;
#pragma unroll
    for (int i = 0; i < 4; i++) {
        int k = k0 + ty + i * 8;
        t[ty + i * 8][tx] = qkvh[(long)(b * Nn + k) * 3072 + 2048 + h * 64 + d0 + tx];
    }
    __syncthreads();
#pragma unroll
    for (int i = 0; i < 4; i++) {
        int d = d0 + ty + i * 8;
        vt[((long)z * 64 + d) * Nn + k0 + tx] = t[tx][ty + i * 8];
    }
}

// ---------------- fp16 softmax ----------------
__global__ __launch_bounds__(256) void softmax_h_kernel(__half* __restrict__ s)
{
    __half2* p = (__half2*)(s + (size_t)blockIdx.x * Nn);
    int tid = threadIdx.x;
    __shared__ float red[256];

    __half2 a = p[tid * 2], b = p[tid * 2 + 1];
    float v[4] = {__low2float(a), __high2float(a), __low2float(b), __high2float(b)};
    float m = fmaxf(fmaxf(v[0], v[1]), fmaxf(v[2], v[3]));
    red[tid] = m; __syncthreads();
    for (int st = 128; st > 0; st >>= 1) {
        if (tid < st) red[tid] = fmaxf(red[tid], red[tid + st]);
        __syncthreads();
    }
    m = red[0]; __syncthreads();

    float sum = 0.f;
#pragma unroll
    for (int i = 0; i < 4; i++) { v[i] = expf(v[i] - m); sum += v[i]; }
    red[tid] = sum; __syncthreads();
    for (int st = 128; st > 0; st >>= 1) {
        if (tid < st) red[tid] += red[tid + st];
        __syncthreads();
    }
    float inv = 1.f / red[0];
    p[tid * 2]     = __halves2half2(__float2half_rn(v[0] * inv), __float2half_rn(v[1] * inv));
    p[tid * 2 + 1] = __halves2half2(__float2half_rn(v[2] * inv), __float2half_rn(v[3] * inv));
}

// ---------------- weight transpose + fp16 split (vectorized 64x64) ----------------
__global__ __launch_bounds__(256) void wsplit_kernel(
    const float* __restrict__ W, __half* __restrict__ hi, __half* __restrict__ lo,
    int K, int N, long inStride, long outStride)
{
    __shared__ float tile[64][65];
    const float* Wz = W + blockIdx.z * inStride;
    long ob = (long)blockIdx.z * outStride;
    int k0 = blockIdx.y * 64, n0 = blockIdx.x * 64;
    int tid = threadIdx.x;
#pragma unroll
    for (int i = 0; i < 4; i++) {
        int idx = i * 256 + tid;
        int r = idx >> 4, c4 = idx & 15;
        float4 v = *(const float4*)(Wz + (long)(k0 + r) * N + n0 + c4 * 4);
        tile[r][c4 * 4 + 0] = v.x; tile[r][c4 * 4 + 1] = v.y;
        tile[r][c4 * 4 + 2] = v.z; tile[r][c4 * 4 + 3] = v.w;
    }
    __syncthreads();
#pragma unroll
    for (int i = 0; i < 2; i++) {
        int idx = i * 256 + tid;
        int nn = idx >> 3, kg = idx & 7;
        __half hbuf[8], lbuf[8];
#pragma unroll
        for (int j = 0; j < 8; j++) {
            float v = tile[kg * 8 + j][nn];
            __half h = __float2half_rn(v);
            hbuf[j] = h;
            lbuf[j] = __float2half_rn(v - __half2float(h));
        }
        long o = ob + (long)(n0 + nn) * K + k0 + kg * 8;
        *(uint4*)(hi + o) = *(uint4*)hbuf;
        *(uint4*)(lo + o) = *(uint4*)lbuf;
    }
}

// ---------------- LayerNorm -> fp16 hi(/lo) ----------------
__global__ __launch_bounds__(256) void ln_split_kernel(
    const float* __restrict__ x, const float* __restrict__ g,
    const float* __restrict__ bta,
    __half* __restrict__ hi, __half* __restrict__ lo, int wantLo)
{
    int t = blockIdx.x, tid = threadIdx.x;
    const float* xp = x + (long)t * Dm;
    __shared__ float r1[256], r2[256];

    float v[4], s = 0.f, s2 = 0.f;
#pragma unroll
    for (int i = 0; i < 4; i++) { v[i] = xp[tid + i * 256]; s += v[i]; s2 += v[i] * v[i]; }
    r1[tid] = s; r2[tid] = s2; __syncthreads();
    for (int st = 128; st > 0; st >>= 1) {
        if (tid < st) { r1[tid] += r1[tid + st]; r2[tid] += r2[tid + st]; }
        __syncthreads();
    }
    float mean = r1[0] * (1.f / Dm);
    float var = r2[0] * (1.f / Dm) - mean * mean;
    float rstd = rsqrtf(var + 1e-5f);
#pragma unroll
    for (int i = 0; i < 4; i++) {
        int d = tid + i * 256;
        float y = (v[i] - mean) * rstd * g[d] + bta[d];
        __half h = __float2half_rn(y);
        hi[(long)t * Dm + d] = h;
        if (wantLo) lo[(long)t * Dm + d] = __float2half_rn(y - __half2float(h));
    }
}

// ---------------- reset expert counters ----------------
__global__ void reset_cnt_kernel(int* cnt)
{
    if (threadIdx.x < NEXP) cnt[threadIdx.x] = 0;
}

// ---------------- router (+ expert token gather) ----------------
__global__ __launch_bounds__(128) void router_kernel(const float* __restrict__ x,
                                                     const float* __restrict__ Wr,
                                                     const float* __restrict__ br,
                                                     float* __restrict__ wout,
                                                     int* __restrict__ cnt,
                                                     int* __restrict__ eidx)
{
    int t = blockIdx.x, tid = threadIdx.x;
    __shared__ float part[128][Ee];
    float acc[Ee];
#pragma unroll
    for (int e = 0; e < Ee; e++) acc[e] = 0.f;
    const float* xp = x + (long)t * Dm;
    for (int d = tid; d < Dm; d += 128) {
        float xv = xp[d];
        const float* wrow = Wr + (long)d * Ee;
#pragma unroll
        for (int e = 0; e < Ee; e++) acc[e] += xv * wrow[e];
    }
#pragma unroll
    for (int e = 0; e < Ee; e++) part[tid][e] = acc[e];
    __syncthreads();
    for (int st = 64; st > 0; st >>= 1) {
        if (tid < st)
#pragma unroll
            for (int e = 0; e < Ee; e++) part[tid][e] += part[tid + st][e];
        __syncthreads();
    }
    if (tid == 0) {
        float lg[Ee];
#pragma unroll
        for (int e = 0; e < Ee; e++) lg[e] = part[0][e] + br[e];
        float m1 = -3.4e38f, m2 = -3.4e38f;
#pragma unroll
        for (int e = 0; e < Ee; e++) {
            float v = lg[e];
            if (v > m1) { m2 = m1; m1 = v; }
            else if (v > m2) m2 = v;
        }
        float sum = 0.f, we[Ee];
#pragma unroll
        for (int e = 0; e < Ee; e++) {
            we[e] = (lg[e] < m2) ? 0.f : expf(lg[e] - m1);
            sum += we[e];
        }
        float inv = 1.f / sum;
#pragma unroll
        for (int e = 0; e < Ee; e++) wout[(long)t * Ee + e] = we[e] * inv;
#pragma unroll
        for (int e = 0; e < NEXP; e++) {
            if (we[e + 1] != 0.f) {
                int p = atomicAdd(&cnt[e], 1);
                eidx[(long)e * Tt + p] = t;
            }
        }
    }
}

// ---------------- FiLM: ytf = gelu(t0+b0)*(t1+b1); write fp32 + hi(/lo) ----------------
__global__ __launch_bounds__(256) void film_kernel(float* __restrict__ t0,
                                                   const float* __restrict__ t1,
                                                   const float* __restrict__ b0,
                                                   const float* __restrict__ b1,
                                                   __half* __restrict__ hi,
                                                   __half* __restrict__ lo, int wantLo)
{
    long i = (long)blockIdx.x * 256 + threadIdx.x;
    int d = (int)(i & (Dm - 1));
    float y = gelu_f(t0[i] + b0[d]) * (t1[i] + b1[d]);
    t0[i] = y;
    __half h = __float2half_rn(y);
    hi[i] = h;
    if (wantLo) lo[i] = __float2half_rn(y - __half2float(h));
}

// ---------------- expert mixing -> hi(/lo) ----------------
__global__ __launch_bounds__(256) void mix_kernel(const float* __restrict__ ytf,
                                                  const float* __restrict__ pe,
                                                  const float* __restrict__ ae,
                                                  const float* __restrict__ Pb,
                                                  const float* __restrict__ Ab,
                                                  const float* __restrict__ w,
                                                  __half* __restrict__ hi,
                                                  __half* __restrict__ lo, int wantLo)
{
    int t = blockIdx.x;
    __shared__ float ws[Ee];
    if (threadIdx.x < Ee) ws[threadIdx.x] = w[(long)t * Ee + threadIdx.x];
    __syncthreads();
#pragma unroll
    for (int it = 0; it < 4; it++) {
        int d = threadIdx.x + it * 256;
        long td = (long)t * Dm + d;
        float yv = ytf[td];
        float out = ws[0] * gelu_f(yv);
#pragma unroll
        for (int e = 0; e < NEXP; e++) {
            float we = ws[e + 1];
            if (we != 0.f) {
                float p = pe[(long)e * Tt * Dm + td] + Pb[e * Dm + d];
                float a = ae[(long)e * Tt * Dm + td] + Ab[e * Dm + d];
                out += we * (p * yv + a);
            }
        }
        __half h = __float2half_rn(out);
        hi[td] = h;
        if (wantLo) lo[td] = __float2half_rn(out - __half2float(h));
    }
}

// ---------------- host helpers ----------------
static float* symf(const void* s) { void* p = nullptr; cudaGetSymbolAddress(&p, s); return (float*)p; }
static __half* symh(const void* s) { void* p = nullptr; cudaGetSymbolAddress(&p, s); return (__half*)p; }
static int* symi(const void* s) { void* p = nullptr; cudaGetSymbolAddress(&p, s); return (int*)p; }

static void wsplit(const float* W, __half* hi, __half* lo, int K, int N,
                   long inStride, long outStride, int z)
{
    dim3 grid(N / 64, K / 64, z);
    wsplit_kernel<<<grid, 256>>>(W, hi, lo, K, N, inStride, outStride);
}

static void tgemm(const __half* ahi, const __half* alo,
                  const __half* bhi, const __half* blo,
                  const float* bias, const float* resid,
                  float* C, __half* Chi, __half* Clo,
                  int N, int K, int Z, long sB, long sC, int act, int terms)
{
    dim3 grid(N / BN, Tt / BM, Z);
    mma_gemm_kernel<<<grid, 256, SMEM_MM>>>(ahi, alo, bhi, blo, bias, resid,
                                            C, Chi, Clo, Tt, N, K, sB, sC, act,
                                            bias != nullptr, resid != nullptr,
                                            C != nullptr, Chi != nullptr, Clo != nullptr,
                                            terms);
}

extern "C" void kernel_launch(void* const* d_in, const int* in_sizes, int n_in,
                              void* d_out, int out_size)
{
    const float* x_in  = (const float*)d_in[0];
    const float* ln1_g = (const float*)d_in[1];
    const float* ln1_b = (const float*)d_in[2];
    const float* Wqkv  = (const float*)d_in[3];
    const float* bqkv  = (const float*)d_in[4];
    const float* Wo    = (const float*)d_in[5];
    const float* bo    = (const float*)d_in[6];
    const float* Wr    = (const float*)d_in[7];
    const float* br    = (const float*)d_in[8];
    const float* Wa1   = (const float*)d_in[9];
    const float* ba1   = (const float*)d_in[10];
    const float* Wa2   = (const float*)d_in[11];
    const float* ba2   = (const float*)d_in[12];
    const float* ln2_g = (const float*)d_in[13];
    const float* ln2_b = (const float*)d_in[14];
    const float* Wb0   = (const float*)d_in[15];
    const float* bb0   = (const float*)d_in[16];
    const float* Wb1   = (const float*)d_in[17];
    const float* bb1   = (const float*)d_in[18];
    const float* We_p  = (const float*)d_in[19];
    const float* be_p  = (const float*)d_in[20];
    const float* We_a  = (const float*)d_in[21];
    const float* be_a  = (const float*)d_in[22];

    float* X   = symf(g_x);
    float* T01 = symf(g_t01);
    float* T0  = T01;
    float* T1  = T01 + (long)Tt * Dm;
    float* PA  = symf(g_pa);
    float* Wt  = symf(g_w);
    __half* WHI = symh(g_whi);
    __half* WLO = symh(g_wlo);
    __half* AHI = symh(g_ahi);
    __half* ALO = symh(g_alo);
    __half* MHI = symh(g_mhi);
    __half* MLO = symh(g_mlo);
    __half* QKVH = symh(g_qkvh);
    __half* VT  = symh(g_vt);
    __half* SH  = symh(g_sh);
    int* CNT = symi(g_cnt);
    int* EIDX = symi(g_eidx);

    cudaFuncSetAttribute(mma_gemm_kernel,
                         cudaFuncAttributeMaxDynamicSharedMemorySize, SMEM_MM);
    cudaFuncSetAttribute(mma_gather_kernel,
                         cudaFuncAttributeMaxDynamicSharedMemorySize, SMEM_MM);
    cudaFuncSetAttribute(mma_h_kernel,
                         cudaFuncAttributeMaxDynamicSharedMemorySize, SMEM_H);

    // ---- weight transpose + split ----
    wsplit(Wqkv, WHI + OFF_QKV, WLO + OFF_QKV, 1024, 3072, 3072L * 1024, PER_L, Lnum);
    wsplit(Wo,   WHI + OFF_WO,  WLO + OFF_WO,  1024, 1024, SZ1M, PER_L, Lnum);
    wsplit(Wb0,  WHI + OFF_WB0, WLO + OFF_WB0, 1024, 1024, SZ1M, PER_L, Lnum);
    wsplit(Wb1,  WHI + OFF_WB1, WLO + OFF_WB1, 1024, 1024, SZ1M, PER_L, Lnum);
    for (int l = 0; l < Lnum; l++) {
        wsplit(We_p + (long)l * NEXP * SZ1M, WHI + l * PER_L + OFF_WEP,
               WLO + l * PER_L + OFF_WEP, 1024, 1024, SZ1M, SZ1M, NEXP);
        wsplit(We_a + (long)l * NEXP * SZ1M, WHI + l * PER_L + OFF_WEA,
               WLO + l * PER_L + OFF_WEA, 1024, 1024, SZ1M, SZ1M, NEXP);
    }
    wsplit(Wa1, WHI + OFF_WA1, WLO + OFF_WA1, 1024, 4096, 4096L * 1024, PER_L, Lnum);
    wsplit(Wa2, WHI + OFF_WA2, WLO + OFF_WA2, 4096, 1024, 4096L * 1024, PER_L, Lnum);

    cudaMemcpyAsync(X, x_in, (size_t)Tt * Dm * sizeof(float),
                    cudaMemcpyDeviceToDevice, 0);

    for (int l = 0; l < Lnum; l++) {
        const __half* whl = WHI + (long)l * PER_L;
        const __half* wll = WLO + (long)l * PER_L;
        const int tpost = (l == Lnum - 1) ? 2 : 3;
        const int loPost = (tpost == 3) ? 1 : 0;

        // --- attention ---
        ln_split_kernel<<<Tt, 256>>>(X, ln1_g + l * Dm, ln1_b + l * Dm, AHI, ALO, 1);
        tgemm(AHI, ALO, whl + OFF_QKV, wll + OFF_QKV,
              bqkv + (long)l * 3 * INNERd, nullptr,
              nullptr, QKVH, nullptr, 3 * INNERd, Dm, 1, 0, 0, 0, 3);

        {
            dim3 grid(Nn / 32, DHh / 32, Bb * Hh);
            vtrans_kernel<<<grid, 256>>>(QKVH, VT);
        }
        {
            dim3 grid(Nn / HBN, Nn / HBM, Bb * Hh);
            mma_h_kernel<<<grid, 256, SMEM_H>>>(
                QKVH, QKVH + INNERd, SH, nullptr,
                DHh, 3 * INNERd, 3 * INNERd, Nn, Hh,
                (long)Nn * 3 * INNERd, DHh,
                (long)Nn * 3 * INNERd, DHh,
                (long)Hh * Nn * Nn, (long)Nn * Nn,
                0.125f, 0);
        }
        softmax_h_kernel<<<Bb * Hh * Nn, 256>>>(SH);
        {
            dim3 grid(1, Nn / HBM, Bb * Hh);
            mma_h_kernel<<<grid, 256, SMEM_H>>>(
                SH, VT, AHI, ALO,
                Nn, Nn, Nn, INNERd, Hh,
                (long)Hh * Nn * Nn, (long)Nn * Nn,
                (long)Hh * DHh * Nn, (long)DHh * Nn,
                (long)Nn * INNERd, DHh,
                1.0f, 1);
        }
        tgemm(AHI, ALO, whl + OFF_WO, wll + OFF_WO,
              bo + (long)l * Dm, X, X, nullptr, nullptr, Dm, INNERd, 1, 0, 0, 0, 3);

        // --- router + expert gather ---
        reset_cnt_kernel<<<1, 32>>>(CNT);
        router_kernel<<<Tt, 128>>>(X, Wr + (long)l * Dm * Ee, br + (long)l * Ee,
                                   Wt + (long)l * Tt * Ee, CNT, EIDX);

        // --- FiLM trunk ---
        ln_split_kernel<<<Tt, 256>>>(X, ln2_g + l * Dm, ln2_b + l * Dm, AHI, ALO, loPost);
        tgemm(AHI, ALO, whl + OFF_WB0, wll + OFF_WB0,
              nullptr, nullptr, T01, nullptr, nullptr,
              Dm, Dm, 2, SZ1M, (long)Tt * Dm, 0, tpost);
        film_kernel<<<(Tt * Dm) / 256, 256>>>(T0, T1, bb0 + (long)l * Dm,
                                              bb1 + (long)l * Dm, AHI, ALO, loPost);

        // --- sparse gathered expert GEMMs ---
        {
            dim3 grid(Dm / BN, Tt / BM, 2 * NEXP);
            mma_gather_kernel<<<grid, 256, SMEM_MM>>>(
                AHI, ALO, whl + OFF_WEP, wll + OFF_WEP, PA, CNT, EIDX, tpost);
        }

        // --- mix -> hi(/lo) ---
        mix_kernel<<<Tt, 256>>>(T0, PA, PA + (long)NEXP * Tt * Dm,
                                be_p + (long)l * NEXP * Dm,
                                be_a + (long)l * NEXP * Dm,
                                Wt + (long)l * Tt * Ee, AHI, ALO, loPost);

        // --- adaptor MLP + residual ---
        tgemm(AHI, ALO, whl + OFF_WA1, wll + OFF_WA1,
              ba1 + (long)l * MLPd, nullptr,
              nullptr, MHI, (loPost ? MLO : nullptr), MLPd, Dm, 1, 0, 0, 1, tpost);
        tgemm(MHI, MLO, whl + OFF_WA2, wll + OFF_WA2,
              ba2 + (long)l * Dm, X, X, nullptr, nullptr, Dm, MLPd, 1, 0, 0, 0, tpost);
    }

    // outputs: x [B,N,D] then stacked router weights [L,B,N,E]
    cudaMemcpyAsync(d_out, X, (size_t)Tt * Dm * sizeof(float),
                    cudaMemcpyDeviceToDevice, 0);
    if (out_size >= Tt * Dm + Lnum * Tt * Ee) {
        cudaMemcpyAsync((float*)d_out + (size_t)Tt * Dm, Wt,
                        (size_t)Lnum * Tt * Ee * sizeof(float),
                        cudaMemcpyDeviceToDevice, 0);
    }
}

// round 10
// speedup vs baseline: 4.1176x; 1.0475x over previous
#include <cuda_runtime.h>
#include <cuda_fp16.h>
#include <cstdint>
#include <math.h>

// ---------------- problem constants ----------------
#define Dm     1024
#define Lnum   2
#define Hh     16
#define DHh    64
#define INNERd 1024
#define MLPd   4096
#define Ee     8
#define Bb     4
#define Nn     1024
#define Tt     (Bb*Nn)
#define NEXP   (Ee-1)

// weight pack offsets (elements, per layer)
#define SZ1M   (1024L*1024L)
#define OFF_QKV 0L
#define OFF_WO  (OFF_QKV + 3072L*1024L)
#define OFF_WB0 (OFF_WO  + SZ1M)
#define OFF_WB1 (OFF_WB0 + SZ1M)
#define OFF_WEP (OFF_WB1 + SZ1M)
#define OFF_WEA (OFF_WEP + 7L*SZ1M)
#define OFF_WA1 (OFF_WEA + 7L*SZ1M)
#define OFF_WA2 (OFF_WA1 + 4096L*1024L)
#define PER_L   (OFF_WA2 + 4096L*1024L)

// ---------------- scratch (device globals) ----------------
__device__ float g_x[Tt*Dm];
__device__ float g_t01[2L*Tt*Dm];
__device__ float g_pa[(size_t)2*NEXP*Tt*Dm];
__device__ float g_w[Lnum*Tt*Ee];
__device__ __half g_whi[2L*PER_L];
__device__ __half g_wlo[2L*PER_L];
__device__ __half g_ahi[(size_t)Tt*Dm];
__device__ __half g_alo[(size_t)Tt*Dm];
__device__ __half g_mhi[(size_t)Tt*MLPd];
__device__ __half g_mlo[(size_t)Tt*MLPd];
__device__ __half g_qkvh[(size_t)Tt*3*INNERd];
__device__ __half g_vt[(size_t)Bb*Hh*DHh*Nn];
__device__ __half g_sh[(size_t)Bb*Hh*Nn*Nn];
__device__ int g_cnt[NEXP];
__device__ int g_eidx[(size_t)NEXP*Tt];

__device__ __forceinline__ float gelu_f(float v) {
    return 0.5f * v * (1.0f + erff(v * 0.7071067811865475f));
}

__device__ __forceinline__ uint32_t smem_u32(const void* p) {
    uint32_t a;
    asm("{ .reg .u64 t; cvta.to.shared.u64 t, %1; cvt.u32.u64 %0, t; }"
        : "=r"(a) : "l"(p));
    return a;
}
__device__ __forceinline__ void ldmx4(uint32_t* r, uint32_t addr) {
    asm volatile("ldmatrix.sync.aligned.m8n8.x4.shared.b16 {%0,%1,%2,%3}, [%4];"
        : "=r"(r[0]), "=r"(r[1]), "=r"(r[2]), "=r"(r[3]) : "r"(addr));
}
__device__ __forceinline__ void ldmx2(uint32_t* r, uint32_t addr) {
    asm volatile("ldmatrix.sync.aligned.m8n8.x2.shared.b16 {%0,%1}, [%2];"
        : "=r"(r[0]), "=r"(r[1]) : "r"(addr));
}
__device__ __forceinline__ void mma16816(float* d, const uint32_t* a, const uint32_t* b) {
    asm volatile("mma.sync.aligned.m16n8k16.row.col.f32.f16.f16.f32 "
        "{%0,%1,%2,%3}, {%4,%5,%6,%7}, {%8,%9}, {%0,%1,%2,%3};"
        : "+f"(d[0]), "+f"(d[1]), "+f"(d[2]), "+f"(d[3])
        : "r"(a[0]), "r"(a[1]), "r"(a[2]), "r"(a[3]), "r"(b[0]), "r"(b[1]));
}

// ================= split HMMA GEMM (2 or 3 terms), 2-stage, 2 CTAs/SM =================
#define BM 128
#define BN 128
#define BK 32
#define LDT 40
#define TILE_B (128*LDT*2)
#define ST_AHI 0
#define ST_ALO (1*TILE_B)
#define ST_BHI (2*TILE_B)
#define ST_BLO (3*TILE_B)
#define STAGE_B (4*TILE_B)
#define SMEM_MM (2*STAGE_B)

#define GEMM_PHASE(base, ph)                                                      \
    do {                                                                          \
        uint32_t bhi[4][2], blo[4][2], af[4][4];                                  \
        _Pragma("unroll")                                                         \
        for (int nt = 0; nt < 4; nt++) {                                          \
            int rr = wn * 32 + nt * 8 + (lane & 7);                               \
            uint32_t co = (uint32_t)(rr * LDT + (ph) * 16 + ((lane >> 3) & 1) * 8) * 2; \
            ldmx2(bhi[nt], (base) + ST_BHI + co);                                 \
            ldmx2(blo[nt], (base) + ST_BLO + co);                                 \
        }                                                                         \
        _Pragma("unroll")                                                         \
        for (int mt = 0; mt < 4; mt++) {                                          \
            int rr = wm * 64 + mt * 16 + (lane & 15);                             \
            uint32_t co = (uint32_t)(rr * LDT + (ph) * 16 + (lane >> 4) * 8) * 2; \
            ldmx4(af[mt], (base) + ST_AHI + co);                                  \
        }                                                                         \
        _Pragma("unroll")                                                         \
        for (int mt = 0; mt < 4; mt++)                                            \
            _Pragma("unroll")                                                     \
            for (int nt = 0; nt < 4; nt++) {                                      \
                mma16816(acc[mt][nt], af[mt], bhi[nt]);                           \
                mma16816(acc[mt][nt], af[mt], blo[nt]);                           \
            }                                                                     \
        if (terms == 3) {                                                         \
            _Pragma("unroll")                                                     \
            for (int mt = 0; mt < 4; mt++) {                                      \
                int rr = wm * 64 + mt * 16 + (lane & 15);                         \
                uint32_t co = (uint32_t)(rr * LDT + (ph) * 16 + (lane >> 4) * 8) * 2; \
                ldmx4(af[mt], (base) + ST_ALO + co);                              \
            }                                                                     \
            _Pragma("unroll")                                                     \
            for (int mt = 0; mt < 4; mt++)                                        \
                _Pragma("unroll")                                                 \
                for (int nt = 0; nt < 4; nt++)                                    \
                    mma16816(acc[mt][nt], af[mt], bhi[nt]);                       \
        }                                                                         \
    } while (0)

__global__ __launch_bounds__(256, 2) void mma_gemm_kernel(
    const __half* __restrict__ Ahi, const __half* __restrict__ Alo,
    const __half* __restrict__ Bhi, const __half* __restrict__ Blo,
    const float* __restrict__ bias, const float* __restrict__ resid,
    float* __restrict__ C, __half* __restrict__ Chi, __half* __restrict__ Clo,
    int M, int N, int K, long sB, long sC, int act,
    int hasBias, int hasRes, int wantF32, int wantHi, int wantLo, int terms)
{
    extern __shared__ char smem[];
    uint32_t sb = smem_u32(smem);
    const int tid = threadIdx.x;
    const int wid = tid >> 5;
    const int lane = tid & 31;
    const long z = blockIdx.z;
    Bhi += z * sB;
    Blo += z * sB;
    if (wantF32) C += z * sC;
    if (wantHi) Chi += z * sC;
    if (wantLo) Clo += z * sC;
    const float* res = hasRes ? (resid + z * sC) : nullptr;
    const int row0 = blockIdx.y * BM;
    const int col0 = blockIdx.x * BN;
    const int wm = wid & 1;
    const int wn = wid >> 1;

    float acc[4][4][4];
#pragma unroll
    for (int a = 0; a < 4; a++)
#pragma unroll
        for (int b = 0; b < 4; b++)
#pragma unroll
            for (int c = 0; c < 4; c++) acc[a][b][c] = 0.f;

    const int nc = K / BK;

    auto load_stage = [&](int s, int kt) {
        uint32_t base = sb + s * STAGE_B;
#pragma unroll
        for (int i = 0; i < 8; i++) {
            int idx = i * 256 + tid;
            int mat = idx >> 9;
            if (terms == 2 && mat == 1) continue;
            int rem = idx & 511;
            int r = rem >> 2, c = rem & 3;
            uint32_t sa = base + mat * TILE_B + (uint32_t)(r * LDT + c * 8) * 2;
            const __half* gp;
            if (mat == 0)      gp = Ahi + (long)(row0 + r) * K + kt + c * 8;
            else if (mat == 1) gp = Alo + (long)(row0 + r) * K + kt + c * 8;
            else if (mat == 2) gp = Bhi + (long)(col0 + r) * K + kt + c * 8;
            else               gp = Blo + (long)(col0 + r) * K + kt + c * 8;
            asm volatile("cp.async.cg.shared.global [%0], [%1], 16;"
                         :: "r"(sa), "l"(gp));
        }
        asm volatile("cp.async.commit_group;");
    };

    load_stage(0, 0);

    for (int c = 0; c < nc; c++) {
        int s = c & 1;
        if (c + 1 < nc) {
            load_stage(s ^ 1, (c + 1) * BK);
            asm volatile("cp.async.wait_group 1;");
        } else {
            asm volatile("cp.async.wait_group 0;");
        }
        __syncthreads();
        uint32_t base = sb + s * STAGE_B;
        GEMM_PHASE(base, 0);
        GEMM_PHASE(base, 1);
        __syncthreads();
    }

#pragma unroll
    for (int mt = 0; mt < 4; mt++) {
#pragma unroll
        for (int nt = 0; nt < 4; nt++) {
            int rb = row0 + wm * 64 + mt * 16 + (lane >> 2);
            int cc = col0 + wn * 32 + nt * 8 + (lane & 3) * 2;
            float b0 = 0.f, b1 = 0.f;
            if (hasBias) { b0 = bias[cc]; b1 = bias[cc + 1]; }
#pragma unroll
            for (int hf = 0; hf < 2; hf++) {
                int rr = rb + hf * 8;
                float v0 = acc[mt][nt][hf * 2] + b0;
                float v1 = acc[mt][nt][hf * 2 + 1] + b1;
                if (act == 1) { v0 = gelu_f(v0); v1 = gelu_f(v1); }
                if (hasRes) {
                    v0 += res[(long)rr * N + cc];
                    v1 += res[(long)rr * N + cc + 1];
                }
                long o = (long)rr * N + cc;
                if (wantF32) *(float2*)&C[o] = make_float2(v0, v1);
                if (wantHi) {
                    __half h0 = __float2half_rn(v0), h1 = __float2half_rn(v1);
                    *(__half2*)&Chi[o] = __halves2half2(h0, h1);
                    if (wantLo) {
                        __half l0 = __float2half_rn(v0 - __half2float(h0));
                        __half l1 = __float2half_rn(v1 - __half2float(h1));
                        *(__half2*)&Clo[o] = __halves2half2(l0, l1);
                    }
                }
            }
        }
    }
}

// ================= token-gathered sparse expert GEMM =================
__global__ __launch_bounds__(256, 2) void mma_gather_kernel(
    const __half* __restrict__ Ahi, const __half* __restrict__ Alo,
    const __half* __restrict__ Whi, const __half* __restrict__ Wlo,
    float* __restrict__ PA,
    const int* __restrict__ cnt, const int* __restrict__ eidx, int terms)
{
    const int z = blockIdx.z;
    const int e = z % NEXP;
    const int n = cnt[e];
    const int row0 = blockIdx.y * BM;
    if (row0 >= n) return;

    extern __shared__ char smem[];
    uint32_t sb = smem_u32(smem);
    __shared__ int sidx[BM];
    const int tid = threadIdx.x;
    const int wid = tid >> 5;
    const int lane = tid & 31;
    const __half* Bhi = Whi + (long)z * SZ1M;
    const __half* Blo = Wlo + (long)z * SZ1M;
    float* C = PA + (long)z * Tt * Dm;
    const int col0 = blockIdx.x * BN;
    const int wm = wid & 1;
    const int wn = wid >> 1;
    const int K = Dm;

    if (tid < BM) {
        int rr = row0 + tid;
        sidx[tid] = eidx[(long)e * Tt + (rr < n ? rr : n - 1)];
    }
    __syncthreads();

    float acc[4][4][4];
#pragma unroll
    for (int a = 0; a < 4; a++)
#pragma unroll
        for (int b = 0; b < 4; b++)
#pragma unroll
            for (int c = 0; c < 4; c++) acc[a][b][c] = 0.f;

    const int nc = K / BK;

    auto load_stage = [&](int s, int kt) {
        uint32_t base = sb + s * STAGE_B;
#pragma unroll
        for (int i = 0; i < 8; i++) {
            int idx = i * 256 + tid;
            int mat = idx >> 9;
            if (terms == 2 && mat == 1) continue;
            int rem = idx & 511;
            int r = rem >> 2, c = rem & 3;
            uint32_t sa = base + mat * TILE_B + (uint32_t)(r * LDT + c * 8) * 2;
            const __half* gp;
            if (mat == 0)      gp = Ahi + (long)sidx[r] * K + kt + c * 8;
            else if (mat == 1) gp = Alo + (long)sidx[r] * K + kt + c * 8;
            else if (mat == 2) gp = Bhi + (long)(col0 + r) * K + kt + c * 8;
            else               gp = Blo + (long)(col0 + r) * K + kt + c * 8;
            asm volatile("cp.async.cg.shared.global [%0], [%1], 16;"
                         :: "r"(sa), "l"(gp));
        }
        asm volatile("cp.async.commit_group;");
    };

    load_stage(0, 0);

    for (int c = 0; c < nc; c++) {
        int s = c & 1;
        if (c + 1 < nc) {
            load_stage(s ^ 1, (c + 1) * BK);
            asm volatile("cp.async.wait_group 1;");
        } else {
            asm volatile("cp.async.wait_group 0;");
        }
        __syncthreads();
        uint32_t base = sb + s * STAGE_B;
        GEMM_PHASE(base, 0);
        GEMM_PHASE(base, 1);
        __syncthreads();
    }

#pragma unroll
    for (int mt = 0; mt < 4; mt++) {
#pragma unroll
        for (int nt = 0; nt < 4; nt++) {
            int lr = wm * 64 + mt * 16 + (lane >> 2);
            int cc = col0 + wn * 32 + nt * 8 + (lane & 3) * 2;
#pragma unroll
            for (int hf = 0; hf < 2; hf++) {
                int lrr = lr + hf * 8;
                if (row0 + lrr < n) {
                    long o = (long)sidx[lrr] * Dm + cc;
                    *(float2*)&C[o] = make_float2(acc[mt][nt][hf * 2],
                                                  acc[mt][nt][hf * 2 + 1]);
                }
            }
        }
    }
}

// ================= single-term fp16 HMMA (attention QK^T and P*V) =================
#define HBM 128
#define HBN 64
#define HBK 64
#define LDTH 72
#define H_ATILE (128*LDTH*2)
#define H_BTILE (64*LDTH*2)
#define H_STAGE (H_ATILE + H_BTILE)
#define SMEM_H  (2*H_STAGE)

__global__ __launch_bounds__(256, 2) void mma_h_kernel(
    const __half* __restrict__ A, const __half* __restrict__ B,
    __half* __restrict__ Chi, __half* __restrict__ Clo,
    int K, int lda, int ldb, int ldc, int Hd,
    long sAb, long sAh, long sBb, long sBh, long sCb, long sCh,
    float scale, int wantLo)
{
    extern __shared__ char smem[];
    uint32_t sb = smem_u32(smem);
    const int tid = threadIdx.x;
    const int wid = tid >> 5;
    const int lane = tid & 31;
    const int z = blockIdx.z;
    const int zb = z / Hd, zh = z % Hd;
    A += (long)zb * sAb + (long)zh * sAh;
    B += (long)zb * sBb + (long)zh * sBh;
    Chi += (long)zb * sCb + (long)zh * sCh;
    if (wantLo) Clo += (long)zb * sCb + (long)zh * sCh;
    const int row0 = blockIdx.y * HBM;
    const int col0 = blockIdx.x * HBN;
    const int wm = wid & 1;
    const int wn = wid >> 1;

    float acc[4][2][4];
#pragma unroll
    for (int a = 0; a < 4; a++)
#pragma unroll
        for (int b = 0; b < 2; b++)
#pragma unroll
            for (int c = 0; c < 4; c++) acc[a][b][c] = 0.f;

    const int nc = K / HBK;

    auto load_stage = [&](int s, int kt) {
        uint32_t base = sb + s * H_STAGE;
#pragma unroll
        for (int i = 0; i < 6; i++) {
            int idx = i * 256 + tid;
            if (idx < 1024) {
                int r = idx >> 3, c = idx & 7;
                uint32_t sa = base + (uint32_t)(r * LDTH + c * 8) * 2;
                const __half* gp = A + (long)(row0 + r) * lda + kt + c * 8;
                asm volatile("cp.async.cg.shared.global [%0], [%1], 16;"
                             :: "r"(sa), "l"(gp));
            } else {
                int j = idx - 1024;
                int r = j >> 3, c = j & 7;
                uint32_t sa = base + H_ATILE + (uint32_t)(r * LDTH + c * 8) * 2;
                const __half* gp = B + (long)(col0 + r) * ldb + kt + c * 8;
                asm volatile("cp.async.cg.shared.global [%0], [%1], 16;"
                             :: "r"(sa), "l"(gp));
            }
        }
        asm volatile("cp.async.commit_group;");
    };

    load_stage(0, 0);

    for (int c = 0; c < nc; c++) {
        int s = c & 1;
        if (c + 1 < nc) {
            load_stage(s ^ 1, (c + 1) * HBK);
            asm volatile("cp.async.wait_group 1;");
        } else {
            asm volatile("cp.async.wait_group 0;");
        }
        __syncthreads();

        uint32_t base = sb + s * H_STAGE;
#pragma unroll
        for (int ph = 0; ph < 4; ph++) {
            uint32_t af[4][4], bf[2][2];
#pragma unroll
            for (int mt = 0; mt < 4; mt++) {
                int rr = wm * 64 + mt * 16 + (lane & 15);
                uint32_t co = (uint32_t)(rr * LDTH + ph * 16 + (lane >> 4) * 8) * 2;
                ldmx4(af[mt], base + co);
            }
#pragma unroll
            for (int nt = 0; nt < 2; nt++) {
                int rr = wn * 16 + nt * 8 + (lane & 7);
                uint32_t co = (uint32_t)(rr * LDTH + ph * 16 + ((lane >> 3) & 1) * 8) * 2;
                ldmx2(bf[nt], base + H_ATILE + co);
            }
#pragma unroll
            for (int mt = 0; mt < 4; mt++)
#pragma unroll
                for (int nt = 0; nt < 2; nt++)
                    mma16816(acc[mt][nt], af[mt], bf[nt]);
        }
        __syncthreads();
    }

#pragma unroll
    for (int mt = 0; mt < 4; mt++) {
#pragma unroll
        for (int nt = 0; nt < 2; nt++) {
            int rb = row0 + wm * 64 + mt * 16 + (lane >> 2);
            int cc = col0 + wn * 16 + nt * 8 + (lane & 3) * 2;
#pragma unroll
            for (int hf = 0; hf < 2; hf++) {
                int rr = rb + hf * 8;
                float v0 = acc[mt][nt][hf * 2] * scale;
                float v1 = acc[mt][nt][hf * 2 + 1] * scale;
                __half h0 = __float2half_rn(v0), h1 = __float2half_rn(v1);
                long o = (long)rr * ldc + cc;
                *(__half2*)&Chi[o] = __halves2half2(h0, h1);
                if (wantLo) {
                    __half l0 = __float2half_rn(v0 - __half2float(h0));
                    __half l1 = __float2half_rn(v1 - __half2float(h1));
                    *(__half2*)&Clo[o] = __halves2half2(l0, l1);
                }
            }
        }
    }
}

// ---------------- V transpose ----------------
__global__ __launch_bounds__(256) void vtrans_kernel(const __half* __restrict__ qkvh,
                                                     __half* __restrict__ vt)
{
    __shared__ __half t[32][33];
    int z = blockIdx.z, b = z >> 4, h = z & 15;
    int k0 = blockIdx.x * 32, d0 = blockIdx.y * 32;
    int tx = threadIdx.x & 31, ty = threadIdx.x >> 5;
#pragma unroll
    for (int i = 0; i < 4; i++) {
        int k = k0 + ty + i * 8;
        t[ty + i * 8][tx] = qkvh[(long)(b * Nn + k) * 3072 + 2048 + h * 64 + d0 + tx];
    }
    __syncthreads();
#pragma unroll
    for (int i = 0; i < 4; i++) {
        int d = d0 + ty + i * 8;
        vt[((long)z * 64 + d) * Nn + k0 + tx] = t[tx][ty + i * 8];
    }
}

// ---------------- fp16 softmax ----------------
__global__ __launch_bounds__(256) void softmax_h_kernel(__half* __restrict__ s)
{
    __half2* p = (__half2*)(s + (size_t)blockIdx.x * Nn);
    int tid = threadIdx.x;
    __shared__ float red[256];

    __half2 a = p[tid * 2], b = p[tid * 2 + 1];
    float v[4] = {__low2float(a), __high2float(a), __low2float(b), __high2float(b)};
    float m = fmaxf(fmaxf(v[0], v[1]), fmaxf(v[2], v[3]));
    red[tid] = m; __syncthreads();
    for (int st = 128; st > 0; st >>= 1) {
        if (tid < st) red[tid] = fmaxf(red[tid], red[tid + st]);
        __syncthreads();
    }
    m = red[0]; __syncthreads();

    float sum = 0.f;
#pragma unroll
    for (int i = 0; i < 4; i++) { v[i] = expf(v[i] - m); sum += v[i]; }
    red[tid] = sum; __syncthreads();
    for (int st = 128; st > 0; st >>= 1) {
        if (tid < st) red[tid] += red[tid + st];
        __syncthreads();
    }
    float inv = 1.f / red[0];
    p[tid * 2]     = __halves2half2(__float2half_rn(v[0] * inv), __float2half_rn(v[1] * inv));
    p[tid * 2 + 1] = __halves2half2(__float2half_rn(v[2] * inv), __float2half_rn(v[3] * inv));
}

// ---------------- weight transpose + fp16 split core ----------------
__device__ __forceinline__ void wsplit_tile(const float* __restrict__ Wz,
                                            __half* __restrict__ hi,
                                            __half* __restrict__ lo,
                                            long ob, int K, int N,
                                            int k0, int n0, int tid)
{
    __shared__ float tile[64][65];
#pragma unroll
    for (int i = 0; i < 4; i++) {
        int idx = i * 256 + tid;
        int r = idx >> 4, c4 = idx & 15;
        float4 v = *(const float4*)(Wz + (long)(k0 + r) * N + n0 + c4 * 4);
        tile[r][c4 * 4 + 0] = v.x; tile[r][c4 * 4 + 1] = v.y;
        tile[r][c4 * 4 + 2] = v.z; tile[r][c4 * 4 + 3] = v.w;
    }
    __syncthreads();
#pragma unroll
    for (int i = 0; i < 2; i++) {
        int idx = i * 256 + tid;
        int nn = idx >> 3, kg = idx & 7;
        __half hbuf[8], lbuf[8];
#pragma unroll
        for (int j = 0; j < 8; j++) {
            float v = tile[kg * 8 + j][nn];
            __half h = __float2half_rn(v);
            hbuf[j] = h;
            lbuf[j] = __float2half_rn(v - __half2float(h));
        }
        long o = ob + (long)(n0 + nn) * K + k0 + kg * 8;
        *(uint4*)(hi + o) = *(uint4*)hbuf;
        *(uint4*)(lo + o) = *(uint4*)lbuf;
    }
}

// generic single-tensor wsplit (batched over z with strides)
__global__ __launch_bounds__(256) void wsplit_kernel(
    const float* __restrict__ W, __half* __restrict__ hi, __half* __restrict__ lo,
    int K, int N, long inStride, long outStride)
{
    wsplit_tile(W + blockIdx.z * inStride, hi, lo, (long)blockIdx.z * outStride,
                K, N, blockIdx.y * 64, blockIdx.x * 64, threadIdx.x);
}

// combined Wo/Wb0/Wb1 split: z in [0,6): tensor t=z>>1, layer l=z&1
__global__ __launch_bounds__(256) void wsplit3_kernel(
    const float* __restrict__ W0, const float* __restrict__ W1,
    const float* __restrict__ W2,
    __half* __restrict__ hi, __half* __restrict__ lo)
{
    int z = blockIdx.z;
    int t = z >> 1, l = z & 1;
    const float* src = (t == 0 ? W0 : (t == 1 ? W1 : W2)) + (long)l * SZ1M;
    long off = (t == 0 ? OFF_WO : (t == 1 ? OFF_WB0 : OFF_WB1)) + (long)l * PER_L;
    wsplit_tile(src, hi, lo, off, 1024, 1024,
                blockIdx.y * 64, blockIdx.x * 64, threadIdx.x);
}

// combined expert split: z in [0,28): layer l=z/14, s=z%14; s<7 -> We_p else We_a
__global__ __launch_bounds__(256) void wsplitE_kernel(
    const float* __restrict__ Wp, const float* __restrict__ Wa,
    __half* __restrict__ hi, __half* __restrict__ lo)
{
    int z = blockIdx.z;
    int l = z / 14, s = z % 14;
    const float* src = (s < 7 ? Wp + (long)l * 7 * SZ1M + (long)s * SZ1M
                              : Wa + (long)l * 7 * SZ1M + (long)(s - 7) * SZ1M);
    long off = (long)l * PER_L + OFF_WEP + (long)s * SZ1M;
    wsplit_tile(src, hi, lo, off, 1024, 1024,
                blockIdx.y * 64, blockIdx.x * 64, threadIdx.x);
}

// ---------------- LayerNorm -> fp16 hi(/lo) ----------------
__global__ __launch_bounds__(256) void ln_split_kernel(
    const float* __restrict__ x, const float* __restrict__ g,
    const float* __restrict__ bta,
    __half* __restrict__ hi, __half* __restrict__ lo, int wantLo)
{
    int t = blockIdx.x, tid = threadIdx.x;
    const float* xp = x + (long)t * Dm;
    __shared__ float r1[256], r2[256];

    float v[4], s = 0.f, s2 = 0.f;
#pragma unroll
    for (int i = 0; i < 4; i++) { v[i] = xp[tid + i * 256]; s += v[i]; s2 += v[i] * v[i]; }
    r1[tid] = s; r2[tid] = s2; __syncthreads();
    for (int st = 128; st > 0; st >>= 1) {
        if (tid < st) { r1[tid] += r1[tid + st]; r2[tid] += r2[tid + st]; }
        __syncthreads();
    }
    float mean = r1[0] * (1.f / Dm);
    float var = r2[0] * (1.f / Dm) - mean * mean;
    float rstd = rsqrtf(var + 1e-5f);
#pragma unroll
    for (int i = 0; i < 4; i++) {
        int d = tid + i * 256;
        float y = (v[i] - mean) * rstd * g[d] + bta[d];
        __half h = __float2half_rn(y);
        hi[(long)t * Dm + d] = h;
        if (wantLo) lo[(long)t * Dm + d] = __float2half_rn(y - __half2float(h));
    }
}

// ---------------- reset expert counters ----------------
__global__ void reset_cnt_kernel(int* cnt)
{
    if (threadIdx.x < NEXP) cnt[threadIdx.x] = 0;
}

// ---------------- router (+ expert token gather) ----------------
__global__ __launch_bounds__(128) void router_kernel(const float* __restrict__ x,
                                                     const float* __restrict__ Wr,
                                                     const float* __restrict__ br,
                                                     float* __restrict__ wout,
                                                     int* __restrict__ cnt,
                                                     int* __restrict__ eidx)
{
    int t = blockIdx.x, tid = threadIdx.x;
    __shared__ float part[128][Ee];
    float acc[Ee];
#pragma unroll
    for (int e = 0; e < Ee; e++) acc[e] = 0.f;
    const float* xp = x + (long)t * Dm;
    for (int d = tid; d < Dm; d += 128) {
        float xv = xp[d];
        const float* wrow = Wr + (long)d * Ee;
#pragma unroll
        for (int e = 0; e < Ee; e++) acc[e] += xv * wrow[e];
    }
#pragma unroll
    for (int e = 0; e < Ee; e++) part[tid][e] = acc[e];
    __syncthreads();
    for (int st = 64; st > 0; st >>= 1) {
        if (tid < st)
#pragma unroll
            for (int e = 0; e < Ee; e++) part[tid][e] += part[tid + st][e];
        __syncthreads();
    }
    if (tid == 0) {
        float lg[Ee];
#pragma unroll
        for (int e = 0; e < Ee; e++) lg[e] = part[0][e] + br[e];
        float m1 = -3.4e38f, m2 = -3.4e38f;
#pragma unroll
        for (int e = 0; e < Ee; e++) {
            float v = lg[e];
            if (v > m1) { m2 = m1; m1 = v; }
            else if (v > m2) m2 = v;
        }
        float sum = 0.f, we[Ee];
#pragma unroll
        for (int e = 0; e < Ee; e++) {
            we[e] = (lg[e] < m2) ? 0.f : expf(lg[e] - m1);
            sum += we[e];
        }
        float inv = 1.f / sum;
#pragma unroll
        for (int e = 0; e < Ee; e++) wout[(long)t * Ee + e] = we[e] * inv;
#pragma unroll
        for (int e = 0; e < NEXP; e++) {
            if (we[e + 1] != 0.f) {
                int p = atomicAdd(&cnt[e], 1);
                eidx[(long)e * Tt + p] = t;
            }
        }
    }
}

// ---------------- FiLM ----------------
__global__ __launch_bounds__(256) void film_kernel(float* __restrict__ t0,
                                                   const float* __restrict__ t1,
                                                   const float* __restrict__ b0,
                                                   const float* __restrict__ b1,
                                                   __half* __restrict__ hi,
                                                   __half* __restrict__ lo, int wantLo)
{
    long i = (long)blockIdx.x * 256 + threadIdx.x;
    int d = (int)(i & (Dm - 1));
    float y = gelu_f(t0[i] + b0[d]) * (t1[i] + b1[d]);
    t0[i] = y;
    __half h = __float2half_rn(y);
    hi[i] = h;
    if (wantLo) lo[i] = __float2half_rn(y - __half2float(h));
}

// ---------------- expert mixing ----------------
__global__ __launch_bounds__(256) void mix_kernel(const float* __restrict__ ytf,
                                                  const float* __restrict__ pe,
                                                  const float* __restrict__ ae,
                                                  const float* __restrict__ Pb,
                                                  const float* __restrict__ Ab,
                                                  const float* __restrict__ w,
                                                  __half* __restrict__ hi,
                                                  __half* __restrict__ lo, int wantLo)
{
    int t = blockIdx.x;
    __shared__ float ws[Ee];
    if (threadIdx.x < Ee) ws[threadIdx.x] = w[(long)t * Ee + threadIdx.x];
    __syncthreads();
#pragma unroll
    for (int it = 0; it < 4; it++) {
        int d = threadIdx.x + it * 256;
        long td = (long)t * Dm + d;
        float yv = ytf[td];
        float out = ws[0] * gelu_f(yv);
#pragma unroll
        for (int e = 0; e < NEXP; e++) {
            float we = ws[e + 1];
            if (we != 0.f) {
                float p = pe[(long)e * Tt * Dm + td] + Pb[e * Dm + d];
                float a = ae[(long)e * Tt * Dm + td] + Ab[e * Dm + d];
                out += we * (p * yv + a);
            }
        }
        __half h = __float2half_rn(out);
        hi[td] = h;
        if (wantLo) lo[td] = __float2half_rn(out - __half2float(h));
    }
}

// ---------------- host helpers ----------------
static float* symf(const void* s) { void* p = nullptr; cudaGetSymbolAddress(&p, s); return (float*)p; }
static __half* symh(const void* s) { void* p = nullptr; cudaGetSymbolAddress(&p, s); return (__half*)p; }
static int* symi(const void* s) { void* p = nullptr; cudaGetSymbolAddress(&p, s); return (int*)p; }

static void tgemm(const __half* ahi, const __half* alo,
                  const __half* bhi, const __half* blo,
                  const float* bias, const float* resid,
                  float* C, __half* Chi, __half* Clo,
                  int N, int K, int Z, long sB, long sC, int act, int terms)
{
    dim3 grid(N / BN, Tt / BM, Z);
    mma_gemm_kernel<<<grid, 256, SMEM_MM>>>(ahi, alo, bhi, blo, bias, resid,
                                            C, Chi, Clo, Tt, N, K, sB, sC, act,
                                            bias != nullptr, resid != nullptr,
                                            C != nullptr, Chi != nullptr, Clo != nullptr,
                                            terms);
}

extern "C" void kernel_launch(void* const* d_in, const int* in_sizes, int n_in,
                              void* d_out, int out_size)
{
    const float* x_in  = (const float*)d_in[0];
    const float* ln1_g = (const float*)d_in[1];
    const float* ln1_b = (const float*)d_in[2];
    const float* Wqkv  = (const float*)d_in[3];
    const float* bqkv  = (const float*)d_in[4];
    const float* Wo    = (const float*)d_in[5];
    const float* bo    = (const float*)d_in[6];
    const float* Wr    = (const float*)d_in[7];
    const float* br    = (const float*)d_in[8];
    const float* Wa1   = (const float*)d_in[9];
    const float* ba1   = (const float*)d_in[10];
    const float* Wa2   = (const float*)d_in[11];
    const float* ba2   = (const float*)d_in[12];
    const float* ln2_g = (const float*)d_in[13];
    const float* ln2_b = (const float*)d_in[14];
    const float* Wb0   = (const float*)d_in[15];
    const float* bb0   = (const float*)d_in[16];
    const float* Wb1   = (const float*)d_in[17];
    const float* bb1   = (const float*)d_in[18];
    const float* We_p  = (const float*)d_in[19];
    const float* be_p  = (const float*)d_in[20];
    const float* We_a  = (const float*)d_in[21];
    const float* be_a  = (const float*)d_in[22];

    float* X   = symf(g_x);
    float* T01 = symf(g_t01);
    float* T0  = T01;
    float* T1  = T01 + (long)Tt * Dm;
    float* PA  = symf(g_pa);
    float* Wt  = symf(g_w);
    __half* WHI = symh(g_whi);
    __half* WLO = symh(g_wlo);
    __half* AHI = symh(g_ahi);
    __half* ALO = symh(g_alo);
    __half* MHI = symh(g_mhi);
    __half* MLO = symh(g_mlo);
    __half* QKVH = symh(g_qkvh);
    __half* VT  = symh(g_vt);
    __half* SH  = symh(g_sh);
    int* CNT = symi(g_cnt);
    int* EIDX = symi(g_eidx);

    cudaFuncSetAttribute(mma_gemm_kernel,
                         cudaFuncAttributeMaxDynamicSharedMemorySize, SMEM_MM);
    cudaFuncSetAttribute(mma_gather_kernel,
                         cudaFuncAttributeMaxDynamicSharedMemorySize, SMEM_MM);
    cudaFuncSetAttribute(mma_h_kernel,
                         cudaFuncAttributeMaxDynamicSharedMemorySize, SMEM_H);

    // ---- weight transpose + split (5 launches) ----
    {
        dim3 g1(3072 / 64, 1024 / 64, Lnum);
        wsplit_kernel<<<g1, 256>>>(Wqkv, WHI + OFF_QKV, WLO + OFF_QKV,
                                   1024, 3072, 3072L * 1024, PER_L);
        dim3 g2(16, 16, 6);
        wsplit3_kernel<<<g2, 256>>>(Wo, Wb0, Wb1, WHI, WLO);
        dim3 g3(16, 16, 28);
        wsplitE_kernel<<<g3, 256>>>(We_p, We_a, WHI, WLO);
        dim3 g4(4096 / 64, 1024 / 64, Lnum);
        wsplit_kernel<<<g4, 256>>>(Wa1, WHI + OFF_WA1, WLO + OFF_WA1,
                                   1024, 4096, 4096L * 1024, PER_L);
        dim3 g5(1024 / 64, 4096 / 64, Lnum);
        wsplit_kernel<<<g5, 256>>>(Wa2, WHI + OFF_WA2, WLO + OFF_WA2,
                                   4096, 1024, 4096L * 1024, PER_L);
    }

    cudaMemcpyAsync(X, x_in, (size_t)Tt * Dm * sizeof(float),
                    cudaMemcpyDeviceToDevice, 0);

    for (int l = 0; l < Lnum; l++) {
        const __half* whl = WHI + (long)l * PER_L;
        const __half* wll = WLO + (long)l * PER_L;
        const int tpost = (l == Lnum - 1) ? 2 : 3;
        const int loPost = (tpost == 3) ? 1 : 0;

        // --- attention (QKV 2-term: output is fp16 anyway) ---
        ln_split_kernel<<<Tt, 256>>>(X, ln1_g + l * Dm, ln1_b + l * Dm, AHI, ALO, 0);
        tgemm(AHI, ALO, whl + OFF_QKV, wll + OFF_QKV,
              bqkv + (long)l * 3 * INNERd, nullptr,
              nullptr, QKVH, nullptr, 3 * INNERd, Dm, 1, 0, 0, 0, 2);

        {
            dim3 grid(Nn / 32, DHh / 32, Bb * Hh);
            vtrans_kernel<<<grid, 256>>>(QKVH, VT);
        }
        {
            dim3 grid(Nn / HBN, Nn / HBM, Bb * Hh);
            mma_h_kernel<<<grid, 256, SMEM_H>>>(
                QKVH, QKVH + INNERd, SH, nullptr,
                DHh, 3 * INNERd, 3 * INNERd, Nn, Hh,
                (long)Nn * 3 * INNERd, DHh,
                (long)Nn * 3 * INNERd, DHh,
                (long)Hh * Nn * Nn, (long)Nn * Nn,
                0.125f, 0);
        }
        softmax_h_kernel<<<Bb * Hh * Nn, 256>>>(SH);
        {
            dim3 grid(1, Nn / HBM, Bb * Hh);
            mma_h_kernel<<<grid, 256, SMEM_H>>>(
                SH, VT, AHI, ALO,
                Nn, Nn, Nn, INNERd, Hh,
                (long)Hh * Nn * Nn, (long)Nn * Nn,
                (long)Hh * DHh * Nn, (long)DHh * Nn,
                (long)Nn * INNERd, DHh,
                1.0f, 1);
        }
        tgemm(AHI, ALO, whl + OFF_WO, wll + OFF_WO,
              bo + (long)l * Dm, X, X, nullptr, nullptr, Dm, INNERd, 1, 0, 0, 0, 3);

        // --- router + expert gather ---
        reset_cnt_kernel<<<1, 32>>>(CNT);
        router_kernel<<<Tt, 128>>>(X, Wr + (long)l * Dm * Ee, br + (long)l * Ee,
                                   Wt + (long)l * Tt * Ee, CNT, EIDX);

        // --- FiLM trunk ---
        ln_split_kernel<<<Tt, 256>>>(X, ln2_g + l * Dm, ln2_b + l * Dm, AHI, ALO, loPost);
        tgemm(AHI, ALO, whl + OFF_WB0, wll + OFF_WB0,
              nullptr, nullptr, T01, nullptr, nullptr,
              Dm, Dm, 2, SZ1M, (long)Tt * Dm, 0, tpost);
        film_kernel<<<(Tt * Dm) / 256, 256>>>(T0, T1, bb0 + (long)l * Dm,
                                              bb1 + (long)l * Dm, AHI, ALO, loPost);

        // --- sparse gathered expert GEMMs ---
        {
            dim3 grid(Dm / BN, Tt / BM, 2 * NEXP);
            mma_gather_kernel<<<grid, 256, SMEM_MM>>>(
                AHI, ALO, whl + OFF_WEP, wll + OFF_WEP, PA, CNT, EIDX, tpost);
        }

        // --- mix -> hi(/lo) ---
        mix_kernel<<<Tt, 256>>>(T0, PA, PA + (long)NEXP * Tt * Dm,
                                be_p + (long)l * NEXP * Dm,
                                be_a + (long)l * NEXP * Dm,
                                Wt + (long)l * Tt * Ee, AHI, ALO, loPost);

        // --- adaptor MLP + residual ---
        tgemm(AHI, ALO, whl + OFF_WA1, wll + OFF_WA1,
              ba1 + (long)l * MLPd, nullptr,
              nullptr, MHI, (loPost ? MLO : nullptr), MLPd, Dm, 1, 0, 0, 1, tpost);
        tgemm(MHI, MLO, whl + OFF_WA2, wll + OFF_WA2,
              ba2 + (long)l * Dm, X, X, nullptr, nullptr, Dm, MLPd, 1, 0, 0, 0, tpost);
    }

    // outputs: x [B,N,D] then stacked router weights [L,B,N,E]
    cudaMemcpyAsync(d_out, X, (size_t)Tt * Dm * sizeof(float),
                    cudaMemcpyDeviceToDevice, 0);
    if (out_size >= Tt * Dm + Lnum * Tt * Ee) {
        cudaMemcpyAsync((float*)d_out + (size_t)Tt * Dm, Wt,
                        (size_t)Lnum * Tt * Ee * sizeof(float),
                        cudaMemcpyDeviceToDevice, 0);
    }
}

// round 11
// speedup vs baseline: 4.2460x; 1.0312x over previous
#include <cuda_runtime.h>
#include <cuda_fp16.h>
#include <cstdint>
#include <math.h>

// ---------------- problem constants ----------------
#define Dm     1024
#define Lnum   2
#define Hh     16
#define DHh    64
#define INNERd 1024
#define MLPd   4096
#define Ee     8
#define Bb     4
#define Nn     1024
#define Tt     (Bb*Nn)
#define NEXP   (Ee-1)

// weight pack offsets (elements, per layer)
#define SZ1M   (1024L*1024L)
#define OFF_QKV 0L
#define OFF_WO  (OFF_QKV + 3072L*1024L)
#define OFF_WB0 (OFF_WO  + SZ1M)
#define OFF_WB1 (OFF_WB0 + SZ1M)
#define OFF_WEP (OFF_WB1 + SZ1M)
#define OFF_WEA (OFF_WEP + 7L*SZ1M)
#define OFF_WA1 (OFF_WEA + 7L*SZ1M)
#define OFF_WA2 (OFF_WA1 + 4096L*1024L)
#define PER_L   (OFF_WA2 + 4096L*1024L)

// ---------------- scratch (device globals) ----------------
__device__ float g_x[Tt*Dm];
__device__ float g_t01[2L*Tt*Dm];
__device__ __half g_pa[(size_t)2*NEXP*Tt*Dm];     // fp16 expert outputs
__device__ float g_w[Lnum*Tt*Ee];
__device__ __half g_whi[2L*PER_L];
__device__ __half g_wlo[2L*PER_L];
__device__ __half g_ahi[(size_t)Tt*Dm];
__device__ __half g_alo[(size_t)Tt*Dm];
__device__ __half g_mhi[(size_t)Tt*MLPd];
__device__ __half g_mlo[(size_t)Tt*MLPd];
__device__ __half g_qkvh[(size_t)Tt*3*INNERd];
__device__ __half g_vt[(size_t)Bb*Hh*DHh*Nn];
__device__ __half g_sh[(size_t)Bb*Hh*Nn*Nn];
__device__ int g_cnt[NEXP];
__device__ int g_eidx[(size_t)NEXP*Tt];

__device__ __forceinline__ float gelu_f(float v) {
    return 0.5f * v * (1.0f + erff(v * 0.7071067811865475f));
}

__device__ __forceinline__ uint32_t smem_u32(const void* p) {
    uint32_t a;
    asm("{ .reg .u64 t; cvta.to.shared.u64 t, %1; cvt.u32.u64 %0, t; }"
        : "=r"(a) : "l"(p));
    return a;
}
__device__ __forceinline__ void ldmx4(uint32_t* r, uint32_t addr) {
    asm volatile("ldmatrix.sync.aligned.m8n8.x4.shared.b16 {%0,%1,%2,%3}, [%4];"
        : "=r"(r[0]), "=r"(r[1]), "=r"(r[2]), "=r"(r[3]) : "r"(addr));
}
__device__ __forceinline__ void ldmx2(uint32_t* r, uint32_t addr) {
    asm volatile("ldmatrix.sync.aligned.m8n8.x2.shared.b16 {%0,%1}, [%2];"
        : "=r"(r[0]), "=r"(r[1]) : "r"(addr));
}
__device__ __forceinline__ void mma16816(float* d, const uint32_t* a, const uint32_t* b) {
    asm volatile("mma.sync.aligned.m16n8k16.row.col.f32.f16.f16.f32 "
        "{%0,%1,%2,%3}, {%4,%5,%6,%7}, {%8,%9}, {%0,%1,%2,%3};"
        : "+f"(d[0]), "+f"(d[1]), "+f"(d[2]), "+f"(d[3])
        : "r"(a[0]), "r"(a[1]), "r"(a[2]), "r"(a[3]), "r"(b[0]), "r"(b[1]));
}

// ================= split HMMA GEMM (2 or 3 terms), 2-stage, 2 CTAs/SM =================
#define BM 128
#define BN 128
#define BK 32
#define LDT 40
#define TILE_B (128*LDT*2)
#define ST_AHI 0
#define ST_ALO (1*TILE_B)
#define ST_BHI (2*TILE_B)
#define ST_BLO (3*TILE_B)
#define STAGE_B (4*TILE_B)
#define SMEM_MM (2*STAGE_B)

#define GEMM_PHASE(base, ph)                                                      \
    do {                                                                          \
        uint32_t bhi[4][2], blo[4][2], af[4][4];                                  \
        _Pragma("unroll")                                                         \
        for (int nt = 0; nt < 4; nt++) {                                          \
            int rr = wn * 32 + nt * 8 + (lane & 7);                               \
            uint32_t co = (uint32_t)(rr * LDT + (ph) * 16 + ((lane >> 3) & 1) * 8) * 2; \
            ldmx2(bhi[nt], (base) + ST_BHI + co);                                 \
            ldmx2(blo[nt], (base) + ST_BLO + co);                                 \
        }                                                                         \
        _Pragma("unroll")                                                         \
        for (int mt = 0; mt < 4; mt++) {                                          \
            int rr = wm * 64 + mt * 16 + (lane & 15);                             \
            uint32_t co = (uint32_t)(rr * LDT + (ph) * 16 + (lane >> 4) * 8) * 2; \
            ldmx4(af[mt], (base) + ST_AHI + co);                                  \
        }                                                                         \
        _Pragma("unroll")                                                         \
        for (int mt = 0; mt < 4; mt++)                                            \
            _Pragma("unroll")                                                     \
            for (int nt = 0; nt < 4; nt++) {                                      \
                mma16816(acc[mt][nt], af[mt], bhi[nt]);                           \
                mma16816(acc[mt][nt], af[mt], blo[nt]);                           \
            }                                                                     \
        if (terms == 3) {                                                         \
            _Pragma("unroll")                                                     \
            for (int mt = 0; mt < 4; mt++) {                                      \
                int rr = wm * 64 + mt * 16 + (lane & 15);                         \
                uint32_t co = (uint32_t)(rr * LDT + (ph) * 16 + (lane >> 4) * 8) * 2; \
                ldmx4(af[mt], (base) + ST_ALO + co);                              \
            }                                                                     \
            _Pragma("unroll")                                                     \
            for (int mt = 0; mt < 4; mt++)                                        \
                _Pragma("unroll")                                                 \
                for (int nt = 0; nt < 4; nt++)                                    \
                    mma16816(acc[mt][nt], af[mt], bhi[nt]);                       \
        }                                                                         \
    } while (0)

__global__ __launch_bounds__(256, 2) void mma_gemm_kernel(
    const __half* __restrict__ Ahi, const __half* __restrict__ Alo,
    const __half* __restrict__ Bhi, const __half* __restrict__ Blo,
    const float* __restrict__ bias, const float* __restrict__ resid,
    float* __restrict__ C, __half* __restrict__ Chi, __half* __restrict__ Clo,
    int M, int N, int K, long sB, long sC, int act,
    int hasBias, int hasRes, int wantF32, int wantHi, int wantLo, int terms)
{
    extern __shared__ char smem[];
    uint32_t sb = smem_u32(smem);
    const int tid = threadIdx.x;
    const int wid = tid >> 5;
    const int lane = tid & 31;
    const long z = blockIdx.z;
    Bhi += z * sB;
    Blo += z * sB;
    if (wantF32) C += z * sC;
    if (wantHi) Chi += z * sC;
    if (wantLo) Clo += z * sC;
    const float* res = hasRes ? (resid + z * sC) : nullptr;
    const int row0 = blockIdx.y * BM;
    const int col0 = blockIdx.x * BN;
    const int wm = wid & 1;
    const int wn = wid >> 1;

    float acc[4][4][4];
#pragma unroll
    for (int a = 0; a < 4; a++)
#pragma unroll
        for (int b = 0; b < 4; b++)
#pragma unroll
            for (int c = 0; c < 4; c++) acc[a][b][c] = 0.f;

    const int nc = K / BK;

    auto load_stage = [&](int s, int kt) {
        uint32_t base = sb + s * STAGE_B;
#pragma unroll
        for (int i = 0; i < 8; i++) {
            int idx = i * 256 + tid;
            int mat = idx >> 9;
            if (terms == 2 && mat == 1) continue;
            int rem = idx & 511;
            int r = rem >> 2, c = rem & 3;
            uint32_t sa = base + mat * TILE_B + (uint32_t)(r * LDT + c * 8) * 2;
            const __half* gp;
            if (mat == 0)      gp = Ahi + (long)(row0 + r) * K + kt + c * 8;
            else if (mat == 1) gp = Alo + (long)(row0 + r) * K + kt + c * 8;
            else if (mat == 2) gp = Bhi + (long)(col0 + r) * K + kt + c * 8;
            else               gp = Blo + (long)(col0 + r) * K + kt + c * 8;
            asm volatile("cp.async.cg.shared.global [%0], [%1], 16;"
                         :: "r"(sa), "l"(gp));
        }
        asm volatile("cp.async.commit_group;");
    };

    load_stage(0, 0);

    for (int c = 0; c < nc; c++) {
        int s = c & 1;
        if (c + 1 < nc) {
            load_stage(s ^ 1, (c + 1) * BK);
            asm volatile("cp.async.wait_group 1;");
        } else {
            asm volatile("cp.async.wait_group 0;");
        }
        __syncthreads();
        uint32_t base = sb + s * STAGE_B;
        GEMM_PHASE(base, 0);
        GEMM_PHASE(base, 1);
        __syncthreads();
    }

#pragma unroll
    for (int mt = 0; mt < 4; mt++) {
#pragma unroll
        for (int nt = 0; nt < 4; nt++) {
            int rb = row0 + wm * 64 + mt * 16 + (lane >> 2);
            int cc = col0 + wn * 32 + nt * 8 + (lane & 3) * 2;
            float b0 = 0.f, b1 = 0.f;
            if (hasBias) { b0 = bias[cc]; b1 = bias[cc + 1]; }
#pragma unroll
            for (int hf = 0; hf < 2; hf++) {
                int rr = rb + hf * 8;
                float v0 = acc[mt][nt][hf * 2] + b0;
                float v1 = acc[mt][nt][hf * 2 + 1] + b1;
                if (act == 1) { v0 = gelu_f(v0); v1 = gelu_f(v1); }
                if (hasRes) {
                    v0 += res[(long)rr * N + cc];
                    v1 += res[(long)rr * N + cc + 1];
                }
                long o = (long)rr * N + cc;
                if (wantF32) *(float2*)&C[o] = make_float2(v0, v1);
                if (wantHi) {
                    __half h0 = __float2half_rn(v0), h1 = __float2half_rn(v1);
                    *(__half2*)&Chi[o] = __halves2half2(h0, h1);
                    if (wantLo) {
                        __half l0 = __float2half_rn(v0 - __half2float(h0));
                        __half l1 = __float2half_rn(v1 - __half2float(h1));
                        *(__half2*)&Clo[o] = __halves2half2(l0, l1);
                    }
                }
            }
        }
    }
}

// ================= token-gathered sparse expert GEMM (fp16 output) =================
__global__ __launch_bounds__(256, 2) void mma_gather_kernel(
    const __half* __restrict__ Ahi, const __half* __restrict__ Alo,
    const __half* __restrict__ Whi, const __half* __restrict__ Wlo,
    __half* __restrict__ PA,
    const int* __restrict__ cnt, const int* __restrict__ eidx, int terms)
{
    const int z = blockIdx.z;
    const int e = z % NEXP;
    const int n = cnt[e];
    const int row0 = blockIdx.y * BM;
    if (row0 >= n) return;

    extern __shared__ char smem[];
    uint32_t sb = smem_u32(smem);
    __shared__ int sidx[BM];
    const int tid = threadIdx.x;
    const int wid = tid >> 5;
    const int lane = tid & 31;
    const __half* Bhi = Whi + (long)z * SZ1M;
    const __half* Blo = Wlo + (long)z * SZ1M;
    __half* C = PA + (long)z * Tt * Dm;
    const int col0 = blockIdx.x * BN;
    const int wm = wid & 1;
    const int wn = wid >> 1;
    const int K = Dm;

    if (tid < BM) {
        int rr = row0 + tid;
        sidx[tid] = eidx[(long)e * Tt + (rr < n ? rr : n - 1)];
    }
    __syncthreads();

    float acc[4][4][4];
#pragma unroll
    for (int a = 0; a < 4; a++)
#pragma unroll
        for (int b = 0; b < 4; b++)
#pragma unroll
            for (int c = 0; c < 4; c++) acc[a][b][c] = 0.f;

    const int nc = K / BK;

    auto load_stage = [&](int s, int kt) {
        uint32_t base = sb + s * STAGE_B;
#pragma unroll
        for (int i = 0; i < 8; i++) {
            int idx = i * 256 + tid;
            int mat = idx >> 9;
            if (terms == 2 && mat == 1) continue;
            int rem = idx & 511;
            int r = rem >> 2, c = rem & 3;
            uint32_t sa = base + mat * TILE_B + (uint32_t)(r * LDT + c * 8) * 2;
            const __half* gp;
            if (mat == 0)      gp = Ahi + (long)sidx[r] * K + kt + c * 8;
            else if (mat == 1) gp = Alo + (long)sidx[r] * K + kt + c * 8;
            else if (mat == 2) gp = Bhi + (long)(col0 + r) * K + kt + c * 8;
            else               gp = Blo + (long)(col0 + r) * K + kt + c * 8;
            asm volatile("cp.async.cg.shared.global [%0], [%1], 16;"
                         :: "r"(sa), "l"(gp));
        }
        asm volatile("cp.async.commit_group;");
    };

    load_stage(0, 0);

    for (int c = 0; c < nc; c++) {
        int s = c & 1;
        if (c + 1 < nc) {
            load_stage(s ^ 1, (c + 1) * BK);
            asm volatile("cp.async.wait_group 1;");
        } else {
            asm volatile("cp.async.wait_group 0;");
        }
        __syncthreads();
        uint32_t base = sb + s * STAGE_B;
        GEMM_PHASE(base, 0);
        GEMM_PHASE(base, 1);
        __syncthreads();
    }

#pragma unroll
    for (int mt = 0; mt < 4; mt++) {
#pragma unroll
        for (int nt = 0; nt < 4; nt++) {
            int lr = wm * 64 + mt * 16 + (lane >> 2);
            int cc = col0 + wn * 32 + nt * 8 + (lane & 3) * 2;
#pragma unroll
            for (int hf = 0; hf < 2; hf++) {
                int lrr = lr + hf * 8;
                if (row0 + lrr < n) {
                    long o = (long)sidx[lrr] * Dm + cc;
                    *(__half2*)&C[o] = __halves2half2(
                        __float2half_rn(acc[mt][nt][hf * 2]),
                        __float2half_rn(acc[mt][nt][hf * 2 + 1]));
                }
            }
        }
    }
}

// ================= single-term fp16 HMMA (attention QK^T and P*V) =================
#define HBM 128
#define HBN 64
#define HBK 64
#define LDTH 72
#define H_ATILE (128*LDTH*2)
#define H_BTILE (64*LDTH*2)
#define H_STAGE (H_ATILE + H_BTILE)
#define SMEM_H  (2*H_STAGE)

__global__ __launch_bounds__(256, 2) void mma_h_kernel(
    const __half* __restrict__ A, const __half* __restrict__ B,
    __half* __restrict__ Chi, __half* __restrict__ Clo,
    int K, int lda, int ldb, int ldc, int Hd,
    long sAb, long sAh, long sBb, long sBh, long sCb, long sCh,
    float scale, int wantLo)
{
    extern __shared__ char smem[];
    uint32_t sb = smem_u32(smem);
    const int tid = threadIdx.x;
    const int wid = tid >> 5;
    const int lane = tid & 31;
    const int z = blockIdx.z;
    const int zb = z / Hd, zh = z % Hd;
    A += (long)zb * sAb + (long)zh * sAh;
    B += (long)zb * sBb + (long)zh * sBh;
    Chi += (long)zb * sCb + (long)zh * sCh;
    if (wantLo) Clo += (long)zb * sCb + (long)zh * sCh;
    const int row0 = blockIdx.y * HBM;
    const int col0 = blockIdx.x * HBN;
    const int wm = wid & 1;
    const int wn = wid >> 1;

    float acc[4][2][4];
#pragma unroll
    for (int a = 0; a < 4; a++)
#pragma unroll
        for (int b = 0; b < 2; b++)
#pragma unroll
            for (int c = 0; c < 4; c++) acc[a][b][c] = 0.f;

    const int nc = K / HBK;

    auto load_stage = [&](int s, int kt) {
        uint32_t base = sb + s * H_STAGE;
#pragma unroll
        for (int i = 0; i < 6; i++) {
            int idx = i * 256 + tid;
            if (idx < 1024) {
                int r = idx >> 3, c = idx & 7;
                uint32_t sa = base + (uint32_t)(r * LDTH + c * 8) * 2;
                const __half* gp = A + (long)(row0 + r) * lda + kt + c * 8;
                asm volatile("cp.async.cg.shared.global [%0], [%1], 16;"
                             :: "r"(sa), "l"(gp));
            } else {
                int j = idx - 1024;
                int r = j >> 3, c = j & 7;
                uint32_t sa = base + H_ATILE + (uint32_t)(r * LDTH + c * 8) * 2;
                const __half* gp = B + (long)(col0 + r) * ldb + kt + c * 8;
                asm volatile("cp.async.cg.shared.global [%0], [%1], 16;"
                             :: "r"(sa), "l"(gp));
            }
        }
        asm volatile("cp.async.commit_group;");
    };

    load_stage(0, 0);

    for (int c = 0; c < nc; c++) {
        int s = c & 1;
        if (c + 1 < nc) {
            load_stage(s ^ 1, (c + 1) * HBK);
            asm volatile("cp.async.wait_group 1;");
        } else {
            asm volatile("cp.async.wait_group 0;");
        }
        __syncthreads();

        uint32_t base = sb + s * H_STAGE;
#pragma unroll
        for (int ph = 0; ph < 4; ph++) {
            uint32_t af[4][4], bf[2][2];
#pragma unroll
            for (int mt = 0; mt < 4; mt++) {
                int rr = wm * 64 + mt * 16 + (lane & 15);
                uint32_t co = (uint32_t)(rr * LDTH + ph * 16 + (lane >> 4) * 8) * 2;
                ldmx4(af[mt], base + co);
            }
#pragma unroll
            for (int nt = 0; nt < 2; nt++) {
                int rr = wn * 16 + nt * 8 + (lane & 7);
                uint32_t co = (uint32_t)(rr * LDTH + ph * 16 + ((lane >> 3) & 1) * 8) * 2;
                ldmx2(bf[nt], base + H_ATILE + co);
            }
#pragma unroll
            for (int mt = 0; mt < 4; mt++)
#pragma unroll
                for (int nt = 0; nt < 2; nt++)
                    mma16816(acc[mt][nt], af[mt], bf[nt]);
        }
        __syncthreads();
    }

#pragma unroll
    for (int mt = 0; mt < 4; mt++) {
#pragma unroll
        for (int nt = 0; nt < 2; nt++) {
            int rb = row0 + wm * 64 + mt * 16 + (lane >> 2);
            int cc = col0 + wn * 16 + nt * 8 + (lane & 3) * 2;
#pragma unroll
            for (int hf = 0; hf < 2; hf++) {
                int rr = rb + hf * 8;
                float v0 = acc[mt][nt][hf * 2] * scale;
                float v1 = acc[mt][nt][hf * 2 + 1] * scale;
                __half h0 = __float2half_rn(v0), h1 = __float2half_rn(v1);
                long o = (long)rr * ldc + cc;
                *(__half2*)&Chi[o] = __halves2half2(h0, h1);
                if (wantLo) {
                    __half l0 = __float2half_rn(v0 - __half2float(h0));
                    __half l1 = __float2half_rn(v1 - __half2float(h1));
                    *(__half2*)&Clo[o] = __halves2half2(l0, l1);
                }
            }
        }
    }
}

// ---------------- V transpose ----------------
__global__ __launch_bounds__(256) void vtrans_kernel(const __half* __restrict__ qkvh,
                                                     __half* __restrict__ vt)
{
    __shared__ __half t[32][33];
    int z = blockIdx.z, b = z >> 4, h = z & 15;
    int k0 = blockIdx.x * 32, d0 = blockIdx.y * 32;
    int tx = threadIdx.x & 31, ty = threadIdx.x >> 5;
#pragma unroll
    for (int i = 0; i < 4; i++) {
        int k = k0 + ty + i * 8;
        t[ty + i * 8][tx] = qkvh[(long)(b * Nn + k) * 3072 + 2048 + h * 64 + d0 + tx];
    }
    __syncthreads();
#pragma unroll
    for (int i = 0; i < 4; i++) {
        int d = d0 + ty + i * 8;
        vt[((long)z * 64 + d) * Nn + k0 + tx] = t[tx][ty + i * 8];
    }
}

// ---------------- fp16 softmax (warp-shuffle reductions) ----------------
__global__ __launch_bounds__(256) void softmax_h_kernel(__half* __restrict__ s)
{
    __half2* p = (__half2*)(s + (size_t)blockIdx.x * Nn);
    int tid = threadIdx.x;
    int lane = tid & 31, wid = tid >> 5;
    __shared__ float red[8];

    __half2 a = p[tid * 2], b = p[tid * 2 + 1];
    float v[4] = {__low2float(a), __high2float(a), __low2float(b), __high2float(b)};
    float m = fmaxf(fmaxf(v[0], v[1]), fmaxf(v[2], v[3]));
#pragma unroll
    for (int o = 16; o > 0; o >>= 1)
        m = fmaxf(m, __shfl_xor_sync(0xffffffff, m, o));
    if (lane == 0) red[wid] = m;
    __syncthreads();
    {
        float t = red[lane & 7];
#pragma unroll
        for (int o = 4; o > 0; o >>= 1)
            t = fmaxf(t, __shfl_xor_sync(0xffffffff, t, o));
        m = t;
    }
    m = __shfl_sync(0xffffffff, m, 0);

    float sum = 0.f;
#pragma unroll
    for (int i = 0; i < 4; i++) { v[i] = expf(v[i] - m); sum += v[i]; }
#pragma unroll
    for (int o = 16; o > 0; o >>= 1)
        sum += __shfl_xor_sync(0xffffffff, sum, o);
    __syncthreads();
    if (lane == 0) red[wid] = sum;
    __syncthreads();
    {
        float t = red[lane & 7];
#pragma unroll
        for (int o = 4; o > 0; o >>= 1)
            t += __shfl_xor_sync(0xffffffff, t, o);
        sum = t;
    }
    sum = __shfl_sync(0xffffffff, sum, 0);

    float inv = 1.f / sum;
    p[tid * 2]     = __halves2half2(__float2half_rn(v[0] * inv), __float2half_rn(v[1] * inv));
    p[tid * 2 + 1] = __halves2half2(__float2half_rn(v[2] * inv), __float2half_rn(v[3] * inv));
}

// ---------------- weight transpose + fp16 split core ----------------
__device__ __forceinline__ void wsplit_tile(const float* __restrict__ Wz,
                                            __half* __restrict__ hi,
                                            __half* __restrict__ lo,
                                            long ob, int K, int N,
                                            int k0, int n0, int tid)
{
    __shared__ float tile[64][65];
#pragma unroll
    for (int i = 0; i < 4; i++) {
        int idx = i * 256 + tid;
        int r = idx >> 4, c4 = idx & 15;
        float4 v = *(const float4*)(Wz + (long)(k0 + r) * N + n0 + c4 * 4);
        tile[r][c4 * 4 + 0] = v.x; tile[r][c4 * 4 + 1] = v.y;
        tile[r][c4 * 4 + 2] = v.z; tile[r][c4 * 4 + 3] = v.w;
    }
    __syncthreads();
#pragma unroll
    for (int i = 0; i < 2; i++) {
        int idx = i * 256 + tid;
        int nn = idx >> 3, kg = idx & 7;
        __half hbuf[8], lbuf[8];
#pragma unroll
        for (int j = 0; j < 8; j++) {
            float v = tile[kg * 8 + j][nn];
            __half h = __float2half_rn(v);
            hbuf[j] = h;
            lbuf[j] = __float2half_rn(v - __half2float(h));
        }
        long o = ob + (long)(n0 + nn) * K + k0 + kg * 8;
        *(uint4*)(hi + o) = *(uint4*)hbuf;
        *(uint4*)(lo + o) = *(uint4*)lbuf;
    }
}

__global__ __launch_bounds__(256) void wsplit_kernel(
    const float* __restrict__ W, __half* __restrict__ hi, __half* __restrict__ lo,
    int K, int N, long inStride, long outStride)
{
    wsplit_tile(W + blockIdx.z * inStride, hi, lo, (long)blockIdx.z * outStride,
                K, N, blockIdx.y * 64, blockIdx.x * 64, threadIdx.x);
}

__global__ __launch_bounds__(256) void wsplit3_kernel(
    const float* __restrict__ W0, const float* __restrict__ W1,
    const float* __restrict__ W2,
    __half* __restrict__ hi, __half* __restrict__ lo)
{
    int z = blockIdx.z;
    int t = z >> 1, l = z & 1;
    const float* src = (t == 0 ? W0 : (t == 1 ? W1 : W2)) + (long)l * SZ1M;
    long off = (t == 0 ? OFF_WO : (t == 1 ? OFF_WB0 : OFF_WB1)) + (long)l * PER_L;
    wsplit_tile(src, hi, lo, off, 1024, 1024,
                blockIdx.y * 64, blockIdx.x * 64, threadIdx.x);
}

__global__ __launch_bounds__(256) void wsplitE_kernel(
    const float* __restrict__ Wp, const float* __restrict__ Wa,
    __half* __restrict__ hi, __half* __restrict__ lo)
{
    int z = blockIdx.z;
    int l = z / 14, s = z % 14;
    const float* src = (s < 7 ? Wp + (long)l * 7 * SZ1M + (long)s * SZ1M
                              : Wa + (long)l * 7 * SZ1M + (long)(s - 7) * SZ1M);
    long off = (long)l * PER_L + OFF_WEP + (long)s * SZ1M;
    wsplit_tile(src, hi, lo, off, 1024, 1024,
                blockIdx.y * 64, blockIdx.x * 64, threadIdx.x);
}

// ---------------- LayerNorm -> fp16 hi(/lo) ----------------
__global__ __launch_bounds__(256) void ln_split_kernel(
    const float* __restrict__ x, const float* __restrict__ g,
    const float* __restrict__ bta,
    __half* __restrict__ hi, __half* __restrict__ lo, int wantLo)
{
    int t = blockIdx.x, tid = threadIdx.x;
    const float* xp = x + (long)t * Dm;
    __shared__ float r1[256], r2[256];

    float v[4], s = 0.f, s2 = 0.f;
#pragma unroll
    for (int i = 0; i < 4; i++) { v[i] = xp[tid + i * 256]; s += v[i]; s2 += v[i] * v[i]; }
    r1[tid] = s; r2[tid] = s2; __syncthreads();
    for (int st = 128; st > 0; st >>= 1) {
        if (tid < st) { r1[tid] += r1[tid + st]; r2[tid] += r2[tid + st]; }
        __syncthreads();
    }
    float mean = r1[0] * (1.f / Dm);
    float var = r2[0] * (1.f / Dm) - mean * mean;
    float rstd = rsqrtf(var + 1e-5f);
#pragma unroll
    for (int i = 0; i < 4; i++) {
        int d = tid + i * 256;
        float y = (v[i] - mean) * rstd * g[d] + bta[d];
        __half h = __float2half_rn(y);
        hi[(long)t * Dm + d] = h;
        if (wantLo) lo[(long)t * Dm + d] = __float2half_rn(y - __half2float(h));
    }
}

// ---------------- reset expert counters ----------------
__global__ void reset_cnt_kernel(int* cnt)
{
    if (threadIdx.x < NEXP) cnt[threadIdx.x] = 0;
}

// ---------------- router (+ expert token gather) ----------------
__global__ __launch_bounds__(128) void router_kernel(const float* __restrict__ x,
                                                     const float* __restrict__ Wr,
                                                     const float* __restrict__ br,
                                                     float* __restrict__ wout,
                                                     int* __restrict__ cnt,
                                                     int* __restrict__ eidx)
{
    int t = blockIdx.x, tid = threadIdx.x;
    __shared__ float part[128][Ee];
    float acc[Ee];
#pragma unroll
    for (int e = 0; e < Ee; e++) acc[e] = 0.f;
    const float* xp = x + (long)t * Dm;
    for (int d = tid; d < Dm; d += 128) {
        float xv = xp[d];
        const float* wrow = Wr + (long)d * Ee;
#pragma unroll
        for (int e = 0; e < Ee; e++) acc[e] += xv * wrow[e];
    }
#pragma unroll
    for (int e = 0; e < Ee; e++) part[tid][e] = acc[e];
    __syncthreads();
    for (int st = 64; st > 0; st >>= 1) {
        if (tid < st)
#pragma unroll
            for (int e = 0; e < Ee; e++) part[tid][e] += part[tid + st][e];
        __syncthreads();
    }
    if (tid == 0) {
        float lg[Ee];
#pragma unroll
        for (int e = 0; e < Ee; e++) lg[e] = part[0][e] + br[e];
        float m1 = -3.4e38f, m2 = -3.4e38f;
#pragma unroll
        for (int e = 0; e < Ee; e++) {
            float v = lg[e];
            if (v > m1) { m2 = m1; m1 = v; }
            else if (v > m2) m2 = v;
        }
        float sum = 0.f, we[Ee];
#pragma unroll
        for (int e = 0; e < Ee; e++) {
            we[e] = (lg[e] < m2) ? 0.f : expf(lg[e] - m1);
            sum += we[e];
        }
        float inv = 1.f / sum;
#pragma unroll
        for (int e = 0; e < Ee; e++) wout[(long)t * Ee + e] = we[e] * inv;
#pragma unroll
        for (int e = 0; e < NEXP; e++) {
            if (we[e + 1] != 0.f) {
                int p = atomicAdd(&cnt[e], 1);
                eidx[(long)e * Tt + p] = t;
            }
        }
    }
}

// ---------------- FiLM: write ytf as hi(/lo) only ----------------
__global__ __launch_bounds__(256) void film_kernel(const float* __restrict__ t0,
                                                   const float* __restrict__ t1,
                                                   const float* __restrict__ b0,
                                                   const float* __restrict__ b1,
                                                   __half* __restrict__ hi,
                                                   __half* __restrict__ lo, int wantLo)
{
    long i = (long)blockIdx.x * 256 + threadIdx.x;
    int d = (int)(i & (Dm - 1));
    float y = gelu_f(t0[i] + b0[d]) * (t1[i] + b1[d]);
    __half h = __float2half_rn(y);
    hi[i] = h;
    if (wantLo) lo[i] = __float2half_rn(y - __half2float(h));
}

// ---------------- expert mixing (ytf from hi/lo; PA fp16) ----------------
__global__ __launch_bounds__(256) void mix_kernel(const __half* __restrict__ pe,
                                                  const __half* __restrict__ ae,
                                                  const float* __restrict__ Pb,
                                                  const float* __restrict__ Ab,
                                                  const float* __restrict__ w,
                                                  __half* __restrict__ hi,
                                                  __half* __restrict__ lo, int wantLo)
{
    int t = blockIdx.x;
    __shared__ float ws[Ee];
    if (threadIdx.x < Ee) ws[threadIdx.x] = w[(long)t * Ee + threadIdx.x];
    __syncthreads();
#pragma unroll
    for (int it = 0; it < 4; it++) {
        int d = threadIdx.x + it * 256;
        long td = (long)t * Dm + d;
        float yv = __half2float(hi[td]);
        if (wantLo) yv += __half2float(lo[td]);
        float out = ws[0] * gelu_f(yv);
#pragma unroll
        for (int e = 0; e < NEXP; e++) {
            float we = ws[e + 1];
            if (we != 0.f) {
                float p = __half2float(pe[(long)e * Tt * Dm + td]) + Pb[e * Dm + d];
                float a = __half2float(ae[(long)e * Tt * Dm + td]) + Ab[e * Dm + d];
                out += we * (p * yv + a);
            }
        }
        __half h = __float2half_rn(out);
        hi[td] = h;
        if (wantLo) lo[td] = __float2half_rn(out - __half2float(h));
    }
}

// ---------------- host helpers ----------------
static float* symf(const void* s) { void* p = nullptr; cudaGetSymbolAddress(&p, s); return (float*)p; }
static __half* symh(const void* s) { void* p = nullptr; cudaGetSymbolAddress(&p, s); return (__half*)p; }
static int* symi(const void* s) { void* p = nullptr; cudaGetSymbolAddress(&p, s); return (int*)p; }

static void tgemm(const __half* ahi, const __half* alo,
                  const __half* bhi, const __half* blo,
                  const float* bias, const float* resid,
                  float* C, __half* Chi, __half* Clo,
                  int N, int K, int Z, long sB, long sC, int act, int terms)
{
    dim3 grid(N / BN, Tt / BM, Z);
    mma_gemm_kernel<<<grid, 256, SMEM_MM>>>(ahi, alo, bhi, blo, bias, resid,
                                            C, Chi, Clo, Tt, N, K, sB, sC, act,
                                            bias != nullptr, resid != nullptr,
                                            C != nullptr, Chi != nullptr, Clo != nullptr,
                                            terms);
}

extern "C" void kernel_launch(void* const* d_in, const int* in_sizes, int n_in,
                              void* d_out, int out_size)
{
    const float* x_in  = (const float*)d_in[0];
    const float* ln1_g = (const float*)d_in[1];
    const float* ln1_b = (const float*)d_in[2];
    const float* Wqkv  = (const float*)d_in[3];
    const float* bqkv  = (const float*)d_in[4];
    const float* Wo    = (const float*)d_in[5];
    const float* bo    = (const float*)d_in[6];
    const float* Wr    = (const float*)d_in[7];
    const float* br    = (const float*)d_in[8];
    const float* Wa1   = (const float*)d_in[9];
    const float* ba1   = (const float*)d_in[10];
    const float* Wa2   = (const float*)d_in[11];
    const float* ba2   = (const float*)d_in[12];
    const float* ln2_g = (const float*)d_in[13];
    const float* ln2_b = (const float*)d_in[14];
    const float* Wb0   = (const float*)d_in[15];
    const float* bb0   = (const float*)d_in[16];
    const float* Wb1   = (const float*)d_in[17];
    const float* bb1   = (const float*)d_in[18];
    const float* We_p  = (const float*)d_in[19];
    const float* be_p  = (const float*)d_in[20];
    const float* We_a  = (const float*)d_in[21];
    const float* be_a  = (const float*)d_in[22];

    float* X   = symf(g_x);
    float* T01 = symf(g_t01);
    float* T0  = T01;
    float* T1  = T01 + (long)Tt * Dm;
    __half* PA = symh(g_pa);
    float* Wt  = symf(g_w);
    __half* WHI = symh(g_whi);
    __half* WLO = symh(g_wlo);
    __half* AHI = symh(g_ahi);
    __half* ALO = symh(g_alo);
    __half* MHI = symh(g_mhi);
    __half* MLO = symh(g_mlo);
    __half* QKVH = symh(g_qkvh);
    __half* VT  = symh(g_vt);
    __half* SH  = symh(g_sh);
    int* CNT = symi(g_cnt);
    int* EIDX = symi(g_eidx);

    cudaFuncSetAttribute(mma_gemm_kernel,
                         cudaFuncAttributeMaxDynamicSharedMemorySize, SMEM_MM);
    cudaFuncSetAttribute(mma_gather_kernel,
                         cudaFuncAttributeMaxDynamicSharedMemorySize, SMEM_MM);
    cudaFuncSetAttribute(mma_h_kernel,
                         cudaFuncAttributeMaxDynamicSharedMemorySize, SMEM_H);

    // ---- weight transpose + split (5 launches) ----
    {
        dim3 g1(3072 / 64, 1024 / 64, Lnum);
        wsplit_kernel<<<g1, 256>>>(Wqkv, WHI + OFF_QKV, WLO + OFF_QKV,
                                   1024, 3072, 3072L * 1024, PER_L);
        dim3 g2(16, 16, 6);
        wsplit3_kernel<<<g2, 256>>>(Wo, Wb0, Wb1, WHI, WLO);
        dim3 g3(16, 16, 28);
        wsplitE_kernel<<<g3, 256>>>(We_p, We_a, WHI, WLO);
        dim3 g4(4096 / 64, 1024 / 64, Lnum);
        wsplit_kernel<<<g4, 256>>>(Wa1, WHI + OFF_WA1, WLO + OFF_WA1,
                                   1024, 4096, 4096L * 1024, PER_L);
        dim3 g5(1024 / 64, 4096 / 64, Lnum);
        wsplit_kernel<<<g5, 256>>>(Wa2, WHI + OFF_WA2, WLO + OFF_WA2,
                                   4096, 1024, 4096L * 1024, PER_L);
    }

    cudaMemcpyAsync(X, x_in, (size_t)Tt * Dm * sizeof(float),
                    cudaMemcpyDeviceToDevice, 0);

    for (int l = 0; l < Lnum; l++) {
        const __half* whl = WHI + (long)l * PER_L;
        const __half* wll = WLO + (long)l * PER_L;
        const int tpost = (l == Lnum - 1) ? 2 : 3;
        const int loPost = (tpost == 3) ? 1 : 0;

        // --- attention (QKV 2-term) ---
        ln_split_kernel<<<Tt, 256>>>(X, ln1_g + l * Dm, ln1_b + l * Dm, AHI, ALO, 0);
        tgemm(AHI, ALO, whl + OFF_QKV, wll + OFF_QKV,
              bqkv + (long)l * 3 * INNERd, nullptr,
              nullptr, QKVH, nullptr, 3 * INNERd, Dm, 1, 0, 0, 0, 2);

        {
            dim3 grid(Nn / 32, DHh / 32, Bb * Hh);
            vtrans_kernel<<<grid, 256>>>(QKVH, VT);
        }
        {
            dim3 grid(Nn / HBN, Nn / HBM, Bb * Hh);
            mma_h_kernel<<<grid, 256, SMEM_H>>>(
                QKVH, QKVH + INNERd, SH, nullptr,
                DHh, 3 * INNERd, 3 * INNERd, Nn, Hh,
                (long)Nn * 3 * INNERd, DHh,
                (long)Nn * 3 * INNERd, DHh,
                (long)Hh * Nn * Nn, (long)Nn * Nn,
                0.125f, 0);
        }
        softmax_h_kernel<<<Bb * Hh * Nn, 256>>>(SH);
        {
            dim3 grid(1, Nn / HBM, Bb * Hh);
            mma_h_kernel<<<grid, 256, SMEM_H>>>(
                SH, VT, AHI, ALO,
                Nn, Nn, Nn, INNERd, Hh,
                (long)Hh * Nn * Nn, (long)Nn * Nn,
                (long)Hh * DHh * Nn, (long)DHh * Nn,
                (long)Nn * INNERd, DHh,
                1.0f, 1);
        }
        tgemm(AHI, ALO, whl + OFF_WO, wll + OFF_WO,
              bo + (long)l * Dm, X, X, nullptr, nullptr, Dm, INNERd, 1, 0, 0, 0, 3);

        // --- router + expert gather ---
        reset_cnt_kernel<<<1, 32>>>(CNT);
        router_kernel<<<Tt, 128>>>(X, Wr + (long)l * Dm * Ee, br + (long)l * Ee,
                                   Wt + (long)l * Tt * Ee, CNT, EIDX);

        // --- FiLM trunk ---
        ln_split_kernel<<<Tt, 256>>>(X, ln2_g + l * Dm, ln2_b + l * Dm, AHI, ALO, loPost);
        tgemm(AHI, ALO, whl + OFF_WB0, wll + OFF_WB0,
              nullptr, nullptr, T01, nullptr, nullptr,
              Dm, Dm, 2, SZ1M, (long)Tt * Dm, 0, tpost);
        film_kernel<<<(Tt * Dm) / 256, 256>>>(T0, T1, bb0 + (long)l * Dm,
                                              bb1 + (long)l * Dm, AHI, ALO, loPost);

        // --- sparse gathered expert GEMMs (fp16 out) ---
        {
            dim3 grid(Dm / BN, Tt / BM, 2 * NEXP);
            mma_gather_kernel<<<grid, 256, SMEM_MM>>>(
                AHI, ALO, whl + OFF_WEP, wll + OFF_WEP, PA, CNT, EIDX, tpost);
        }

        // --- mix (in-place on AHI/ALO) ---
        mix_kernel<<<Tt, 256>>>(PA, PA + (long)NEXP * Tt * Dm,
                                be_p + (long)l * NEXP * Dm,
                                be_a + (long)l * NEXP * Dm,
                                Wt + (long)l * Tt * Ee, AHI, ALO, loPost);

        // --- adaptor MLP + residual ---
        tgemm(AHI, ALO, whl + OFF_WA1, wll + OFF_WA1,
              ba1 + (long)l * MLPd, nullptr,
              nullptr, MHI, (loPost ? MLO : nullptr), MLPd, Dm, 1, 0, 0, 1, tpost);
        tgemm(MHI, MLO, whl + OFF_WA2, wll + OFF_WA2,
              ba2 + (long)l * Dm, X, X, nullptr, nullptr, Dm, MLPd, 1, 0, 0, 0, tpost);
    }

    // outputs: x [B,N,D] then stacked router weights [L,B,N,E]
    cudaMemcpyAsync(d_out, X, (size_t)Tt * Dm * sizeof(float),
                    cudaMemcpyDeviceToDevice, 0);
    if (out_size >= Tt * Dm + Lnum * Tt * Ee) {
        cudaMemcpyAsync((float*)d_out + (size_t)Tt * Dm, Wt,
                        (size_t)Lnum * Tt * Ee * sizeof(float),
                        cudaMemcpyDeviceToDevice, 0);
    }
}

// round 13
// speedup vs baseline: 4.4149x; 1.0398x over previous
#include <cuda_runtime.h>
#include <cuda_fp16.h>
#include <cstdint>
#include <math.h>

// ---------------- problem constants ----------------
#define Dm     1024
#define Lnum   2
#define Hh     16
#define DHh    64
#define INNERd 1024
#define MLPd   4096
#define Ee     8
#define Bb     4
#define Nn     1024
#define Tt     (Bb*Nn)
#define NEXP   (Ee-1)

// weight pack offsets (elements, per layer)
#define SZ1M   (1024L*1024L)
#define OFF_QKV 0L
#define OFF_WO  (OFF_QKV + 3072L*1024L)
#define OFF_WB0 (OFF_WO  + SZ1M)
#define OFF_WB1 (OFF_WB0 + SZ1M)
#define OFF_WEP (OFF_WB1 + SZ1M)
#define OFF_WEA (OFF_WEP + 7L*SZ1M)
#define OFF_WA1 (OFF_WEA + 7L*SZ1M)
#define OFF_WA2 (OFF_WA1 + 4096L*1024L)
#define PER_L   (OFF_WA2 + 4096L*1024L)

// ---------------- scratch (device globals) ----------------
__device__ float g_x[Tt*Dm];
__device__ float g_t01[2L*Tt*Dm];
__device__ __half g_pa[(size_t)2*NEXP*Tt*Dm];     // fp16 expert outputs
__device__ float g_w[Lnum*Tt*Ee];
__device__ __half g_whi[2L*PER_L];
__device__ __half g_wlo[2L*PER_L];
__device__ __half g_ahi[(size_t)Tt*Dm];
__device__ __half g_alo[(size_t)Tt*Dm];
__device__ __half g_mhi[(size_t)Tt*MLPd];
__device__ __half g_mlo[(size_t)Tt*MLPd];
__device__ __half g_qkvh[(size_t)Tt*3*INNERd];
__device__ __half g_vt[(size_t)Bb*Hh*DHh*Nn];
__device__ __half g_sh[(size_t)Bb*Hh*Nn*Nn];      // exp(scores) fp16
__device__ int g_cnt[NEXP];
__device__ int g_eidx[(size_t)NEXP*Tt];

__device__ __forceinline__ float gelu_f(float v) {
    return 0.5f * v * (1.0f + erff(v * 0.7071067811865475f));
}

__device__ __forceinline__ uint32_t smem_u32(const void* p) {
    uint32_t a;
    asm("{ .reg .u64 t; cvta.to.shared.u64 t, %1; cvt.u32.u64 %0, t; }"
        : "=r"(a) : "l"(p));
    return a;
}
__device__ __forceinline__ void ldmx4(uint32_t* r, uint32_t addr) {
    asm volatile("ldmatrix.sync.aligned.m8n8.x4.shared.b16 {%0,%1,%2,%3}, [%4];"
        : "=r"(r[0]), "=r"(r[1]), "=r"(r[2]), "=r"(r[3]) : "r"(addr));
}
__device__ __forceinline__ void ldmx2(uint32_t* r, uint32_t addr) {
    asm volatile("ldmatrix.sync.aligned.m8n8.x2.shared.b16 {%0,%1}, [%2];"
        : "=r"(r[0]), "=r"(r[1]) : "r"(addr));
}
__device__ __forceinline__ void mma16816(float* d, const uint32_t* a, const uint32_t* b) {
    asm volatile("mma.sync.aligned.m16n8k16.row.col.f32.f16.f16.f32 "
        "{%0,%1,%2,%3}, {%4,%5,%6,%7}, {%8,%9}, {%0,%1,%2,%3};"
        : "+f"(d[0]), "+f"(d[1]), "+f"(d[2]), "+f"(d[3])
        : "r"(a[0]), "r"(a[1]), "r"(a[2]), "r"(a[3]), "r"(b[0]), "r"(b[1]));
}

// ================= split HMMA GEMM (2 or 3 terms), 2-stage, 2 CTAs/SM =================
#define BM 128
#define BN 128
#define BK 32
#define LDT 40
#define TILE_B (128*LDT*2)
#define ST_AHI 0
#define ST_ALO (1*TILE_B)
#define ST_BHI (2*TILE_B)
#define ST_BLO (3*TILE_B)
#define STAGE_B (4*TILE_B)
#define SMEM_MM (2*STAGE_B)

#define GEMM_PHASE(base, ph)                                                      \
    do {                                                                          \
        uint32_t bhi[4][2], blo[4][2], af[4][4];                                  \
        _Pragma("unroll")                                                         \
        for (int nt = 0; nt < 4; nt++) {                                          \
            int rr = wn * 32 + nt * 8 + (lane & 7);                               \
            uint32_t co = (uint32_t)(rr * LDT + (ph) * 16 + ((lane >> 3) & 1) * 8) * 2; \
            ldmx2(bhi[nt], (base) + ST_BHI + co);                                 \
            ldmx2(blo[nt], (base) + ST_BLO + co);                                 \
        }                                                                         \
        _Pragma("unroll")                                                         \
        for (int mt = 0; mt < 4; mt++) {                                          \
            int rr = wm * 64 + mt * 16 + (lane & 15);                             \
            uint32_t co = (uint32_t)(rr * LDT + (ph) * 16 + (lane >> 4) * 8) * 2; \
            ldmx4(af[mt], (base) + ST_AHI + co);                                  \
        }                                                                         \
        _Pragma("unroll")                                                         \
        for (int mt = 0; mt < 4; mt++)                                            \
            _Pragma("unroll")                                                     \
            for (int nt = 0; nt < 4; nt++) {                                      \
                mma16816(acc[mt][nt], af[mt], bhi[nt]);                           \
                mma16816(acc[mt][nt], af[mt], blo[nt]);                           \
            }                                                                     \
        if (terms == 3) {                                                         \
            _Pragma("unroll")                                                     \
            for (int mt = 0; mt < 4; mt++) {                                      \
                int rr = wm * 64 + mt * 16 + (lane & 15);                         \
                uint32_t co = (uint32_t)(rr * LDT + (ph) * 16 + (lane >> 4) * 8) * 2; \
                ldmx4(af[mt], (base) + ST_ALO + co);                              \
            }                                                                     \
            _Pragma("unroll")                                                     \
            for (int mt = 0; mt < 4; mt++)                                        \
                _Pragma("unroll")                                                 \
                for (int nt = 0; nt < 4; nt++)                                    \
                    mma16816(acc[mt][nt], af[mt], bhi[nt]);                       \
        }                                                                         \
    } while (0)

__global__ __launch_bounds__(256, 2) void mma_gemm_kernel(
    const __half* __restrict__ Ahi, const __half* __restrict__ Alo,
    const __half* __restrict__ Bhi, const __half* __restrict__ Blo,
    const float* __restrict__ bias, const float* __restrict__ resid,
    float* __restrict__ C, __half* __restrict__ Chi, __half* __restrict__ Clo,
    int M, int N, int K, long sB, long sC, int act,
    int hasBias, int hasRes, int wantF32, int wantHi, int wantLo, int terms)
{
    extern __shared__ char smem[];
    uint32_t sb = smem_u32(smem);
    const int tid = threadIdx.x;
    const int wid = tid >> 5;
    const int lane = tid & 31;
    const long z = blockIdx.z;
    Bhi += z * sB;
    Blo += z * sB;
    if (wantF32) C += z * sC;
    if (wantHi) Chi += z * sC;
    if (wantLo) Clo += z * sC;
    const float* res = hasRes ? (resid + z * sC) : nullptr;
    const int row0 = blockIdx.y * BM;
    const int col0 = blockIdx.x * BN;
    const int wm = wid & 1;
    const int wn = wid >> 1;

    float acc[4][4][4];
#pragma unroll
    for (int a = 0; a < 4; a++)
#pragma unroll
        for (int b = 0; b < 4; b++)
#pragma unroll
            for (int c = 0; c < 4; c++) acc[a][b][c] = 0.f;

    const int nc = K / BK;

    auto load_stage = [&](int s, int kt) {
        uint32_t base = sb + s * STAGE_B;
#pragma unroll
        for (int i = 0; i < 8; i++) {
            int idx = i * 256 + tid;
            int mat = idx >> 9;
            if (terms == 2 && mat == 1) continue;
            int rem = idx & 511;
            int r = rem >> 2, c = rem & 3;
            uint32_t sa = base + mat * TILE_B + (uint32_t)(r * LDT + c * 8) * 2;
            const __half* gp;
            if (mat == 0)      gp = Ahi + (long)(row0 + r) * K + kt + c * 8;
            else if (mat == 1) gp = Alo + (long)(row0 + r) * K + kt + c * 8;
            else if (mat == 2) gp = Bhi + (long)(col0 + r) * K + kt + c * 8;
            else               gp = Blo + (long)(col0 + r) * K + kt + c * 8;
            asm volatile("cp.async.cg.shared.global [%0], [%1], 16;"
                         :: "r"(sa), "l"(gp));
        }
        asm volatile("cp.async.commit_group;");
    };

    load_stage(0, 0);

    for (int c = 0; c < nc; c++) {
        int s = c & 1;
        if (c + 1 < nc) {
            load_stage(s ^ 1, (c + 1) * BK);
            asm volatile("cp.async.wait_group 1;");
        } else {
            asm volatile("cp.async.wait_group 0;");
        }
        __syncthreads();
        uint32_t base = sb + s * STAGE_B;
        GEMM_PHASE(base, 0);
        GEMM_PHASE(base, 1);
        __syncthreads();
    }

#pragma unroll
    for (int mt = 0; mt < 4; mt++) {
#pragma unroll
        for (int nt = 0; nt < 4; nt++) {
            int rb = row0 + wm * 64 + mt * 16 + (lane >> 2);
            int cc = col0 + wn * 32 + nt * 8 + (lane & 3) * 2;
            float b0 = 0.f, b1 = 0.f;
            if (hasBias) { b0 = bias[cc]; b1 = bias[cc + 1]; }
#pragma unroll
            for (int hf = 0; hf < 2; hf++) {
                int rr = rb + hf * 8;
                float v0 = acc[mt][nt][hf * 2] + b0;
                float v1 = acc[mt][nt][hf * 2 + 1] + b1;
                if (act == 1) { v0 = gelu_f(v0); v1 = gelu_f(v1); }
                if (hasRes) {
                    v0 += res[(long)rr * N + cc];
                    v1 += res[(long)rr * N + cc + 1];
                }
                long o = (long)rr * N + cc;
                if (wantF32) *(float2*)&C[o] = make_float2(v0, v1);
                if (wantHi) {
                    __half h0 = __float2half_rn(v0), h1 = __float2half_rn(v1);
                    *(__half2*)&Chi[o] = __halves2half2(h0, h1);
                    if (wantLo) {
                        __half l0 = __float2half_rn(v0 - __half2float(h0));
                        __half l1 = __float2half_rn(v1 - __half2float(h1));
                        *(__half2*)&Clo[o] = __halves2half2(l0, l1);
                    }
                }
            }
        }
    }
}

// ================= token-gathered sparse expert GEMM (fp16 output) =================
__global__ __launch_bounds__(256, 2) void mma_gather_kernel(
    const __half* __restrict__ Ahi, const __half* __restrict__ Alo,
    const __half* __restrict__ Whi, const __half* __restrict__ Wlo,
    __half* __restrict__ PA,
    const int* __restrict__ cnt, const int* __restrict__ eidx, int terms)
{
    const int z = blockIdx.z;
    const int e = z % NEXP;
    const int n = cnt[e];
    const int row0 = blockIdx.y * BM;
    if (row0 >= n) return;

    extern __shared__ char smem[];
    uint32_t sb = smem_u32(smem);
    __shared__ int sidx[BM];
    const int tid = threadIdx.x;
    const int wid = tid >> 5;
    const int lane = tid & 31;
    const __half* Bhi = Whi + (long)z * SZ1M;
    const __half* Blo = Wlo + (long)z * SZ1M;
    __half* C = PA + (long)z * Tt * Dm;
    const int col0 = blockIdx.x * BN;
    const int wm = wid & 1;
    const int wn = wid >> 1;
    const int K = Dm;

    if (tid < BM) {
        int rr = row0 + tid;
        sidx[tid] = eidx[(long)e * Tt + (rr < n ? rr : n - 1)];
    }
    __syncthreads();

    float acc[4][4][4];
#pragma unroll
    for (int a = 0; a < 4; a++)
#pragma unroll
        for (int b = 0; b < 4; b++)
#pragma unroll
            for (int c = 0; c < 4; c++) acc[a][b][c] = 0.f;

    const int nc = K / BK;

    auto load_stage = [&](int s, int kt) {
        uint32_t base = sb + s * STAGE_B;
#pragma unroll
        for (int i = 0; i < 8; i++) {
            int idx = i * 256 + tid;
            int mat = idx >> 9;
            if (terms == 2 && mat == 1) continue;
            int rem = idx & 511;
            int r = rem >> 2, c = rem & 3;
            uint32_t sa = base + mat * TILE_B + (uint32_t)(r * LDT + c * 8) * 2;
            const __half* gp;
            if (mat == 0)      gp = Ahi + (long)sidx[r] * K + kt + c * 8;
            else if (mat == 1) gp = Alo + (long)sidx[r] * K + kt + c * 8;
            else if (mat == 2) gp = Bhi + (long)(col0 + r) * K + kt + c * 8;
            else               gp = Blo + (long)(col0 + r) * K + kt + c * 8;
            asm volatile("cp.async.cg.shared.global [%0], [%1], 16;"
                         :: "r"(sa), "l"(gp));
        }
        asm volatile("cp.async.commit_group;");
    };

    load_stage(0, 0);

    for (int c = 0; c < nc; c++) {
        int s = c & 1;
        if (c + 1 < nc) {
            load_stage(s ^ 1, (c + 1) * BK);
            asm volatile("cp.async.wait_group 1;");
        } else {
            asm volatile("cp.async.wait_group 0;");
        }
        __syncthreads();
        uint32_t base = sb + s * STAGE_B;
        GEMM_PHASE(base, 0);
        GEMM_PHASE(base, 1);
        __syncthreads();
    }

#pragma unroll
    for (int mt = 0; mt < 4; mt++) {
#pragma unroll
        for (int nt = 0; nt < 4; nt++) {
            int lr = wm * 64 + mt * 16 + (lane >> 2);
            int cc = col0 + wn * 32 + nt * 8 + (lane & 3) * 2;
#pragma unroll
            for (int hf = 0; hf < 2; hf++) {
                int lrr = lr + hf * 8;
                if (row0 + lrr < n) {
                    long o = (long)sidx[lrr] * Dm + cc;
                    *(__half2*)&C[o] = __halves2half2(
                        __float2half_rn(acc[mt][nt][hf * 2]),
                        __float2half_rn(acc[mt][nt][hf * 2 + 1]));
                }
            }
        }
    }
}

// ================= single-term fp16 HMMA (attention) =================
// mode 0: C = acc*scale -> hi(/lo)
// mode 1: C = exp(acc*scale) -> hi           (QK^T + fused exp; |s| < ~3, no max needed)
// mode 2: C = acc / rowsum(expP) -> hi(/lo)  (P*V with fused softmax normalization)
#define HBM 128
#define HBN 64
#define HBK 64
#define LDTH 72
#define H_ATILE (128*LDTH*2)
#define H_BTILE (64*LDTH*2)
#define H_STAGE (H_ATILE + H_BTILE)
#define SMEM_H  (2*H_STAGE)

__global__ __launch_bounds__(256, 2) void mma_h_kernel(
    const __half* __restrict__ A, const __half* __restrict__ B,
    __half* __restrict__ Chi, __half* __restrict__ Clo,
    int K, int lda, int ldb, int ldc, int Hd,
    long sAb, long sAh, long sBb, long sBh, long sCb, long sCh,
    float scale, int wantLo, int mode)
{
    extern __shared__ char smem[];
    __shared__ float rs[128][2];
    uint32_t sb = smem_u32(smem);
    const int tid = threadIdx.x;
    const int wid = tid >> 5;
    const int lane = tid & 31;
    const int z = blockIdx.z;
    const int zb = z / Hd, zh = z % Hd;
    A += (long)zb * sAb + (long)zh * sAh;
    B += (long)zb * sBb + (long)zh * sBh;
    Chi += (long)zb * sCb + (long)zh * sCh;
    if (wantLo) Clo += (long)zb * sCb + (long)zh * sCh;
    const int row0 = blockIdx.y * HBM;
    const int col0 = blockIdx.x * HBN;
    const int wm = wid & 1;
    const int wn = wid >> 1;

    float acc[4][2][4];
#pragma unroll
    for (int a = 0; a < 4; a++)
#pragma unroll
        for (int b = 0; b < 2; b++)
#pragma unroll
            for (int c = 0; c < 4; c++) acc[a][b][c] = 0.f;

    const int nc = K / HBK;
    float fsum = 0.f;   // mode 2: partial row sum (row tid&127, half tid>>7)

    auto load_stage = [&](int s, int kt) {
        uint32_t base = sb + s * H_STAGE;
#pragma unroll
        for (int i = 0; i < 6; i++) {
            int idx = i * 256 + tid;
            if (idx < 1024) {
                int r = idx >> 3, c = idx & 7;
                uint32_t sa = base + (uint32_t)(r * LDTH + c * 8) * 2;
                const __half* gp = A + (long)(row0 + r) * lda + kt + c * 8;
                asm volatile("cp.async.cg.shared.global [%0], [%1], 16;"
                             :: "r"(sa), "l"(gp));
            } else {
                int j = idx - 1024;
                int r = j >> 3, c = j & 7;
                uint32_t sa = base + H_ATILE + (uint32_t)(r * LDTH + c * 8) * 2;
                const __half* gp = B + (long)(col0 + r) * ldb + kt + c * 8;
                asm volatile("cp.async.cg.shared.global [%0], [%1], 16;"
                             :: "r"(sa), "l"(gp));
            }
        }
        asm volatile("cp.async.commit_group;");
    };

    load_stage(0, 0);

    for (int c = 0; c < nc; c++) {
        int s = c & 1;
        if (c + 1 < nc) {
            load_stage(s ^ 1, (c + 1) * HBK);
            asm volatile("cp.async.wait_group 1;");
        } else {
            asm volatile("cp.async.wait_group 0;");
        }
        __syncthreads();

        uint32_t base = sb + s * H_STAGE;
#pragma unroll
        for (int ph = 0; ph < 4; ph++) {
            uint32_t af[4][4], bf[2][2];
#pragma unroll
            for (int mt = 0; mt < 4; mt++) {
                int rr = wm * 64 + mt * 16 + (lane & 15);
                uint32_t co = (uint32_t)(rr * LDTH + ph * 16 + (lane >> 4) * 8) * 2;
                ldmx4(af[mt], base + co);
            }
#pragma unroll
            for (int nt = 0; nt < 2; nt++) {
                int rr = wn * 16 + nt * 8 + (lane & 7);
                uint32_t co = (uint32_t)(rr * LDTH + ph * 16 + ((lane >> 3) & 1) * 8) * 2;
                ldmx2(bf[nt], base + H_ATILE + co);
            }
#pragma unroll
            for (int mt = 0; mt < 4; mt++)
#pragma unroll
                for (int nt = 0; nt < 2; nt++)
                    mma16816(acc[mt][nt], af[mt], bf[nt]);
        }
        if (mode == 2) {
            // row-sum of the exp(S) tile (same fp16 values the MMA consumed)
            int r = tid & 127, hf2 = tid >> 7;
            const __half2* ap = (const __half2*)(smem + s * H_STAGE
                                                 + (size_t)(r * LDTH + hf2 * 32) * 2);
            float lsum = 0.f;
#pragma unroll
            for (int j = 0; j < 16; j++) {
                float2 f = __half22float2(ap[j]);
                lsum += f.x + f.y;
            }
            fsum += lsum;
        }
        __syncthreads();
    }
    if (mode == 2) {
        rs[tid & 127][tid >> 7] = fsum;
        __syncthreads();
    }

#pragma unroll
    for (int mt = 0; mt < 4; mt++) {
#pragma unroll
        for (int nt = 0; nt < 2; nt++) {
            int lrb = wm * 64 + mt * 16 + (lane >> 2);
            int cc = col0 + wn * 16 + nt * 8 + (lane & 3) * 2;
#pragma unroll
            for (int hf = 0; hf < 2; hf++) {
                int lr = lrb + hf * 8;
                int rr = row0 + lr;
                float v0, v1;
                if (mode == 1) {
                    v0 = expf(acc[mt][nt][hf * 2] * scale);
                    v1 = expf(acc[mt][nt][hf * 2 + 1] * scale);
                } else if (mode == 2) {
                    float inv = 1.f / (rs[lr][0] + rs[lr][1]);
                    v0 = acc[mt][nt][hf * 2] * inv;
                    v1 = acc[mt][nt][hf * 2 + 1] * inv;
                } else {
                    v0 = acc[mt][nt][hf * 2] * scale;
                    v1 = acc[mt][nt][hf * 2 + 1] * scale;
                }
                __half h0 = __float2half_rn(v0), h1 = __float2half_rn(v1);
                long o = (long)rr * ldc + cc;
                *(__half2*)&Chi[o] = __halves2half2(h0, h1);
                if (wantLo) {
                    __half l0 = __float2half_rn(v0 - __half2float(h0));
                    __half l1 = __float2half_rn(v1 - __half2float(h1));
                    *(__half2*)&Clo[o] = __halves2half2(l0, l1);
                }
            }
        }
    }
}

// ---------------- V transpose ----------------
__global__ __launch_bounds__(256) void vtrans_kernel(const __half* __restrict__ qkvh,
                                                     __half* __restrict__ vt)
{
    __shared__ __half t[32][33];
    int z = blockIdx.z, b = z >> 4, h = z & 15;
    int k0 = blockIdx.x * 32, d0 = blockIdx.y * 32;
    int tx = threadIdx.x & 31, ty = threadIdx.x >> 5;
#pragma unroll
    for (int i = 0; i < 4; i++) {
        int k = k0 + ty + i * 8;
        t[ty + i * 8][tx] = qkvh[(long)(b * Nn + k) * 3072 + 2048 + h * 64 + d0 + tx];
    }
    __syncthreads();
#pragma unroll
    for (int i = 0; i < 4; i++) {
        int d = d0 + ty + i * 8;
        vt[((long)z * 64 + d) * Nn + k0 + tx] = t[tx][ty + i * 8];
    }
}

// ---------------- weight transpose + fp16 split core ----------------
__device__ __forceinline__ void wsplit_tile(const float* __restrict__ Wz,
                                            __half* __restrict__ hi,
                                            __half* __restrict__ lo,
                                            long ob, int K, int N,
                                            int k0, int n0, int tid)
{
    __shared__ float tile[64][65];
#pragma unroll
    for (int i = 0; i < 4; i++) {
        int idx = i * 256 + tid;
        int r = idx >> 4, c4 = idx & 15;
        float4 v = *(const float4*)(Wz + (long)(k0 + r) * N + n0 + c4 * 4);
        tile[r][c4 * 4 + 0] = v.x; tile[r][c4 * 4 + 1] = v.y;
        tile[r][c4 * 4 + 2] = v.z; tile[r][c4 * 4 + 3] = v.w;
    }
    __syncthreads();
#pragma unroll
    for (int i = 0; i < 2; i++) {
        int idx = i * 256 + tid;
        int nn = idx >> 3, kg = idx & 7;
        __half hbuf[8], lbuf[8];
#pragma unroll
        for (int j = 0; j < 8; j++) {
            float v = tile[kg * 8 + j][nn];
            __half h = __float2half_rn(v);
            hbuf[j] = h;
            lbuf[j] = __float2half_rn(v - __half2float(h));
        }
        long o = ob + (long)(n0 + nn) * K + k0 + kg * 8;
        *(uint4*)(hi + o) = *(uint4*)hbuf;
        *(uint4*)(lo + o) = *(uint4*)lbuf;
    }
}

__global__ __launch_bounds__(256) void wsplit_kernel(
    const float* __restrict__ W, __half* __restrict__ hi, __half* __restrict__ lo,
    int K, int N, long inStride, long outStride)
{
    wsplit_tile(W + blockIdx.z * inStride, hi, lo, (long)blockIdx.z * outStride,
                K, N, blockIdx.y * 64, blockIdx.x * 64, threadIdx.x);
}

__global__ __launch_bounds__(256) void wsplit3_kernel(
    const float* __restrict__ W0, const float* __restrict__ W1,
    const float* __restrict__ W2,
    __half* __restrict__ hi, __half* __restrict__ lo)
{
    int z = blockIdx.z;
    int t = z >> 1, l = z & 1;
    const float* src = (t == 0 ? W0 : (t == 1 ? W1 : W2)) + (long)l * SZ1M;
    long off = (t == 0 ? OFF_WO : (t == 1 ? OFF_WB0 : OFF_WB1)) + (long)l * PER_L;
    wsplit_tile(src, hi, lo, off, 1024, 1024,
                blockIdx.y * 64, blockIdx.x * 64, threadIdx.x);
}

__global__ __launch_bounds__(256) void wsplitE_kernel(
    const float* __restrict__ Wp, const float* __restrict__ Wa,
    __half* __restrict__ hi, __half* __restrict__ lo)
{
    int z = blockIdx.z;
    int l = z / 14, s = z % 14;
    const float* src = (s < 7 ? Wp + (long)l * 7 * SZ1M + (long)s * SZ1M
                              : Wa + (long)l * 7 * SZ1M + (long)(s - 7) * SZ1M);
    long off = (long)l * PER_L + OFF_WEP + (long)s * SZ1M;
    wsplit_tile(src, hi, lo, off, 1024, 1024,
                blockIdx.y * 64, blockIdx.x * 64, threadIdx.x);
}

// ---------------- LayerNorm -> fp16 hi(/lo) ----------------
__global__ __launch_bounds__(256) void ln_split_kernel(
    const float* __restrict__ x, const float* __restrict__ g,
    const float* __restrict__ bta,
    __half* __restrict__ hi, __half* __restrict__ lo, int wantLo)
{
    int t = blockIdx.x, tid = threadIdx.x;
    const float* xp = x + (long)t * Dm;
    __shared__ float r1[256], r2[256];

    float v[4], s = 0.f, s2 = 0.f;
#pragma unroll
    for (int i = 0; i < 4; i++) { v[i] = xp[tid + i * 256]; s += v[i]; s2 += v[i] * v[i]; }
    r1[tid] = s; r2[tid] = s2; __syncthreads();
    for (int st = 128; st > 0; st >>= 1) {
        if (tid < st) { r1[tid] += r1[tid + st]; r2[tid] += r2[tid + st]; }
        __syncthreads();
    }
    float mean = r1[0] * (1.f / Dm);
    float var = r2[0] * (1.f / Dm) - mean * mean;
    float rstd = rsqrtf(var + 1e-5f);
#pragma unroll
    for (int i = 0; i < 4; i++) {
        int d = tid + i * 256;
        float y = (v[i] - mean) * rstd * g[d] + bta[d];
        __half h = __float2half_rn(y);
        hi[(long)t * Dm + d] = h;
        if (wantLo) lo[(long)t * Dm + d] = __float2half_rn(y - __half2float(h));
    }
}

// ---------------- reset expert counters ----------------
__global__ void reset_cnt_kernel(int* cnt)
{
    if (threadIdx.x < NEXP) cnt[threadIdx.x] = 0;
}

// ---------------- router (+ expert token gather) ----------------
__global__ __launch_bounds__(128) void router_kernel(const float* __restrict__ x,
                                                     const float* __restrict__ Wr,
                                                     const float* __restrict__ br,
                                                     float* __restrict__ wout,
                                                     int* __restrict__ cnt,
                                                     int* __restrict__ eidx)
{
    int t = blockIdx.x, tid = threadIdx.x;
    __shared__ float part[128][Ee];
    float acc[Ee];
#pragma unroll
    for (int e = 0; e < Ee; e++) acc[e] = 0.f;
    const float* xp = x + (long)t * Dm;
    for (int d = tid; d < Dm; d += 128) {
        float xv = xp[d];
        const float* wrow = Wr + (long)d * Ee;
#pragma unroll
        for (int e = 0; e < Ee; e++) acc[e] += xv * wrow[e];
    }
#pragma unroll
    for (int e = 0; e < Ee; e++) part[tid][e] = acc[e];
    __syncthreads();
    for (int st = 64; st > 0; st >>= 1) {
        if (tid < st)
#pragma unroll
            for (int e = 0; e < Ee; e++) part[tid][e] += part[tid + st][e];
        __syncthreads();
    }
    if (tid == 0) {
        float lg[Ee];
#pragma unroll
        for (int e = 0; e < Ee; e++) lg[e] = part[0][e] + br[e];
        float m1 = -3.4e38f, m2 = -3.4e38f;
#pragma unroll
        for (int e = 0; e < Ee; e++) {
            float v = lg[e];
            if (v > m1) { m2 = m1; m1 = v; }
            else if (v > m2) m2 = v;
        }
        float sum = 0.f, we[Ee];
#pragma unroll
        for (int e = 0; e < Ee; e++) {
            we[e] = (lg[e] < m2) ? 0.f : expf(lg[e] - m1);
            sum += we[e];
        }
        float inv = 1.f / sum;
#pragma unroll
        for (int e = 0; e < Ee; e++) wout[(long)t * Ee + e] = we[e] * inv;
#pragma unroll
        for (int e = 0; e < NEXP; e++) {
            if (we[e + 1] != 0.f) {
                int p = atomicAdd(&cnt[e], 1);
                eidx[(long)e * Tt + p] = t;
            }
        }
    }
}

// ---------------- FiLM: write ytf as hi(/lo) only ----------------
__global__ __launch_bounds__(256) void film_kernel(const float* __restrict__ t0,
                                                   const float* __restrict__ t1,
                                                   const float* __restrict__ b0,
                                                   const float* __restrict__ b1,
                                                   __half* __restrict__ hi,
                                                   __half* __restrict__ lo, int wantLo)
{
    long i = (long)blockIdx.x * 256 + threadIdx.x;
    int d = (int)(i & (Dm - 1));
    float y = gelu_f(t0[i] + b0[d]) * (t1[i] + b1[d]);
    __half h = __float2half_rn(y);
    hi[i] = h;
    if (wantLo) lo[i] = __float2half_rn(y - __half2float(h));
}

// ---------------- expert mixing (ytf from hi/lo; PA fp16) ----------------
__global__ __launch_bounds__(256) void mix_kernel(const __half* __restrict__ pe,
                                                  const __half* __restrict__ ae,
                                                  const float* __restrict__ Pb,
                                                  const float* __restrict__ Ab,
                                                  const float* __restrict__ w,
                                                  __half* __restrict__ hi,
                                                  __half* __restrict__ lo, int wantLo)
{
    int t = blockIdx.x;
    __shared__ float ws[Ee];
    if (threadIdx.x < Ee) ws[threadIdx.x] = w[(long)t * Ee + threadIdx.x];
    __syncthreads();
#pragma unroll
    for (int it = 0; it < 4; it++) {
        int d = threadIdx.x + it * 256;
        long td = (long)t * Dm + d;
        float yv = __half2float(hi[td]);
        if (wantLo) yv += __half2float(lo[td]);
        float out = ws[0] * gelu_f(yv);
#pragma unroll
        for (int e = 0; e < NEXP; e++) {
            float we = ws[e + 1];
            if (we != 0.f) {
                float p = __half2float(pe[(long)e * Tt * Dm + td]) + Pb[e * Dm + d];
                float a = __half2float(ae[(long)e * Tt * Dm + td]) + Ab[e * Dm + d];
                out += we * (p * yv + a);
            }
        }
        __half h = __float2half_rn(out);
        hi[td] = h;
        if (wantLo) lo[td] = __float2half_rn(out - __half2float(h));
    }
}

// ---------------- host helpers ----------------
static float* symf(const void* s) { void* p = nullptr; cudaGetSymbolAddress(&p, s); return (float*)p; }
static __half* symh(const void* s) { void* p = nullptr; cudaGetSymbolAddress(&p, s); return (__half*)p; }
static int* symi(const void* s) { void* p = nullptr; cudaGetSymbolAddress(&p, s); return (int*)p; }

static void tgemm(const __half* ahi, const __half* alo,
                  const __half* bhi, const __half* blo,
                  const float* bias, const float* resid,
                  float* C, __half* Chi, __half* Clo,
                  int N, int K, int Z, long sB, long sC, int act, int terms)
{
    dim3 grid(N / BN, Tt / BM, Z);
    mma_gemm_kernel<<<grid, 256, SMEM_MM>>>(ahi, alo, bhi, blo, bias, resid,
                                            C, Chi, Clo, Tt, N, K, sB, sC, act,
                                            bias != nullptr, resid != nullptr,
                                            C != nullptr, Chi != nullptr, Clo != nullptr,
                                            terms);
}

extern "C" void kernel_launch(void* const* d_in, const int* in_sizes, int n_in,
                              void* d_out, int out_size)
{
    const float* x_in  = (const float*)d_in[0];
    const float* ln1_g = (const float*)d_in[1];
    const float* ln1_b = (const float*)d_in[2];
    const float* Wqkv  = (const float*)d_in[3];
    const float* bqkv  = (const float*)d_in[4];
    const float* Wo    = (const float*)d_in[5];
    const float* bo    = (const float*)d_in[6];
    const float* Wr    = (const float*)d_in[7];
    const float* br    = (const float*)d_in[8];
    const float* Wa1   = (const float*)d_in[9];
    const float* ba1   = (const float*)d_in[10];
    const float* Wa2   = (const float*)d_in[11];
    const float* ba2   = (const float*)d_in[12];
    const float* ln2_g = (const float*)d_in[13];
    const float* ln2_b = (const float*)d_in[14];
    const float* Wb0   = (const float*)d_in[15];
    const float* bb0   = (const float*)d_in[16];
    const float* Wb1   = (const float*)d_in[17];
    const float* bb1   = (const float*)d_in[18];
    const float* We_p  = (const float*)d_in[19];
    const float* be_p  = (const float*)d_in[20];
    const float* We_a  = (const float*)d_in[21];
    const float* be_a  = (const float*)d_in[22];

    float* X   = symf(g_x);
    float* T01 = symf(g_t01);
    float* T0  = T01;
    float* T1  = T01 + (long)Tt * Dm;
    __half* PA = symh(g_pa);
    float* Wt  = symf(g_w);
    __half* WHI = symh(g_whi);
    __half* WLO = symh(g_wlo);
    __half* AHI = symh(g_ahi);
    __half* ALO = symh(g_alo);
    __half* MHI = symh(g_mhi);
    __half* MLO = symh(g_mlo);
    __half* QKVH = symh(g_qkvh);
    __half* VT  = symh(g_vt);
    __half* SH  = symh(g_sh);
    int* CNT = symi(g_cnt);
    int* EIDX = symi(g_eidx);

    cudaFuncSetAttribute(mma_gemm_kernel,
                         cudaFuncAttributeMaxDynamicSharedMemorySize, SMEM_MM);
    cudaFuncSetAttribute(mma_gather_kernel,
                         cudaFuncAttributeMaxDynamicSharedMemorySize, SMEM_MM);
    cudaFuncSetAttribute(mma_h_kernel,
                         cudaFuncAttributeMaxDynamicSharedMemorySize, SMEM_H);

    // ---- weight transpose + split (5 launches) ----
    {
        dim3 g1(3072 / 64, 1024 / 64, Lnum);
        wsplit_kernel<<<g1, 256>>>(Wqkv, WHI + OFF_QKV, WLO + OFF_QKV,
                                   1024, 3072, 3072L * 1024, PER_L);
        dim3 g2(16, 16, 6);
        wsplit3_kernel<<<g2, 256>>>(Wo, Wb0, Wb1, WHI, WLO);
        dim3 g3(16, 16, 28);
        wsplitE_kernel<<<g3, 256>>>(We_p, We_a, WHI, WLO);
        dim3 g4(4096 / 64, 1024 / 64, Lnum);
        wsplit_kernel<<<g4, 256>>>(Wa1, WHI + OFF_WA1, WLO + OFF_WA1,
                                   1024, 4096, 4096L * 1024, PER_L);
        dim3 g5(1024 / 64, 4096 / 64, Lnum);
        wsplit_kernel<<<g5, 256>>>(Wa2, WHI + OFF_WA2, WLO + OFF_WA2,
                                   4096, 1024, 4096L * 1024, PER_L);
    }

    cudaMemcpyAsync(X, x_in, (size_t)Tt * Dm * sizeof(float),
                    cudaMemcpyDeviceToDevice, 0);

    for (int l = 0; l < Lnum; l++) {
        const __half* whl = WHI + (long)l * PER_L;
        const __half* wll = WLO + (long)l * PER_L;
        const int tpost = (l == Lnum - 1) ? 2 : 3;
        const int loPost = (tpost == 3) ? 1 : 0;

        // --- attention (QKV 2-term) ---
        ln_split_kernel<<<Tt, 256>>>(X, ln1_g + l * Dm, ln1_b + l * Dm, AHI, ALO, 0);
        tgemm(AHI, ALO, whl + OFF_QKV, wll + OFF_QKV,
              bqkv + (long)l * 3 * INNERd, nullptr,
              nullptr, QKVH, nullptr, 3 * INNERd, Dm, 1, 0, 0, 0, 2);

        {
            dim3 grid(Nn / 32, DHh / 32, Bb * Hh);
            vtrans_kernel<<<grid, 256>>>(QKVH, VT);
        }
        // S = exp(Q K^T / 8), fused exp (mode 1)
        {
            dim3 grid(Nn / HBN, Nn / HBM, Bb * Hh);
            mma_h_kernel<<<grid, 256, SMEM_H>>>(
                QKVH, QKVH + INNERd, SH, nullptr,
                DHh, 3 * INNERd, 3 * INNERd, Nn, Hh,
                (long)Nn * 3 * INNERd, DHh,
                (long)Nn * 3 * INNERd, DHh,
                (long)Hh * Nn * Nn, (long)Nn * Nn,
                0.125f, 0, 1);
        }
        // O = (expS @ V) / rowsum(expS), fused softmax normalization (mode 2)
        {
            dim3 grid(1, Nn / HBM, Bb * Hh);
            mma_h_kernel<<<grid, 256, SMEM_H>>>(
                SH, VT, AHI, ALO,
                Nn, Nn, Nn, INNERd, Hh,
                (long)Hh * Nn * Nn, (long)Nn * Nn,
                (long)Hh * DHh * Nn, (long)DHh * Nn,
                (long)Nn * INNERd, DHh,
                1.0f, 1, 2);
        }
        tgemm(AHI, ALO, whl + OFF_WO, wll + OFF_WO,
              bo + (long)l * Dm, X, X, nullptr, nullptr, Dm, INNERd, 1, 0, 0, 0, 3);

        // --- router + expert gather ---
        reset_cnt_kernel<<<1, 32>>>(CNT);
        router_kernel<<<Tt, 128>>>(X, Wr + (long)l * Dm * Ee, br + (long)l * Ee,
                                   Wt + (long)l * Tt * Ee, CNT, EIDX);

        // --- FiLM trunk ---
        ln_split_kernel<<<Tt, 256>>>(X, ln2_g + l * Dm, ln2_b + l * Dm, AHI, ALO, loPost);
        tgemm(AHI, ALO, whl + OFF_WB0, wll + OFF_WB0,
              nullptr, nullptr, T01, nullptr, nullptr,
              Dm, Dm, 2, SZ1M, (long)Tt * Dm, 0, tpost);
        film_kernel<<<(Tt * Dm) / 256, 256>>>(T0, T1, bb0 + (long)l * Dm,
                                              bb1 + (long)l * Dm, AHI, ALO, loPost);

        // --- sparse gathered expert GEMMs (fp16 out) ---
        {
            dim3 grid(Dm / BN, Tt / BM, 2 * NEXP);
            mma_gather_kernel<<<grid, 256, SMEM_MM>>>(
                AHI, ALO, whl + OFF_WEP, wll + OFF_WEP, PA, CNT, EIDX, tpost);
        }

        // --- mix (in-place on AHI/ALO) ---
        mix_kernel<<<Tt, 256>>>(PA, PA + (long)NEXP * Tt * Dm,
                                be_p + (long)l * NEXP * Dm,
                                be_a + (long)l * NEXP * Dm,
                                Wt + (long)l * Tt * Ee, AHI, ALO, loPost);

        // --- adaptor MLP + residual ---
        tgemm(AHI, ALO, whl + OFF_WA1, wll + OFF_WA1,
              ba1 + (long)l * MLPd, nullptr,
              nullptr, MHI, (loPost ? MLO : nullptr), MLPd, Dm, 1, 0, 0, 1, tpost);
        tgemm(MHI, MLO, whl + OFF_WA2, wll + OFF_WA2,
              ba2 + (long)l * Dm, X, X, nullptr, nullptr, Dm, MLPd, 1, 0, 0, 0, tpost);
    }

    // outputs: x [B,N,D] then stacked router weights [L,B,N,E]
    cudaMemcpyAsync(d_out, X, (size_t)Tt * Dm * sizeof(float),
                    cudaMemcpyDeviceToDevice, 0);
    if (out_size >= Tt * Dm + Lnum * Tt * Ee) {
        cudaMemcpyAsync((float*)d_out + (size_t)Tt * Dm, Wt,
                        (size_t)Lnum * Tt * Ee * sizeof(float),
                        cudaMemcpyDeviceToDevice, 0);
    }
}

// round 15
// speedup vs baseline: 4.6112x; 1.0445x over previous
#include <cuda_runtime.h>
#include <cuda_fp16.h>
#include <cstdint>
#include <math.h>

// ---------------- problem constants ----------------
#define Dm     1024
#define Lnum   2
#define Hh     16
#define DHh    64
#define INNERd 1024
#define MLPd   4096
#define Ee     8
#define Bb     4
#define Nn     1024
#define Tt     (Bb*Nn)
#define NEXP   (Ee-1)

// weight pack offsets (elements, per layer)
#define SZ1M   (1024L*1024L)
#define OFF_QKV 0L
#define OFF_WO  (OFF_QKV + 3072L*1024L)
#define OFF_WB0 (OFF_WO  + SZ1M)
#define OFF_WB1 (OFF_WB0 + SZ1M)
#define OFF_WEP (OFF_WB1 + SZ1M)
#define OFF_WEA (OFF_WEP + 7L*SZ1M)
#define OFF_WA1 (OFF_WEA + 7L*SZ1M)
#define OFF_WA2 (OFF_WA1 + 4096L*1024L)
#define PER_L   (OFF_WA2 + 4096L*1024L)

// ---------------- scratch (device globals) ----------------
__device__ float g_x[Tt*Dm];
__device__ float g_t01[2L*Tt*Dm];
__device__ __half g_pa[(size_t)2*NEXP*Tt*Dm];
__device__ float g_w[Lnum*Tt*Ee];
__device__ __half g_whi[2L*PER_L];
__device__ __half g_wlo[2L*PER_L];
__device__ __half g_ahi[(size_t)Tt*Dm];
__device__ __half g_alo[(size_t)Tt*Dm];
__device__ __half g_mhi[(size_t)Tt*MLPd];
__device__ __half g_mlo[(size_t)Tt*MLPd];
__device__ __half g_qkvh[(size_t)Tt*3*INNERd];
__device__ __half g_vt[(size_t)Bb*Hh*DHh*Nn];
__device__ int g_cnt[NEXP];
__device__ int g_eidx[(size_t)NEXP*Tt];

__device__ __forceinline__ float gelu_f(float v) {
    return 0.5f * v * (1.0f + erff(v * 0.7071067811865475f));
}

__device__ __forceinline__ uint32_t smem_u32(const void* p) {
    uint32_t a;
    asm("{ .reg .u64 t; cvta.to.shared.u64 t, %1; cvt.u32.u64 %0, t; }"
        : "=r"(a) : "l"(p));
    return a;
}
__device__ __forceinline__ void ldmx4(uint32_t* r, uint32_t addr) {
    asm volatile("ldmatrix.sync.aligned.m8n8.x4.shared.b16 {%0,%1,%2,%3}, [%4];"
        : "=r"(r[0]), "=r"(r[1]), "=r"(r[2]), "=r"(r[3]) : "r"(addr));
}
__device__ __forceinline__ void ldmx2(uint32_t* r, uint32_t addr) {
    asm volatile("ldmatrix.sync.aligned.m8n8.x2.shared.b16 {%0,%1}, [%2];"
        : "=r"(r[0]), "=r"(r[1]) : "r"(addr));
}
__device__ __forceinline__ void mma16816(float* d, const uint32_t* a, const uint32_t* b) {
    asm volatile("mma.sync.aligned.m16n8k16.row.col.f32.f16.f16.f32 "
        "{%0,%1,%2,%3}, {%4,%5,%6,%7}, {%8,%9}, {%0,%1,%2,%3};"
        : "+f"(d[0]), "+f"(d[1]), "+f"(d[2]), "+f"(d[3])
        : "r"(a[0]), "r"(a[1]), "r"(a[2]), "r"(a[3]), "r"(b[0]), "r"(b[1]));
}

// ================= split HMMA GEMM (2 or 3 terms), 2-stage, 2 CTAs/SM =================
#define BM 128
#define BN 128
#define BK 32
#define LDT 40
#define TILE_B (128*LDT*2)
#define ST_AHI 0
#define ST_ALO (1*TILE_B)
#define ST_BHI (2*TILE_B)
#define ST_BLO (3*TILE_B)
#define STAGE_B (4*TILE_B)
#define SMEM_MM (2*STAGE_B)

#define GEMM_PHASE(base, ph)                                                      \
    do {                                                                          \
        uint32_t bhi[4][2], blo[4][2], af[4][4];                                  \
        _Pragma("unroll")                                                         \
        for (int nt = 0; nt < 4; nt++) {                                          \
            int rr = wn * 32 + nt * 8 + (lane & 7);                               \
            uint32_t co = (uint32_t)(rr * LDT + (ph) * 16 + ((lane >> 3) & 1) * 8) * 2; \
            ldmx2(bhi[nt], (base) + ST_BHI + co);                                 \
            ldmx2(blo[nt], (base) + ST_BLO + co);                                 \
        }                                                                         \
        _Pragma("unroll")                                                         \
        for (int mt = 0; mt < 4; mt++) {                                          \
            int rr = wm * 64 + mt * 16 + (lane & 15);                             \
            uint32_t co = (uint32_t)(rr * LDT + (ph) * 16 + (lane >> 4) * 8) * 2; \
            ldmx4(af[mt], (base) + ST_AHI + co);                                  \
        }                                                                         \
        _Pragma("unroll")                                                         \
        for (int mt = 0; mt < 4; mt++)                                            \
            _Pragma("unroll")                                                     \
            for (int nt = 0; nt < 4; nt++) {                                      \
                mma16816(acc[mt][nt], af[mt], bhi[nt]);                           \
                mma16816(acc[mt][nt], af[mt], blo[nt]);                           \
            }                                                                     \
        if (terms == 3) {                                                         \
            _Pragma("unroll")                                                     \
            for (int mt = 0; mt < 4; mt++) {                                      \
                int rr = wm * 64 + mt * 16 + (lane & 15);                         \
                uint32_t co = (uint32_t)(rr * LDT + (ph) * 16 + (lane >> 4) * 8) * 2; \
                ldmx4(af[mt], (base) + ST_ALO + co);                              \
            }                                                                     \
            _Pragma("unroll")                                                     \
            for (int mt = 0; mt < 4; mt++)                                        \
                _Pragma("unroll")                                                 \
                for (int nt = 0; nt < 4; nt++)                                    \
                    mma16816(acc[mt][nt], af[mt], bhi[nt]);                       \
        }                                                                         \
    } while (0)

__global__ __launch_bounds__(256, 2) void mma_gemm_kernel(
    const __half* __restrict__ Ahi, const __half* __restrict__ Alo,
    const __half* __restrict__ Bhi, const __half* __restrict__ Blo,
    const float* __restrict__ bias, const float* __restrict__ resid,
    float* __restrict__ C, __half* __restrict__ Chi, __half* __restrict__ Clo,
    int M, int N, int K, long sB, long sC, int act,
    int hasBias, int hasRes, int wantF32, int wantHi, int wantLo, int terms)
{
    extern __shared__ char smem[];
    uint32_t sb = smem_u32(smem);
    const int tid = threadIdx.x;
    const int wid = tid >> 5;
    const int lane = tid & 31;
    const long z = blockIdx.z;
    Bhi += z * sB;
    Blo += z * sB;
    if (wantF32) C += z * sC;
    if (wantHi) Chi += z * sC;
    if (wantLo) Clo += z * sC;
    const float* res = hasRes ? (resid + z * sC) : nullptr;
    const int row0 = blockIdx.y * BM;
    const int col0 = blockIdx.x * BN;
    const int wm = wid & 1;
    const int wn = wid >> 1;

    float acc[4][4][4];
#pragma unroll
    for (int a = 0; a < 4; a++)
#pragma unroll
        for (int b = 0; b < 4; b++)
#pragma unroll
            for (int c = 0; c < 4; c++) acc[a][b][c] = 0.f;

    const int nc = K / BK;

    auto load_stage = [&](int s, int kt) {
        uint32_t base = sb + s * STAGE_B;
#pragma unroll
        for (int i = 0; i < 8; i++) {
            int idx = i * 256 + tid;
            int mat = idx >> 9;
            if (terms == 2 && mat == 1) continue;
            int rem = idx & 511;
            int r = rem >> 2, c = rem & 3;
            uint32_t sa = base + mat * TILE_B + (uint32_t)(r * LDT + c * 8) * 2;
            const __half* gp;
            if (mat == 0)      gp = Ahi + (long)(row0 + r) * K + kt + c * 8;
            else if (mat == 1) gp = Alo + (long)(row0 + r) * K + kt + c * 8;
            else if (mat == 2) gp = Bhi + (long)(col0 + r) * K + kt + c * 8;
            else               gp = Blo + (long)(col0 + r) * K + kt + c * 8;
            asm volatile("cp.async.cg.shared.global [%0], [%1], 16;"
                         :: "r"(sa), "l"(gp));
        }
        asm volatile("cp.async.commit_group;");
    };

    load_stage(0, 0);

    for (int c = 0; c < nc; c++) {
        int s = c & 1;
        if (c + 1 < nc) {
            load_stage(s ^ 1, (c + 1) * BK);
            asm volatile("cp.async.wait_group 1;");
        } else {
            asm volatile("cp.async.wait_group 0;");
        }
        __syncthreads();
        uint32_t base = sb + s * STAGE_B;
        GEMM_PHASE(base, 0);
        GEMM_PHASE(base, 1);
        __syncthreads();
    }

#pragma unroll
    for (int mt = 0; mt < 4; mt++) {
#pragma unroll
        for (int nt = 0; nt < 4; nt++) {
            int rb = row0 + wm * 64 + mt * 16 + (lane >> 2);
            int cc = col0 + wn * 32 + nt * 8 + (lane & 3) * 2;
            float b0 = 0.f, b1 = 0.f;
            if (hasBias) { b0 = bias[cc]; b1 = bias[cc + 1]; }
#pragma unroll
            for (int hf = 0; hf < 2; hf++) {
                int rr = rb + hf * 8;
                float v0 = acc[mt][nt][hf * 2] + b0;
                float v1 = acc[mt][nt][hf * 2 + 1] + b1;
                if (act == 1) { v0 = gelu_f(v0); v1 = gelu_f(v1); }
                if (hasRes) {
                    v0 += res[(long)rr * N + cc];
                    v1 += res[(long)rr * N + cc + 1];
                }
                long o = (long)rr * N + cc;
                if (wantF32) *(float2*)&C[o] = make_float2(v0, v1);
                if (wantHi) {
                    __half h0 = __float2half_rn(v0), h1 = __float2half_rn(v1);
                    *(__half2*)&Chi[o] = __halves2half2(h0, h1);
                    if (wantLo) {
                        __half l0 = __float2half_rn(v0 - __half2float(h0));
                        __half l1 = __float2half_rn(v1 - __half2float(h1));
                        *(__half2*)&Clo[o] = __halves2half2(l0, l1);
                    }
                }
            }
        }
    }
}

// ================= token-gathered sparse expert GEMM (fp16 output) =================
__global__ __launch_bounds__(256, 2) void mma_gather_kernel(
    const __half* __restrict__ Ahi, const __half* __restrict__ Alo,
    const __half* __restrict__ Whi, const __half* __restrict__ Wlo,
    __half* __restrict__ PA,
    const int* __restrict__ cnt, const int* __restrict__ eidx, int terms)
{
    const int z = blockIdx.z;
    const int e = z % NEXP;
    const int n = cnt[e];
    const int row0 = blockIdx.y * BM;
    if (row0 >= n) return;

    extern __shared__ char smem[];
    uint32_t sb = smem_u32(smem);
    __shared__ int sidx[BM];
    const int tid = threadIdx.x;
    const int wid = tid >> 5;
    const int lane = tid & 31;
    const __half* Bhi = Whi + (long)z * SZ1M;
    const __half* Blo = Wlo + (long)z * SZ1M;
    __half* C = PA + (long)z * Tt * Dm;
    const int col0 = blockIdx.x * BN;
    const int wm = wid & 1;
    const int wn = wid >> 1;
    const int K = Dm;

    if (tid < BM) {
        int rr = row0 + tid;
        sidx[tid] = eidx[(long)e * Tt + (rr < n ? rr : n - 1)];
    }
    __syncthreads();

    float acc[4][4][4];
#pragma unroll
    for (int a = 0; a < 4; a++)
#pragma unroll
        for (int b = 0; b < 4; b++)
#pragma unroll
            for (int c = 0; c < 4; c++) acc[a][b][c] = 0.f;

    const int nc = K / BK;

    auto load_stage = [&](int s, int kt) {
        uint32_t base = sb + s * STAGE_B;
#pragma unroll
        for (int i = 0; i < 8; i++) {
            int idx = i * 256 + tid;
            int mat = idx >> 9;
            if (terms == 2 && mat == 1) continue;
            int rem = idx & 511;
            int r = rem >> 2, c = rem & 3;
            uint32_t sa = base + mat * TILE_B + (uint32_t)(r * LDT + c * 8) * 2;
            const __half* gp;
            if (mat == 0)      gp = Ahi + (long)sidx[r] * K + kt + c * 8;
            else if (mat == 1) gp = Alo + (long)sidx[r] * K + kt + c * 8;
            else if (mat == 2) gp = Bhi + (long)(col0 + r) * K + kt + c * 8;
            else               gp = Blo + (long)(col0 + r) * K + kt + c * 8;
            asm volatile("cp.async.cg.shared.global [%0], [%1], 16;"
                         :: "r"(sa), "l"(gp));
        }
        asm volatile("cp.async.commit_group;");
    };

    load_stage(0, 0);

    for (int c = 0; c < nc; c++) {
        int s = c & 1;
        if (c + 1 < nc) {
            load_stage(s ^ 1, (c + 1) * BK);
            asm volatile("cp.async.wait_group 1;");
        } else {
            asm volatile("cp.async.wait_group 0;");
        }
        __syncthreads();
        uint32_t base = sb + s * STAGE_B;
        GEMM_PHASE(base, 0);
        GEMM_PHASE(base, 1);
        __syncthreads();
    }

#pragma unroll
    for (int mt = 0; mt < 4; mt++) {
#pragma unroll
        for (int nt = 0; nt < 4; nt++) {
            int lr = wm * 64 + mt * 16 + (lane >> 2);
            int cc = col0 + wn * 32 + nt * 8 + (lane & 3) * 2;
#pragma unroll
            for (int hf = 0; hf < 2; hf++) {
                int lrr = lr + hf * 8;
                if (row0 + lrr < n) {
                    long o = (long)sidx[lrr] * Dm + cc;
                    *(__half2*)&C[o] = __halves2half2(
                        __float2half_rn(acc[mt][nt][hf * 2]),
                        __float2half_rn(acc[mt][nt][hf * 2 + 1]));
                }
            }
        }
    }
}

// ================= fused flash attention =================
// Per (z, 128 q-rows): O = softmax(Q K^T / 8) V, exp without max (|s| small).
// smem: Q[128x64] | S[128x64] | K stages | V stages; pitch 72 halves.
#define FLD 72
#define F_QOFF 0
#define F_SOFF (128*FLD*2)
#define F_KOFF (2*128*FLD*2)
#define F_KT  (64*FLD*2)
#define F_VOFF (F_KOFF + 2*F_KT)
#define SMEM_F (F_VOFF + 2*F_KT)

__global__ __launch_bounds__(256, 2) void flash_kernel(
    const __half* __restrict__ qkvh, const __half* __restrict__ vt,
    __half* __restrict__ Ohi, __half* __restrict__ Olo)
{
    extern __shared__ char smem[];
    __shared__ float rs[128][2];
    uint32_t sb = smem_u32(smem);
    const int tid = threadIdx.x;
    const int wid = tid >> 5;
    const int lane = tid & 31;
    const int z = blockIdx.y;
    const int b = z >> 4, h = z & 15;
    const int row0 = blockIdx.x * 128;
    const int wm = wid & 1;
    const int wn = wid >> 1;

    const __half* Qg = qkvh + (long)(b * Nn) * 3072 + h * 64;
    const __half* Kg = Qg + INNERd;
    const __half* Vg = vt + (long)z * DHh * Nn;

    // Q tile: 128 rows x 8 chunks = 1024; 4 per thread
#pragma unroll
    for (int i = 0; i < 4; i++) {
        int idx = i * 256 + tid;
        int r = idx >> 3, c = idx & 7;
        uint32_t sa = sb + F_QOFF + (uint32_t)(r * FLD + c * 8) * 2;
        const __half* gp = Qg + (long)(row0 + r) * 3072 + c * 8;
        asm volatile("cp.async.cg.shared.global [%0], [%1], 16;"
                     :: "r"(sa), "l"(gp));
    }
    asm volatile("cp.async.commit_group;");

    auto load_kv = [&](int s, int kt) {
        // K tile: 64 rows x 8 chunks = 512; 2 per thread
#pragma unroll
        for (int i = 0; i < 2; i++) {
            int idx = i * 256 + tid;
            int r = idx >> 3, c = idx & 7;
            uint32_t sa = sb + F_KOFF + s * F_KT + (uint32_t)(r * FLD + c * 8) * 2;
            const __half* gp = Kg + (long)(kt + r) * 3072 + c * 8;
            asm volatile("cp.async.cg.shared.global [%0], [%1], 16;"
                         :: "r"(sa), "l"(gp));
        }
        // V tile: 64 d-rows x 8 chunks = 512; 2 per thread
#pragma unroll
        for (int i = 0; i < 2; i++) {
            int idx = i * 256 + tid;
            int r = idx >> 3, c = idx & 7;
            uint32_t sa = sb + F_VOFF + s * F_KT + (uint32_t)(r * FLD + c * 8) * 2;
            const __half* gp = Vg + (long)r * Nn + kt + c * 8;
            asm volatile("cp.async.cg.shared.global [%0], [%1], 16;"
                         :: "r"(sa), "l"(gp));
        }
        asm volatile("cp.async.commit_group;");
    };

    load_kv(0, 0);
    asm volatile("cp.async.wait_group 0;");
    __syncthreads();

    float oacc[4][2][4];
#pragma unroll
    for (int a = 0; a < 4; a++)
#pragma unroll
        for (int bb = 0; bb < 2; bb++)
#pragma unroll
            for (int c = 0; c < 4; c++) oacc[a][bb][c] = 0.f;
    float fsum = 0.f;

    const int nt_tiles = Nn / 64;
    for (int t = 0; t < nt_tiles; t++) {
        int s = t & 1;
        if (t + 1 < nt_tiles) load_kv(s ^ 1, (t + 1) * 64);

        // ---- QK: S = Q @ K^T ----
        float sacc[4][2][4];
#pragma unroll
        for (int a = 0; a < 4; a++)
#pragma unroll
            for (int bb = 0; bb < 2; bb++)
#pragma unroll
                for (int c = 0; c < 4; c++) sacc[a][bb][c] = 0.f;
#pragma unroll
        for (int ph = 0; ph < 4; ph++) {
            uint32_t af[4][4], bf[2][2];
#pragma unroll
            for (int mt = 0; mt < 4; mt++) {
                int rr = wm * 64 + mt * 16 + (lane & 15);
                uint32_t co = (uint32_t)(rr * FLD + ph * 16 + (lane >> 4) * 8) * 2;
                ldmx4(af[mt], sb + F_QOFF + co);
            }
#pragma unroll
            for (int nt = 0; nt < 2; nt++) {
                int rr = wn * 16 + nt * 8 + (lane & 7);
                uint32_t co = (uint32_t)(rr * FLD + ph * 16 + ((lane >> 3) & 1) * 8) * 2;
                ldmx2(bf[nt], sb + F_KOFF + s * F_KT + co);
            }
#pragma unroll
            for (int mt = 0; mt < 4; mt++)
#pragma unroll
                for (int nt = 0; nt < 2; nt++)
                    mma16816(sacc[mt][nt], af[mt], bf[nt]);
        }
        // ---- exp + stage to S smem ----
#pragma unroll
        for (int mt = 0; mt < 4; mt++)
#pragma unroll
            for (int nt = 0; nt < 2; nt++)
#pragma unroll
                for (int hf = 0; hf < 2; hf++) {
                    int row = wm * 64 + mt * 16 + (lane >> 2) + hf * 8;
                    int col = wn * 16 + nt * 8 + (lane & 3) * 2;
                    float v0 = expf(sacc[mt][nt][hf * 2] * 0.125f);
                    float v1 = expf(sacc[mt][nt][hf * 2 + 1] * 0.125f);
                    *(__half2*)(smem + F_SOFF + (size_t)(row * FLD + col) * 2) =
                        __halves2half2(__float2half_rn(v0), __float2half_rn(v1));
                }
        __syncthreads();

        // ---- row-sum strip from S (what PV consumes) ----
        {
            int r = tid & 127, hf2 = tid >> 7;
            const __half2* ap = (const __half2*)(smem + F_SOFF
                                                 + (size_t)(r * FLD + hf2 * 32) * 2);
            float lsum = 0.f;
#pragma unroll
            for (int j = 0; j < 16; j++) {
                float2 f = __half22float2(ap[j]);
                lsum += f.x + f.y;
            }
            fsum += lsum;
        }

        // ---- PV: O += S @ V^T (V tile is [d][k] k-major) ----
#pragma unroll
        for (int ph = 0; ph < 4; ph++) {
            uint32_t af[4][4], bf[2][2];
#pragma unroll
            for (int mt = 0; mt < 4; mt++) {
                int rr = wm * 64 + mt * 16 + (lane & 15);
                uint32_t co = (uint32_t)(rr * FLD + ph * 16 + (lane >> 4) * 8) * 2;
                ldmx4(af[mt], sb + F_SOFF + co);
            }
#pragma unroll
            for (int nt = 0; nt < 2; nt++) {
                int rr = wn * 16 + nt * 8 + (lane & 7);
                uint32_t co = (uint32_t)(rr * FLD + ph * 16 + ((lane >> 3) & 1) * 8) * 2;
                ldmx2(bf[nt], sb + F_VOFF + s * F_KT + co);
            }
#pragma unroll
            for (int mt = 0; mt < 4; mt++)
#pragma unroll
                for (int nt = 0; nt < 2; nt++)
                    mma16816(oacc[mt][nt], af[mt], bf[nt]);
        }
        asm volatile("cp.async.wait_group 0;");
        __syncthreads();
    }

    rs[tid & 127][tid >> 7] = fsum;
    __syncthreads();

    // ---- epilogue: O / rowsum -> hi/lo at [token, h*64+d] ----
#pragma unroll
    for (int mt = 0; mt < 4; mt++)
#pragma unroll
        for (int nt = 0; nt < 2; nt++)
#pragma unroll
            for (int hf = 0; hf < 2; hf++) {
                int lr = wm * 64 + mt * 16 + (lane >> 2) + hf * 8;
                int cc = wn * 16 + nt * 8 + (lane & 3) * 2;
                float inv = 1.f / (rs[lr][0] + rs[lr][1]);
                float v0 = oacc[mt][nt][hf * 2] * inv;
                float v1 = oacc[mt][nt][hf * 2 + 1] * inv;
                long o = (long)(b * Nn + row0 + lr) * INNERd + h * 64 + cc;
                __half h0 = __float2half_rn(v0), h1 = __float2half_rn(v1);
                *(__half2*)&Ohi[o] = __halves2half2(h0, h1);
                __half l0 = __float2half_rn(v0 - __half2float(h0));
                __half l1 = __float2half_rn(v1 - __half2float(h1));
                *(__half2*)&Olo[o] = __halves2half2(l0, l1);
            }
}

// ---------------- V transpose ----------------
__global__ __launch_bounds__(256) void vtrans_kernel(const __half* __restrict__ qkvh,
                                                     __half* __restrict__ vt)
{
    __shared__ __half t[32][33];
    int z = blockIdx.z, b = z >> 4, h = z & 15;
    int k0 = blockIdx.x * 32, d0 = blockIdx.y * 32;
    int tx = threadIdx.x & 31, ty = threadIdx.x >> 5;
#pragma unroll
    for (int i = 0; i < 4; i++) {
        int k = k0 + ty + i * 8;
        t[ty + i * 8][tx] = qkvh[(long)(b * Nn + k) * 3072 + 2048 + h * 64 + d0 + tx];
    }
    __syncthreads();
#pragma unroll
    for (int i = 0; i < 4; i++) {
        int d = d0 + ty + i * 8;
        vt[((long)z * 64 + d) * Nn + k0 + tx] = t[tx][ty + i * 8];
    }
}

// ---------------- weight transpose + fp16 split core ----------------
__device__ __forceinline__ void wsplit_tile(const float* __restrict__ Wz,
                                            __half* __restrict__ hi,
                                            __half* __restrict__ lo,
                                            long ob, int K, int N,
                                            int k0, int n0, int tid)
{
    __shared__ float tile[64][65];
#pragma unroll
    for (int i = 0; i < 4; i++) {
        int idx = i * 256 + tid;
        int r = idx >> 4, c4 = idx & 15;
        float4 v = *(const float4*)(Wz + (long)(k0 + r) * N + n0 + c4 * 4);
        tile[r][c4 * 4 + 0] = v.x; tile[r][c4 * 4 + 1] = v.y;
        tile[r][c4 * 4 + 2] = v.z; tile[r][c4 * 4 + 3] = v.w;
    }
    __syncthreads();
#pragma unroll
    for (int i = 0; i < 2; i++) {
        int idx = i * 256 + tid;
        int nn = idx >> 3, kg = idx & 7;
        __half hbuf[8], lbuf[8];
#pragma unroll
        for (int j = 0; j < 8; j++) {
            float v = tile[kg * 8 + j][nn];
            __half h = __float2half_rn(v);
            hbuf[j] = h;
            lbuf[j] = __float2half_rn(v - __half2float(h));
        }
        long o = ob + (long)(n0 + nn) * K + k0 + kg * 8;
        *(uint4*)(hi + o) = *(uint4*)hbuf;
        *(uint4*)(lo + o) = *(uint4*)lbuf;
    }
}

__global__ __launch_bounds__(256) void wsplit_kernel(
    const float* __restrict__ W, __half* __restrict__ hi, __half* __restrict__ lo,
    int K, int N, long inStride, long outStride)
{
    wsplit_tile(W + blockIdx.z * inStride, hi, lo, (long)blockIdx.z * outStride,
                K, N, blockIdx.y * 64, blockIdx.x * 64, threadIdx.x);
}

__global__ __launch_bounds__(256) void wsplit3_kernel(
    const float* __restrict__ W0, const float* __restrict__ W1,
    const float* __restrict__ W2,
    __half* __restrict__ hi, __half* __restrict__ lo)
{
    int z = blockIdx.z;
    int t = z >> 1, l = z & 1;
    const float* src = (t == 0 ? W0 : (t == 1 ? W1 : W2)) + (long)l * SZ1M;
    long off = (t == 0 ? OFF_WO : (t == 1 ? OFF_WB0 : OFF_WB1)) + (long)l * PER_L;
    wsplit_tile(src, hi, lo, off, 1024, 1024,
                blockIdx.y * 64, blockIdx.x * 64, threadIdx.x);
}

__global__ __launch_bounds__(256) void wsplitE_kernel(
    const float* __restrict__ Wp, const float* __restrict__ Wa,
    __half* __restrict__ hi, __half* __restrict__ lo)
{
    int z = blockIdx.z;
    int l = z / 14, s = z % 14;
    const float* src = (s < 7 ? Wp + (long)l * 7 * SZ1M + (long)s * SZ1M
                              : Wa + (long)l * 7 * SZ1M + (long)(s - 7) * SZ1M);
    long off = (long)l * PER_L + OFF_WEP + (long)s * SZ1M;
    wsplit_tile(src, hi, lo, off, 1024, 1024,
                blockIdx.y * 64, blockIdx.x * 64, threadIdx.x);
}

// ---------------- LayerNorm -> fp16 hi(/lo) ----------------
__global__ __launch_bounds__(256) void ln_split_kernel(
    const float* __restrict__ x, const float* __restrict__ g,
    const float* __restrict__ bta,
    __half* __restrict__ hi, __half* __restrict__ lo, int wantLo)
{
    int t = blockIdx.x, tid = threadIdx.x;
    const float* xp = x + (long)t * Dm;
    __shared__ float r1[256], r2[256];

    float v[4], s = 0.f, s2 = 0.f;
#pragma unroll
    for (int i = 0; i < 4; i++) { v[i] = xp[tid + i * 256]; s += v[i]; s2 += v[i] * v[i]; }
    r1[tid] = s; r2[tid] = s2; __syncthreads();
    for (int st = 128; st > 0; st >>= 1) {
        if (tid < st) { r1[tid] += r1[tid + st]; r2[tid] += r2[tid + st]; }
        __syncthreads();
    }
    float mean = r1[0] * (1.f / Dm);
    float var = r2[0] * (1.f / Dm) - mean * mean;
    float rstd = rsqrtf(var + 1e-5f);
#pragma unroll
    for (int i = 0; i < 4; i++) {
        int d = tid + i * 256;
        float y = (v[i] - mean) * rstd * g[d] + bta[d];
        __half h = __float2half_rn(y);
        hi[(long)t * Dm + d] = h;
        if (wantLo) lo[(long)t * Dm + d] = __float2half_rn(y - __half2float(h));
    }
}

// ---------------- reset expert counters ----------------
__global__ void reset_cnt_kernel(int* cnt)
{
    if (threadIdx.x < NEXP) cnt[threadIdx.x] = 0;
}

// ---------------- router (+ expert token gather) ----------------
__global__ __launch_bounds__(128) void router_kernel(const float* __restrict__ x,
                                                     const float* __restrict__ Wr,
                                                     const float* __restrict__ br,
                                                     float* __restrict__ wout,
                                                     int* __restrict__ cnt,
                                                     int* __restrict__ eidx)
{
    int t = blockIdx.x, tid = threadIdx.x;
    __shared__ float part[128][Ee];
    float acc[Ee];
#pragma unroll
    for (int e = 0; e < Ee; e++) acc[e] = 0.f;
    const float* xp = x + (long)t * Dm;
    for (int d = tid; d < Dm; d += 128) {
        float xv = xp[d];
        const float* wrow = Wr + (long)d * Ee;
#pragma unroll
        for (int e = 0; e < Ee; e++) acc[e] += xv * wrow[e];
    }
#pragma unroll
    for (int e = 0; e < Ee; e++) part[tid][e] = acc[e];
    __syncthreads();
    for (int st = 64; st > 0; st >>= 1) {
        if (tid < st)
#pragma unroll
            for (int e = 0; e < Ee; e++) part[tid][e] += part[tid + st][e];
        __syncthreads();
    }
    if (tid == 0) {
        float lg[Ee];
#pragma unroll
        for (int e = 0; e < Ee; e++) lg[e] = part[0][e] + br[e];
        float m1 = -3.4e38f, m2 = -3.4e38f;
#pragma unroll
        for (int e = 0; e < Ee; e++) {
            float v = lg[e];
            if (v > m1) { m2 = m1; m1 = v; }
            else if (v > m2) m2 = v;
        }
        float sum = 0.f, we[Ee];
#pragma unroll
        for (int e = 0; e < Ee; e++) {
            we[e] = (lg[e] < m2) ? 0.f : expf(lg[e] - m1);
            sum += we[e];
        }
        float inv = 1.f / sum;
#pragma unroll
        for (int e = 0; e < Ee; e++) wout[(long)t * Ee + e] = we[e] * inv;
#pragma unroll
        for (int e = 0; e < NEXP; e++) {
            if (we[e + 1] != 0.f) {
                int p = atomicAdd(&cnt[e], 1);
                eidx[(long)e * Tt + p] = t;
            }
        }
    }
}

// ---------------- FiLM: write ytf as hi(/lo) only ----------------
__global__ __launch_bounds__(256) void film_kernel(const float* __restrict__ t0,
                                                   const float* __restrict__ t1,
                                                   const float* __restrict__ b0,
                                                   const float* __restrict__ b1,
                                                   __half* __restrict__ hi,
                                                   __half* __restrict__ lo, int wantLo)
{
    long i = (long)blockIdx.x * 256 + threadIdx.x;
    int d = (int)(i & (Dm - 1));
    float y = gelu_f(t0[i] + b0[d]) * (t1[i] + b1[d]);
    __half h = __float2half_rn(y);
    hi[i] = h;
    if (wantLo) lo[i] = __float2half_rn(y - __half2float(h));
}

// ---------------- expert mixing (ytf from hi/lo; PA fp16) ----------------
__global__ __launch_bounds__(256) void mix_kernel(const __half* __restrict__ pe,
                                                  const __half* __restrict__ ae,
                                                  const float* __restrict__ Pb,
                                                  const float* __restrict__ Ab,
                                                  const float* __restrict__ w,
                                                  __half* __restrict__ hi,
                                                  __half* __restrict__ lo, int wantLo)
{
    int t = blockIdx.x;
    __shared__ float ws[Ee];
    if (threadIdx.x < Ee) ws[threadIdx.x] = w[(long)t * Ee + threadIdx.x];
    __syncthreads();
#pragma unroll
    for (int it = 0; it < 4; it++) {
        int d = threadIdx.x + it * 256;
        long td = (long)t * Dm + d;
        float yv = __half2float(hi[td]);
        if (wantLo) yv += __half2float(lo[td]);
        float out = ws[0] * gelu_f(yv);
#pragma unroll
        for (int e = 0; e < NEXP; e++) {
            float we = ws[e + 1];
            if (we != 0.f) {
                float p = __half2float(pe[(long)e * Tt * Dm + td]) + Pb[e * Dm + d];
                float a = __half2float(ae[(long)e * Tt * Dm + td]) + Ab[e * Dm + d];
                out += we * (p * yv + a);
            }
        }
        __half h = __float2half_rn(out);
        hi[td] = h;
        if (wantLo) lo[td] = __float2half_rn(out - __half2float(h));
    }
}

// ---------------- host helpers ----------------
static float* symf(const void* s) { void* p = nullptr; cudaGetSymbolAddress(&p, s); return (float*)p; }
static __half* symh(const void* s) { void* p = nullptr; cudaGetSymbolAddress(&p, s); return (__half*)p; }
static int* symi(const void* s) { void* p = nullptr; cudaGetSymbolAddress(&p, s); return (int*)p; }

static void tgemm(const __half* ahi, const __half* alo,
                  const __half* bhi, const __half* blo,
                  const float* bias, const float* resid,
                  float* C, __half* Chi, __half* Clo,
                  int N, int K, int Z, long sB, long sC, int act, int terms)
{
    dim3 grid(N / BN, Tt / BM, Z);
    mma_gemm_kernel<<<grid, 256, SMEM_MM>>>(ahi, alo, bhi, blo, bias, resid,
                                            C, Chi, Clo, Tt, N, K, sB, sC, act,
                                            bias != nullptr, resid != nullptr,
                                            C != nullptr, Chi != nullptr, Clo != nullptr,
                                            terms);
}

extern "C" void kernel_launch(void* const* d_in, const int* in_sizes, int n_in,
                              void* d_out, int out_size)
{
    const float* x_in  = (const float*)d_in[0];
    const float* ln1_g = (const float*)d_in[1];
    const float* ln1_b = (const float*)d_in[2];
    const float* Wqkv  = (const float*)d_in[3];
    const float* bqkv  = (const float*)d_in[4];
    const float* Wo    = (const float*)d_in[5];
    const float* bo    = (const float*)d_in[6];
    const float* Wr    = (const float*)d_in[7];
    const float* br    = (const float*)d_in[8];
    const float* Wa1   = (const float*)d_in[9];
    const float* ba1   = (const float*)d_in[10];
    const float* Wa2   = (const float*)d_in[11];
    const float* ba2   = (const float*)d_in[12];
    const float* ln2_g = (const float*)d_in[13];
    const float* ln2_b = (const float*)d_in[14];
    const float* Wb0   = (const float*)d_in[15];
    const float* bb0   = (const float*)d_in[16];
    const float* Wb1   = (const float*)d_in[17];
    const float* bb1   = (const float*)d_in[18];
    const float* We_p  = (const float*)d_in[19];
    const float* be_p  = (const float*)d_in[20];
    const float* We_a  = (const float*)d_in[21];
    const float* be_a  = (const float*)d_in[22];

    float* X   = symf(g_x);
    float* T01 = symf(g_t01);
    float* T0  = T01;
    float* T1  = T01 + (long)Tt * Dm;
    __half* PA = symh(g_pa);
    float* Wt  = symf(g_w);
    __half* WHI = symh(g_whi);
    __half* WLO = symh(g_wlo);
    __half* AHI = symh(g_ahi);
    __half* ALO = symh(g_alo);
    __half* MHI = symh(g_mhi);
    __half* MLO = symh(g_mlo);
    __half* QKVH = symh(g_qkvh);
    __half* VT  = symh(g_vt);
    int* CNT = symi(g_cnt);
    int* EIDX = symi(g_eidx);

    cudaFuncSetAttribute(mma_gemm_kernel,
                         cudaFuncAttributeMaxDynamicSharedMemorySize, SMEM_MM);
    cudaFuncSetAttribute(mma_gather_kernel,
                         cudaFuncAttributeMaxDynamicSharedMemorySize, SMEM_MM);
    cudaFuncSetAttribute(flash_kernel,
                         cudaFuncAttributeMaxDynamicSharedMemorySize, SMEM_F);

    // ---- weight transpose + split (5 launches) ----
    {
        dim3 g1(3072 / 64, 1024 / 64, Lnum);
        wsplit_kernel<<<g1, 256>>>(Wqkv, WHI + OFF_QKV, WLO + OFF_QKV,
                                   1024, 3072, 3072L * 1024, PER_L);
        dim3 g2(16, 16, 6);
        wsplit3_kernel<<<g2, 256>>>(Wo, Wb0, Wb1, WHI, WLO);
        dim3 g3(16, 16, 28);
        wsplitE_kernel<<<g3, 256>>>(We_p, We_a, WHI, WLO);
        dim3 g4(4096 / 64, 1024 / 64, Lnum);
        wsplit_kernel<<<g4, 256>>>(Wa1, WHI + OFF_WA1, WLO + OFF_WA1,
                                   1024, 4096, 4096L * 1024, PER_L);
        dim3 g5(1024 / 64, 4096 / 64, Lnum);
        wsplit_kernel<<<g5, 256>>>(Wa2, WHI + OFF_WA2, WLO + OFF_WA2,
                                   4096, 1024, 4096L * 1024, PER_L);
    }

    cudaMemcpyAsync(X, x_in, (size_t)Tt * Dm * sizeof(float),
                    cudaMemcpyDeviceToDevice, 0);

    for (int l = 0; l < Lnum; l++) {
        const __half* whl = WHI + (long)l * PER_L;
        const __half* wll = WLO + (long)l * PER_L;
        const int tpost = (l == Lnum - 1) ? 2 : 3;
        const int loPost = (tpost == 3) ? 1 : 0;

        // --- attention (QKV 2-term) ---
        ln_split_kernel<<<Tt, 256>>>(X, ln1_g + l * Dm, ln1_b + l * Dm, AHI, ALO, 0);
        tgemm(AHI, ALO, whl + OFF_QKV, wll + OFF_QKV,
              bqkv + (long)l * 3 * INNERd, nullptr,
              nullptr, QKVH, nullptr, 3 * INNERd, Dm, 1, 0, 0, 0, 2);

        {
            dim3 grid(Nn / 32, DHh / 32, Bb * Hh);
            vtrans_kernel<<<grid, 256>>>(QKVH, VT);
        }
        // fused flash attention: O -> AHI/ALO
        {
            dim3 grid(Nn / 128, Bb * Hh);
            flash_kernel<<<grid, 256, SMEM_F>>>(QKVH, VT, AHI, ALO);
        }
        tgemm(AHI, ALO, whl + OFF_WO, wll + OFF_WO,
              bo + (long)l * Dm, X, X, nullptr, nullptr, Dm, INNERd, 1, 0, 0, 0, 3);

        // --- router + expert gather ---
        reset_cnt_kernel<<<1, 32>>>(CNT);
        router_kernel<<<Tt, 128>>>(X, Wr + (long)l * Dm * Ee, br + (long)l * Ee,
                                   Wt + (long)l * Tt * Ee, CNT, EIDX);

        // --- FiLM trunk ---
        ln_split_kernel<<<Tt, 256>>>(X, ln2_g + l * Dm, ln2_b + l * Dm, AHI, ALO, loPost);
        tgemm(AHI, ALO, whl + OFF_WB0, wll + OFF_WB0,
              nullptr, nullptr, T01, nullptr, nullptr,
              Dm, Dm, 2, SZ1M, (long)Tt * Dm, 0, tpost);
        film_kernel<<<(Tt * Dm) / 256, 256>>>(T0, T1, bb0 + (long)l * Dm,
                                              bb1 + (long)l * Dm, AHI, ALO, loPost);

        // --- sparse gathered expert GEMMs (fp16 out) ---
        {
            dim3 grid(Dm / BN, Tt / BM, 2 * NEXP);
            mma_gather_kernel<<<grid, 256, SMEM_MM>>>(
                AHI, ALO, whl + OFF_WEP, wll + OFF_WEP, PA, CNT, EIDX, tpost);
        }

        // --- mix (in-place on AHI/ALO) ---
        mix_kernel<<<Tt, 256>>>(PA, PA + (long)NEXP * Tt * Dm,
                                be_p + (long)l * NEXP * Dm,
                                be_a + (long)l * NEXP * Dm,
                                Wt + (long)l * Tt * Ee, AHI, ALO, loPost);

        // --- adaptor MLP + residual ---
        tgemm(AHI, ALO, whl + OFF_WA1, wll + OFF_WA1,
              ba1 + (long)l * MLPd, nullptr,
              nullptr, MHI, (loPost ? MLO : nullptr), MLPd, Dm, 1, 0, 0, 1, tpost);
        tgemm(MHI, MLO, whl + OFF_WA2, wll + OFF_WA2,
              ba2 + (long)l * Dm, X, X, nullptr, nullptr, Dm, MLPd, 1, 0, 0, 0, tpost);
    }

    // outputs: x [B,N,D] then stacked router weights [L,B,N,E]
    cudaMemcpyAsync(d_out, X, (size_t)Tt * Dm * sizeof(float),
                    cudaMemcpyDeviceToDevice, 0);
    if (out_size >= Tt * Dm + Lnum * Tt * Ee) {
        cudaMemcpyAsync((float*)d_out + (size_t)Tt * Dm, Wt,
                        (size_t)Lnum * Tt * Ee * sizeof(float),
                        cudaMemcpyDeviceToDevice, 0);
    }
}